// round 1
// baseline (speedup 1.0000x reference)
#include <cuda_runtime.h>
#include <math.h>

#define B_    4
#define NTOK  4096
#define C_    256
#define H_    64
#define W_    64
#define NH2   4
#define HD    32
#define N1_   1024

#define OUT_MAIN (B_*NTOK*C_)
#define OUT_M1   (OUT_MAIN)
#define OUT_M2   (OUT_MAIN + B_*NTOK)

static __device__ float d_q1[B_*NTOK*128];
static __device__ float d_q2[B_*NTOK*128];
static __device__ float d_kv2[B_*NTOK*C_];
static __device__ float d_lepe[B_*NTOK*C_];
static __device__ float d_xsraw[B_*N1_*C_];
static __device__ float d_xs[B_*N1_*C_];
static __device__ float d_kv1[B_*N1_*C_];
static __device__ float d_attnbuf[(size_t)NTOK*N1_];
static __device__ float d_cat[B_*NTOK*C_];
static __device__ float d_g[B_*N1_];
static __device__ float d_lm[B_*NTOK];
static __device__ float d_srw[1024*C_];

__device__ __constant__ float ATT_SCALE = 0.17677669529663687f; // 1/sqrt(32)

// ---------------------------------------------------------------------------
// Generic tiled SGEMM:  C[M,N] = alpha * (A[M,K] @ B[K,N] + bias[N])
// BM=64, BK=16, BN template (64 or 32). 256 threads, 4xTN per thread.
// Assumes M%64==0, K%16==0. N guarded.
// ---------------------------------------------------------------------------
template<int BN>
__global__ void gemm_nn(const float* __restrict__ A, int lda,
                        const float* __restrict__ Bm, int ldb,
                        const float* __restrict__ bias,
                        float* __restrict__ Cm, int ldc,
                        int M, int Nn, int K, float alpha)
{
    constexpr int BM = 64, BK = 16;
    constexpr int TN = BN / 16;
    __shared__ float As[BK][BM];
    __shared__ float Bs[BK][BN];
    int m0 = blockIdx.y * BM;
    int n0 = blockIdx.x * BN;
    int tid = threadIdx.x;
    int tx = tid & 15, ty = tid >> 4;

    float acc[4][TN];
#pragma unroll
    for (int i = 0; i < 4; i++)
#pragma unroll
        for (int j = 0; j < TN; j++) acc[i][j] = 0.f;

    for (int k0 = 0; k0 < K; k0 += BK) {
        // A tile: 64x16 = 256 float4, one per thread
        {
            int row = tid >> 2, kq = tid & 3;
            float4 v = *(const float4*)(A + (size_t)(m0 + row) * lda + k0 + kq * 4);
            As[kq*4+0][row] = v.x; As[kq*4+1][row] = v.y;
            As[kq*4+2][row] = v.z; As[kq*4+3][row] = v.w;
        }
        // B tile: 16xBN
        for (int i = tid; i < BK * BN / 4; i += 256) {
            int kr = i / (BN / 4), cq = i % (BN / 4);
            int col = n0 + cq * 4;
            float4 v = make_float4(0.f, 0.f, 0.f, 0.f);
            if (col < Nn) v = *(const float4*)(Bm + (size_t)(k0 + kr) * ldb + col);
            *(float4*)&Bs[kr][cq * 4] = v;
        }
        __syncthreads();
#pragma unroll
        for (int k = 0; k < BK; k++) {
            float a[4], bb[TN];
#pragma unroll
            for (int i = 0; i < 4; i++) a[i] = As[k][ty * 4 + i];
#pragma unroll
            for (int j = 0; j < TN; j++) bb[j] = Bs[k][tx * TN + j];
#pragma unroll
            for (int i = 0; i < 4; i++)
#pragma unroll
                for (int j = 0; j < TN; j++) acc[i][j] += a[i] * bb[j];
        }
        __syncthreads();
    }
#pragma unroll
    for (int i = 0; i < 4; i++) {
        int row = m0 + ty * 4 + i;
        if (row >= M) continue;
#pragma unroll
        for (int j = 0; j < TN; j++) {
            int col = n0 + tx * TN + j;
            if (col < Nn) {
                float bv = bias ? bias[col] : 0.f;
                Cm[(size_t)row * ldc + col] = alpha * (acc[i][j] + bv);
            }
        }
    }
}

// ---------------------------------------------------------------------------
// sr weight repack: d_srw[(dd*256+ci)*256+co] = sr_w[co,ci,di,dj], dd=di*2+dj
// ---------------------------------------------------------------------------
__global__ void repack_srw(const float* __restrict__ w)
{
    int idx = blockIdx.x * 256 + threadIdx.x;   // 1024*256
    int co = idx & 255;
    int k  = idx >> 8;          // dd*256 + ci
    int dd = k >> 8, ci = k & 255;
    d_srw[idx] = w[co * 1024 + ci * 4 + dd];
}

// ---------------------------------------------------------------------------
// sr conv as gather-GEMM: xsraw[(b,i,j), co] = sum_{dd,ci} x_patch * srw + bias
// M=4096, N=256, K=1024
// ---------------------------------------------------------------------------
__global__ void srconv_gemm(const float* __restrict__ x,
                            const float* __restrict__ bias)
{
    constexpr int BM = 64, BN = 64, BK = 16;
    __shared__ float As[BK][BM];
    __shared__ float Bs[BK][BN];
    int m0 = blockIdx.y * BM, n0 = blockIdx.x * BN;
    int tid = threadIdx.x, tx = tid & 15, ty = tid >> 4;

    float acc[4][4];
#pragma unroll
    for (int i = 0; i < 4; i++)
#pragma unroll
        for (int j = 0; j < 4; j++) acc[i][j] = 0.f;

    for (int k0 = 0; k0 < 1024; k0 += BK) {
        int dd = k0 >> 8;
        int di = dd >> 1, dj = dd & 1;
        {
            int row = tid >> 2, kq = tid & 3;
            int r = m0 + row;
            int b = r >> 10, p = r & 1023;
            int ii = p >> 5, jj = p & 31;
            int n = (2 * ii + di) * W_ + (2 * jj + dj);
            int ci = (k0 & 255) + kq * 4;
            float4 v = *(const float4*)(x + (size_t)(b * NTOK + n) * C_ + ci);
            As[kq*4+0][row] = v.x; As[kq*4+1][row] = v.y;
            As[kq*4+2][row] = v.z; As[kq*4+3][row] = v.w;
        }
        {
            int kr = tid >> 4, cq = tid & 15;
            float4 v = *(const float4*)(d_srw + (size_t)(k0 + kr) * 256 + n0 + cq * 4);
            *(float4*)&Bs[kr][cq * 4] = v;
        }
        __syncthreads();
#pragma unroll
        for (int k = 0; k < BK; k++) {
            float a[4], bb[4];
#pragma unroll
            for (int i = 0; i < 4; i++) a[i] = As[k][ty * 4 + i];
#pragma unroll
            for (int j = 0; j < 4; j++) bb[j] = Bs[k][tx * 4 + j];
#pragma unroll
            for (int i = 0; i < 4; i++)
#pragma unroll
                for (int j = 0; j < 4; j++) acc[i][j] += a[i] * bb[j];
        }
        __syncthreads();
    }
#pragma unroll
    for (int i = 0; i < 4; i++) {
        int row = m0 + ty * 4 + i;
#pragma unroll
        for (int j = 0; j < 4; j++) {
            int col = n0 + tx * 4 + j;
            d_xsraw[(size_t)row * 256 + col] = acc[i][j] + bias[col];
        }
    }
}

// ---------------------------------------------------------------------------
// LayerNorm (over 256) + exact GELU. One block per row, 256 threads.
// ---------------------------------------------------------------------------
__global__ void ln_gelu_kernel(const float* __restrict__ nw,
                               const float* __restrict__ nb)
{
    __shared__ float sh[8];
    int r = blockIdx.x, c = threadIdx.x;
    float v = d_xsraw[(size_t)r * C_ + c];

    float s = v;
#pragma unroll
    for (int o = 16; o > 0; o >>= 1) s += __shfl_xor_sync(0xffffffffu, s, o);
    if ((c & 31) == 0) sh[c >> 5] = s;
    __syncthreads();
    if (c < 32) {
        float t = (c < 8) ? sh[c] : 0.f;
#pragma unroll
        for (int o = 4; o > 0; o >>= 1) t += __shfl_xor_sync(0xffffffffu, t, o);
        if (c == 0) sh[0] = t;
    }
    __syncthreads();
    float mean = sh[0] * (1.f / 256.f);
    __syncthreads();

    float dv = v - mean;
    float q = dv * dv;
#pragma unroll
    for (int o = 16; o > 0; o >>= 1) q += __shfl_xor_sync(0xffffffffu, q, o);
    if ((c & 31) == 0) sh[c >> 5] = q;
    __syncthreads();
    if (c < 32) {
        float t = (c < 8) ? sh[c] : 0.f;
#pragma unroll
        for (int o = 4; o > 0; o >>= 1) t += __shfl_xor_sync(0xffffffffu, t, o);
        if (c == 0) sh[0] = t;
    }
    __syncthreads();
    float var = sh[0] * (1.f / 256.f);

    float y = dv * rsqrtf(var + 1e-5f) * nw[c] + nb[c];
    d_xs[(size_t)r * C_ + c] = 0.5f * y * (1.f + erff(y * 0.70710678118654752f));
}

// ---------------------------------------------------------------------------
// QK^T for one (b,h): S[4096,1024] = scale * Q(4096x32) @ K(1024x32)^T
// ---------------------------------------------------------------------------
__global__ void qk_kernel(const float* __restrict__ Q, const float* __restrict__ Kp)
{
    __shared__ float Qs[64][33];
    __shared__ float Ks[64][33];
    int k0 = blockIdx.x * 64;   // key tile
    int q0 = blockIdx.y * 64;   // query tile
    int tid = threadIdx.x, tx = tid & 15, ty = tid >> 4;

#pragma unroll
    for (int i = tid; i < 512; i += 256) {
        int row = i >> 3, kq = i & 7;
        float4 v = *(const float4*)(Q + (size_t)(q0 + row) * 128 + kq * 4);
        Qs[row][kq*4+0] = v.x; Qs[row][kq*4+1] = v.y;
        Qs[row][kq*4+2] = v.z; Qs[row][kq*4+3] = v.w;
        float4 u = *(const float4*)(Kp + (size_t)(k0 + row) * 256 + kq * 4);
        Ks[row][kq*4+0] = u.x; Ks[row][kq*4+1] = u.y;
        Ks[row][kq*4+2] = u.z; Ks[row][kq*4+3] = u.w;
    }
    __syncthreads();

    float acc[4][4];
#pragma unroll
    for (int i = 0; i < 4; i++)
#pragma unroll
        for (int j = 0; j < 4; j++) acc[i][j] = 0.f;
#pragma unroll
    for (int k = 0; k < 32; k++) {
        float a[4], bb[4];
#pragma unroll
        for (int i = 0; i < 4; i++) a[i] = Qs[ty * 4 + i][k];
#pragma unroll
        for (int j = 0; j < 4; j++) bb[j] = Ks[tx * 4 + j][k];
#pragma unroll
        for (int i = 0; i < 4; i++)
#pragma unroll
            for (int j = 0; j < 4; j++) acc[i][j] += a[i] * bb[j];
    }
    float sc = ATT_SCALE;
#pragma unroll
    for (int i = 0; i < 4; i++) {
        float4 v = make_float4(acc[i][0]*sc, acc[i][1]*sc, acc[i][2]*sc, acc[i][3]*sc);
        *(float4*)&d_attnbuf[(size_t)(q0 + ty*4 + i) * N1_ + k0 + tx * 4] = v;
    }
}

// ---------------------------------------------------------------------------
// Row softmax over 1024, in place on d_attnbuf. One block per row.
// ---------------------------------------------------------------------------
__global__ void softmax_kernel()
{
    __shared__ float sh[8];
    size_t r = blockIdx.x;
    float4* row = (float4*)(d_attnbuf + r * N1_);
    int t = threadIdx.x;
    float4 v = row[t];

    float m = fmaxf(fmaxf(v.x, v.y), fmaxf(v.z, v.w));
#pragma unroll
    for (int o = 16; o > 0; o >>= 1) m = fmaxf(m, __shfl_xor_sync(0xffffffffu, m, o));
    if ((t & 31) == 0) sh[t >> 5] = m;
    __syncthreads();
    if (t < 32) {
        float mm = (t < 8) ? sh[t] : -1e30f;
#pragma unroll
        for (int o = 4; o > 0; o >>= 1) mm = fmaxf(mm, __shfl_xor_sync(0xffffffffu, mm, o));
        if (t == 0) sh[0] = mm;
    }
    __syncthreads();
    m = sh[0];
    __syncthreads();

    v.x = __expf(v.x - m); v.y = __expf(v.y - m);
    v.z = __expf(v.z - m); v.w = __expf(v.w - m);
    float s = v.x + v.y + v.z + v.w;
#pragma unroll
    for (int o = 16; o > 0; o >>= 1) s += __shfl_xor_sync(0xffffffffu, s, o);
    if ((t & 31) == 0) sh[t >> 5] = s;
    __syncthreads();
    if (t < 32) {
        float ss = (t < 8) ? sh[t] : 0.f;
#pragma unroll
        for (int o = 4; o > 0; o >>= 1) ss += __shfl_xor_sync(0xffffffffu, ss, o);
        if (t == 0) sh[0] = ss;
    }
    __syncthreads();
    float inv = 1.f / sh[0];
    v.x *= inv; v.y *= inv; v.z *= inv; v.w *= inv;
    row[t] = v;
}

// ---------------------------------------------------------------------------
// Column sums of attn (over the 4096 queries) -> atomicAdd into g[b*1024+m]
// grid (4 m-chunks, 32 n-chunks), 256 threads
// ---------------------------------------------------------------------------
__global__ void colsum_kernel(float* __restrict__ g)
{
    int m = blockIdx.x * 256 + threadIdx.x;
    int nbase = blockIdx.y * 128;
    float acc = 0.f;
#pragma unroll 4
    for (int n = 0; n < 128; n++)
        acc += d_attnbuf[(size_t)(nbase + n) * N1_ + m];
    atomicAdd(&g[m], acc);
}

// ---------------------------------------------------------------------------
// Windowed attention (branch 2). One block per (b, gy, gx) window, 4 warps =
// 4 heads. Writes x2 into d_cat channels [128,256) and lm (mean over h,q).
// ---------------------------------------------------------------------------
__global__ void attn2_kernel(const float* __restrict__ q2,
                             const float* __restrict__ kv2)
{
    int win = blockIdx.x;                 // b*256 + gy*16 + gx
    int b = win >> 8, rem = win & 255, gy = rem >> 4, gx = rem & 15;
    int tid = threadIdx.x, h = tid >> 5, lane = tid & 31;

    __shared__ float Qs[4][16][32];
    __shared__ float Ks[4][16][32];
    __shared__ float Vs[4][16][32];
    __shared__ float csum[16];

    for (int i = lane; i < 16 * 32; i += 32) {
        int t = i >> 5, dd = i & 31;
        int n = (gy * 4 + (t >> 2)) * W_ + gx * 4 + (t & 3);
        Qs[h][t][dd] = q2 [(size_t)(b * NTOK + n) * 128 + h * 32 + dd];
        Ks[h][t][dd] = kv2[(size_t)(b * NTOK + n) * 256 + h * 32 + dd];
        Vs[h][t][dd] = kv2[(size_t)(b * NTOK + n) * 256 + 128 + h * 32 + dd];
    }
    if (tid < 16) csum[tid] = 0.f;
    __syncthreads();

    if (lane < 16) {
        int q = lane;
        float s[16];
        float mx = -1e30f;
#pragma unroll
        for (int m = 0; m < 16; m++) {
            float dot = 0.f;
#pragma unroll
            for (int dd = 0; dd < 32; dd++) dot += Qs[h][q][dd] * Ks[h][m][dd];
            s[m] = dot * ATT_SCALE;
            mx = fmaxf(mx, s[m]);
        }
        float sum = 0.f;
#pragma unroll
        for (int m = 0; m < 16; m++) { s[m] = __expf(s[m] - mx); sum += s[m]; }
        float inv = 1.f / sum;
#pragma unroll
        for (int m = 0; m < 16; m++) {
            s[m] *= inv;
            atomicAdd(&csum[m], s[m]);
        }
        int nq = (gy * 4 + (q >> 2)) * W_ + gx * 4 + (q & 3);
        float* outp = d_cat + (size_t)(b * NTOK + nq) * 256 + 128 + h * 32;
#pragma unroll
        for (int dd = 0; dd < 32; dd++) {
            float o = 0.f;
#pragma unroll
            for (int m = 0; m < 16; m++) o += s[m] * Vs[h][m][dd];
            outp[dd] = o;
        }
    }
    __syncthreads();
    if (tid < 16) {
        int m = tid;
        int np = (gy * 4 + (m >> 2)) * W_ + gx * 4 + (m & 3);
        d_lm[b * NTOK + np] = csum[m] * (1.f / 64.f);
    }
}

// ---------------------------------------------------------------------------
// LePE depthwise 3x3 conv (+bias) added into d_cat. One block per token row.
// ---------------------------------------------------------------------------
__global__ void lepe_add_kernel(const float* __restrict__ w9,
                                const float* __restrict__ cb)
{
    int r = blockIdx.x;              // b*4096 + n
    int c = threadIdx.x;
    int b = r >> 12, n = r & 4095, y = n >> 6, x = n & 63;
    float wv[9];
#pragma unroll
    for (int t = 0; t < 9; t++) wv[t] = w9[c * 9 + t];
    float acc = cb[c];
#pragma unroll
    for (int dy = 0; dy < 3; dy++) {
        int yy = y + dy - 1;
        if (yy < 0 || yy >= H_) continue;
#pragma unroll
        for (int dx = 0; dx < 3; dx++) {
            int xx = x + dx - 1;
            if (xx < 0 || xx >= W_) continue;
            acc += wv[dy * 3 + dx] *
                   d_lepe[(size_t)(b * NTOK + yy * W_ + xx) * C_ + c];
        }
    }
    d_cat[(size_t)r * C_ + c] += acc;
}

// ---------------------------------------------------------------------------
// Masks: mask = lm + g_upsampled; write mask1 (row-major) and mask2 (transposed)
// ---------------------------------------------------------------------------
__global__ void mask_kernel(float* __restrict__ out)
{
    int idx = blockIdx.x * 256 + threadIdx.x;      // 16384
    int b = idx >> 12, pos = idx & 4095, y = pos >> 6, x = pos & 63;
    float gv = d_g[b * N1_ + (y >> 1) * 32 + (x >> 1)] * (1.f / (NH2 * NTOK));
    float val = d_lm[idx] + gv;
    out[OUT_M1 + idx] = val;
    out[OUT_M2 + b * NTOK + x * 64 + y] = val;
}

// ---------------------------------------------------------------------------
extern "C" void kernel_launch(void* const* d_in, const int* in_sizes, int n_in,
                              void* d_out, int out_size)
{
    const float* x      = (const float*)d_in[0];
    const float* q1_w   = (const float*)d_in[1];
    const float* q1_b   = (const float*)d_in[2];
    const float* kv1_w  = (const float*)d_in[3];
    const float* kv1_b  = (const float*)d_in[4];
    const float* q2_w   = (const float*)d_in[5];
    const float* q2_b   = (const float*)d_in[6];
    const float* kv2_w  = (const float*)d_in[7];
    const float* kv2_b  = (const float*)d_in[8];
    const float* lepe_w = (const float*)d_in[9];
    const float* lepe_b = (const float*)d_in[10];
    const float* lcw    = (const float*)d_in[11];
    const float* lcb    = (const float*)d_in[12];
    const float* sr_w   = (const float*)d_in[13];
    const float* sr_b   = (const float*)d_in[14];
    const float* nw     = (const float*)d_in[15];
    const float* nb     = (const float*)d_in[16];
    const float* pw     = (const float*)d_in[17];
    const float* pb     = (const float*)d_in[18];
    float* out = (float*)d_out;

    void* p;
    float *q1p, *q2p, *kv2p, *lepep, *xsp, *kv1p, *attnp, *catp, *gp;
    cudaGetSymbolAddress(&p, d_q1);     q1p   = (float*)p;
    cudaGetSymbolAddress(&p, d_q2);     q2p   = (float*)p;
    cudaGetSymbolAddress(&p, d_kv2);    kv2p  = (float*)p;
    cudaGetSymbolAddress(&p, d_lepe);   lepep = (float*)p;
    cudaGetSymbolAddress(&p, d_xs);     xsp   = (float*)p;
    cudaGetSymbolAddress(&p, d_kv1);    kv1p  = (float*)p;
    cudaGetSymbolAddress(&p, d_attnbuf);attnp = (float*)p;
    cudaGetSymbolAddress(&p, d_cat);    catp  = (float*)p;
    cudaGetSymbolAddress(&p, d_g);      gp    = (float*)p;

    cudaMemsetAsync(gp, 0, B_ * N1_ * sizeof(float));

    // weight repack for sr conv
    repack_srw<<<1024, 256>>>(sr_w);

    // projections from x: q1, q2, kv2, lepe_lin
    gemm_nn<64><<<dim3(2, 256), 256>>>(x, 256, q1_w, 128, q1_b, q1p, 128,
                                       B_*NTOK, 128, 256, 1.f);
    gemm_nn<64><<<dim3(2, 256), 256>>>(x, 256, q2_w, 128, q2_b, q2p, 128,
                                       B_*NTOK, 128, 256, 1.f);
    gemm_nn<64><<<dim3(4, 256), 256>>>(x, 256, kv2_w, 256, kv2_b, kv2p, 256,
                                       B_*NTOK, 256, 256, 1.f);
    gemm_nn<64><<<dim3(4, 256), 256>>>(x, 256, lepe_w, 256, lepe_b, lepep, 256,
                                       B_*NTOK, 256, 256, 1.f);

    // sr conv -> LN -> GELU -> kv1
    srconv_gemm<<<dim3(4, 64), 256>>>(x, sr_b);
    ln_gelu_kernel<<<B_ * N1_, 256>>>(nw, nb);
    gemm_nn<64><<<dim3(4, 64), 256>>>(xsp, 256, kv1_w, 256, kv1_b, kv1p, 256,
                                      B_*N1_, 256, 256, 1.f);

    // attention branch 1, one (b,h) slice at a time
    for (int bh = 0; bh < B_ * NH2; bh++) {
        int b = bh >> 2, h = bh & 3;
        const float* Qp = q1p + (size_t)b * NTOK * 128 + h * 32;
        const float* Kp = kv1p + (size_t)b * N1_ * 256 + h * 32;
        const float* Vp = Kp + 128;
        float* Cp = catp + (size_t)b * NTOK * 256 + h * 32;

        qk_kernel<<<dim3(16, 64), 256>>>(Qp, Kp);
        softmax_kernel<<<NTOK, 256>>>();
        gemm_nn<32><<<dim3(1, 64), 256>>>(attnp, N1_, Vp, 256, (const float*)0,
                                          Cp, 256, NTOK, 32, N1_, 1.f);
        colsum_kernel<<<dim3(4, 32), 256>>>(gp + b * N1_);
    }

    // branch 2 windowed attention
    attn2_kernel<<<B_ * 16 * 16, 128>>>(q2p, kv2p);

    // lepe depthwise conv + add into cat
    lepe_add_kernel<<<B_ * NTOK, 256>>>(lcw, lcb);

    // final projection: out = 2*(cat @ proj_w + proj_b)
    gemm_nn<64><<<dim3(4, 256), 256>>>(catp, 256, pw, 256, pb, out, 256,
                                       B_*NTOK, 256, 256, 2.f);

    // masks
    mask_kernel<<<64, 256>>>(out);
}

// round 2
// speedup vs baseline: 2.8743x; 2.8743x over previous
#include <cuda_runtime.h>
#include <math.h>

#define B_    4
#define NTOK  4096
#define C_    256
#define H_    64
#define W_    64
#define NH2   4
#define N1_   1024

#define OUT_MAIN (B_*NTOK*C_)
#define OUT_M1   (OUT_MAIN)
#define OUT_M2   (OUT_MAIN + B_*NTOK)

static __device__ float d_q1[B_*NTOK*128];
static __device__ float d_q2[B_*NTOK*128];
static __device__ float d_kv2[B_*NTOK*C_];
static __device__ float d_lepe[B_*NTOK*C_];
static __device__ float d_xsraw[B_*N1_*C_];
static __device__ float d_xs[B_*N1_*C_];
static __device__ float d_kv1[B_*N1_*C_];
static __device__ float d_cat[B_*NTOK*C_];
static __device__ float d_g[B_*N1_];
static __device__ float d_lm[B_*NTOK];
static __device__ float d_srw[1024*C_];

__device__ __constant__ float ATT_SCALE = 0.17677669529663687f; // 1/sqrt(32)

// ---------------------------------------------------------------------------
// SGEMM 128x64x16, 256 threads, 8x4 microtile, float4 smem reads.
// C[M,N] = alpha * (A[M,K] @ B[K,N] + bias[N]).  M%128==0, N%64==0, K%16==0.
// ---------------------------------------------------------------------------
__global__ void __launch_bounds__(256) gemm128(
    const float* __restrict__ A, int lda,
    const float* __restrict__ Bm, int ldb,
    const float* __restrict__ bias,
    float* __restrict__ Cm, int ldc,
    int K, float alpha)
{
    __shared__ float As[16][132];
    __shared__ float Bs[16][64];
    int m0 = blockIdx.y * 128, n0 = blockIdx.x * 64;
    int tid = threadIdx.x, tx = tid & 15, ty = tid >> 4;

    float acc[8][4];
#pragma unroll
    for (int i = 0; i < 8; i++)
#pragma unroll
        for (int j = 0; j < 4; j++) acc[i][j] = 0.f;

    for (int k0 = 0; k0 < K; k0 += 16) {
#pragma unroll
        for (int l = 0; l < 2; l++) {
            int idx = tid + l * 256;
            int row = idx >> 2, kq = idx & 3;
            float4 v = *(const float4*)(A + (size_t)(m0 + row) * lda + k0 + kq * 4);
            As[kq*4+0][row] = v.x; As[kq*4+1][row] = v.y;
            As[kq*4+2][row] = v.z; As[kq*4+3][row] = v.w;
        }
        {
            int kr = tid >> 4, cq = tid & 15;
            *(float4*)&Bs[kr][cq*4] =
                *(const float4*)(Bm + (size_t)(k0 + kr) * ldb + n0 + cq * 4);
        }
        __syncthreads();
#pragma unroll
        for (int k = 0; k < 16; k++) {
            float4 a0 = *(float4*)&As[k][ty*8];
            float4 a1 = *(float4*)&As[k][ty*8+4];
            float4 bv = *(float4*)&Bs[k][tx*4];
            float a[8] = {a0.x,a0.y,a0.z,a0.w,a1.x,a1.y,a1.z,a1.w};
            float bb[4] = {bv.x,bv.y,bv.z,bv.w};
#pragma unroll
            for (int i = 0; i < 8; i++)
#pragma unroll
                for (int j = 0; j < 4; j++) acc[i][j] += a[i]*bb[j];
        }
        __syncthreads();
    }
    float bb0 = bias[n0+tx*4+0], bb1 = bias[n0+tx*4+1];
    float bb2 = bias[n0+tx*4+2], bb3 = bias[n0+tx*4+3];
#pragma unroll
    for (int i = 0; i < 8; i++) {
        float4 o = make_float4(alpha*(acc[i][0]+bb0), alpha*(acc[i][1]+bb1),
                               alpha*(acc[i][2]+bb2), alpha*(acc[i][3]+bb3));
        *(float4*)(Cm + (size_t)(m0+ty*8+i)*ldc + n0 + tx*4) = o;
    }
}

// ---------------------------------------------------------------------------
// sr weight repack: d_srw[(dd*256+ci)*256+co] = sr_w[co,ci,di,dj], dd=di*2+dj
// ---------------------------------------------------------------------------
__global__ void repack_srw(const float* __restrict__ w)
{
    int idx = blockIdx.x * 256 + threadIdx.x;   // 1024*256
    int co = idx & 255;
    int k  = idx >> 8;
    int dd = k >> 8, ci = k & 255;
    d_srw[idx] = w[co * 1024 + ci * 4 + dd];
}

// ---------------------------------------------------------------------------
// sr conv as gather-GEMM with the 128x64 tiling. M=4096, N=256, K=1024.
// ---------------------------------------------------------------------------
__global__ void __launch_bounds__(256) srconv128(
    const float* __restrict__ x, const float* __restrict__ bias)
{
    __shared__ float As[16][132];
    __shared__ float Bs[16][64];
    int m0 = blockIdx.y * 128, n0 = blockIdx.x * 64;
    int tid = threadIdx.x, tx = tid & 15, ty = tid >> 4;

    float acc[8][4];
#pragma unroll
    for (int i = 0; i < 8; i++)
#pragma unroll
        for (int j = 0; j < 4; j++) acc[i][j] = 0.f;

    for (int k0 = 0; k0 < 1024; k0 += 16) {
        int dd = k0 >> 8;
        int di = dd >> 1, dj = dd & 1;
#pragma unroll
        for (int l = 0; l < 2; l++) {
            int idx = tid + l * 256;
            int row = idx >> 2, kq = idx & 3;
            int r = m0 + row;
            int b = r >> 10, p = r & 1023;
            int ii = p >> 5, jj = p & 31;
            int n = (2 * ii + di) * W_ + 2 * jj + dj;
            int ci = (k0 & 255) + kq * 4;
            float4 v = *(const float4*)(x + (size_t)((b << 12) + n) * C_ + ci);
            As[kq*4+0][row] = v.x; As[kq*4+1][row] = v.y;
            As[kq*4+2][row] = v.z; As[kq*4+3][row] = v.w;
        }
        {
            int kr = tid >> 4, cq = tid & 15;
            *(float4*)&Bs[kr][cq*4] =
                *(const float4*)(d_srw + (size_t)(k0 + kr) * 256 + n0 + cq * 4);
        }
        __syncthreads();
#pragma unroll
        for (int k = 0; k < 16; k++) {
            float4 a0 = *(float4*)&As[k][ty*8];
            float4 a1 = *(float4*)&As[k][ty*8+4];
            float4 bv = *(float4*)&Bs[k][tx*4];
            float a[8] = {a0.x,a0.y,a0.z,a0.w,a1.x,a1.y,a1.z,a1.w};
            float bb[4] = {bv.x,bv.y,bv.z,bv.w};
#pragma unroll
            for (int i = 0; i < 8; i++)
#pragma unroll
                for (int j = 0; j < 4; j++) acc[i][j] += a[i]*bb[j];
        }
        __syncthreads();
    }
    float bb0 = bias[n0+tx*4+0], bb1 = bias[n0+tx*4+1];
    float bb2 = bias[n0+tx*4+2], bb3 = bias[n0+tx*4+3];
#pragma unroll
    for (int i = 0; i < 8; i++) {
        float4 o = make_float4(acc[i][0]+bb0, acc[i][1]+bb1,
                               acc[i][2]+bb2, acc[i][3]+bb3);
        *(float4*)(d_xsraw + (size_t)(m0+ty*8+i)*C_ + n0 + tx*4) = o;
    }
}

// ---------------------------------------------------------------------------
// LayerNorm (over 256) + exact GELU. One block per row, 256 threads.
// ---------------------------------------------------------------------------
__global__ void ln_gelu_kernel(const float* __restrict__ nw,
                               const float* __restrict__ nb)
{
    __shared__ float sh[8];
    int r = blockIdx.x, c = threadIdx.x;
    float v = d_xsraw[(size_t)r * C_ + c];

    float s = v;
#pragma unroll
    for (int o = 16; o > 0; o >>= 1) s += __shfl_xor_sync(0xffffffffu, s, o);
    if ((c & 31) == 0) sh[c >> 5] = s;
    __syncthreads();
    if (c < 32) {
        float t = (c < 8) ? sh[c] : 0.f;
#pragma unroll
        for (int o = 4; o > 0; o >>= 1) t += __shfl_xor_sync(0xffffffffu, t, o);
        if (c == 0) sh[0] = t;
    }
    __syncthreads();
    float mean = sh[0] * (1.f / 256.f);
    __syncthreads();

    float dv = v - mean;
    float q = dv * dv;
#pragma unroll
    for (int o = 16; o > 0; o >>= 1) q += __shfl_xor_sync(0xffffffffu, q, o);
    if ((c & 31) == 0) sh[c >> 5] = q;
    __syncthreads();
    if (c < 32) {
        float t = (c < 8) ? sh[c] : 0.f;
#pragma unroll
        for (int o = 4; o > 0; o >>= 1) t += __shfl_xor_sync(0xffffffffu, t, o);
        if (c == 0) sh[0] = t;
    }
    __syncthreads();
    float var = sh[0] * (1.f / 256.f);

    float y = dv * rsqrtf(var + 1e-5f) * nw[c] + nb[c];
    d_xs[(size_t)r * C_ + c] = 0.5f * y * (1.f + erff(y * 0.70710678118654752f));
}

// ---------------------------------------------------------------------------
// Fused branch-1 attention: per block = one (bh, 32-query tile).
// QK (Q in regs, K streamed, double-buffered) -> scores in smem ->
// softmax (store exp, keep 1/sum) -> column sums -> AV (V streamed) -> cat.
// grid (128, 16), 256 threads, ~149KB dynamic smem.
// ---------------------------------------------------------------------------
__global__ void __launch_bounds__(256) attn1_fused(
    const float* __restrict__ q1, const float* __restrict__ kv1,
    float* __restrict__ cat, float* __restrict__ g)
{
    extern __shared__ float sm[];
    float* S   = sm;                 // 32*1024
    float* Qs  = sm + 32*1024;       // 32*33
    float* inv = Qs + 32*33;         // 32
    float* KV  = inv + 32;           // 2*2112 union (KsT double buf / Vs)

    int tid = threadIdx.x, tx = tid & 15, ty = tid >> 4;
    int bh = blockIdx.y; int b = bh >> 2, h = bh & 3;
    int q0 = blockIdx.x * 32;

    const float* Qg = q1 + (size_t)(b * NTOK + q0) * 128 + h * 32;
    const float* Kg = kv1 + (size_t)b * N1_ * 256 + h * 32;
    const float* Vg = Kg + 128;

    // Q tile -> smem (coalesced), then to regs with scale folded in
    {
        int qq = tid >> 3, dq = tid & 7;
        float4 v = *(const float4*)(Qg + (size_t)qq * 128 + dq * 4);
        Qs[qq*33 + dq*4+0] = v.x; Qs[qq*33 + dq*4+1] = v.y;
        Qs[qq*33 + dq*4+2] = v.z; Qs[qq*33 + dq*4+3] = v.w;
    }
    // K tile 0 -> KsT buf 0 (transposed, pad 65)
    {
        int kk = tid >> 3, dq = tid & 7;
        float4 v0 = *(const float4*)(Kg + (size_t)kk * 256 + dq * 4);
        float4 v1 = *(const float4*)(Kg + (size_t)(kk+32) * 256 + dq * 4);
        float* Kb = KV;
        Kb[(dq*4+0)*65 + kk] = v0.x; Kb[(dq*4+1)*65 + kk] = v0.y;
        Kb[(dq*4+2)*65 + kk] = v0.z; Kb[(dq*4+3)*65 + kk] = v0.w;
        Kb[(dq*4+0)*65 + kk+32] = v1.x; Kb[(dq*4+1)*65 + kk+32] = v1.y;
        Kb[(dq*4+2)*65 + kk+32] = v1.z; Kb[(dq*4+3)*65 + kk+32] = v1.w;
    }
    __syncthreads();

    float sc = ATT_SCALE;
    float qr[2][32];
#pragma unroll
    for (int i = 0; i < 2; i++)
#pragma unroll
        for (int d = 0; d < 32; d++)
            qr[i][d] = Qs[(ty*2+i)*33 + d] * sc;

    // ---- QK over 16 key tiles (double buffered) ----
    int kk0 = tid >> 3, dq0 = tid & 7;
    for (int t = 0; t < 16; t++) {
        float4 p0, p1;
        bool pf = (t < 15);
        if (pf) {
            const float* src = Kg + (size_t)((t+1)*64) * 256;
            p0 = *(const float4*)(src + (size_t)kk0 * 256 + dq0 * 4);
            p1 = *(const float4*)(src + (size_t)(kk0+32) * 256 + dq0 * 4);
        }
        const float* Kb = KV + (t & 1) * 2112;
        float acc[2][4];
#pragma unroll
        for (int i = 0; i < 2; i++)
#pragma unroll
            for (int j = 0; j < 4; j++) acc[i][j] = 0.f;
#pragma unroll
        for (int d = 0; d < 32; d++) {
            float b0 = Kb[d*65 + tx*4+0];
            float b1 = Kb[d*65 + tx*4+1];
            float b2 = Kb[d*65 + tx*4+2];
            float b3 = Kb[d*65 + tx*4+3];
#pragma unroll
            for (int i = 0; i < 2; i++) {
                float a = qr[i][d];
                acc[i][0] += a*b0; acc[i][1] += a*b1;
                acc[i][2] += a*b2; acc[i][3] += a*b3;
            }
        }
#pragma unroll
        for (int i = 0; i < 2; i++)
            *(float4*)&S[(size_t)(ty*2+i)*1024 + t*64 + tx*4] =
                make_float4(acc[i][0], acc[i][1], acc[i][2], acc[i][3]);
        if (pf) {
            float* Kn = KV + ((t+1) & 1) * 2112;
            Kn[(dq0*4+0)*65 + kk0] = p0.x; Kn[(dq0*4+1)*65 + kk0] = p0.y;
            Kn[(dq0*4+2)*65 + kk0] = p0.z; Kn[(dq0*4+3)*65 + kk0] = p0.w;
            Kn[(dq0*4+0)*65 + kk0+32] = p1.x; Kn[(dq0*4+1)*65 + kk0+32] = p1.y;
            Kn[(dq0*4+2)*65 + kk0+32] = p1.z; Kn[(dq0*4+3)*65 + kk0+32] = p1.w;
        }
        __syncthreads();
    }

    // ---- softmax: store exp, keep inv[row]; 8 warps x 4 rows ----
    {
        int warp = tid >> 5, lane = tid & 31;
#pragma unroll
        for (int rr = 0; rr < 4; rr++) {
            int row = warp * 4 + rr;
            float* Sr = S + (size_t)row * 1024;
            float m = -1e30f;
#pragma unroll
            for (int i = 0; i < 32; i++) m = fmaxf(m, Sr[lane + 32*i]);
#pragma unroll
            for (int o = 16; o > 0; o >>= 1)
                m = fmaxf(m, __shfl_xor_sync(0xffffffffu, m, o));
            float s = 0.f;
#pragma unroll
            for (int i = 0; i < 32; i++) {
                float e = __expf(Sr[lane + 32*i] - m);
                Sr[lane + 32*i] = e;
                s += e;
            }
#pragma unroll
            for (int o = 16; o > 0; o >>= 1)
                s += __shfl_xor_sync(0xffffffffu, s, o);
            if (lane == 0) inv[row] = 1.f / s;
        }
    }
    __syncthreads();

    // ---- column sums -> g (normalized) ----
    {
        float a0 = 0.f, a1 = 0.f, a2 = 0.f, a3 = 0.f;
#pragma unroll
        for (int q = 0; q < 32; q++) {
            float iv = inv[q];
            const float* Sq = S + (size_t)q * 1024;
            a0 += Sq[tid      ] * iv;
            a1 += Sq[tid + 256] * iv;
            a2 += Sq[tid + 512] * iv;
            a3 += Sq[tid + 768] * iv;
        }
        float* gb = g + b * N1_;
        atomicAdd(&gb[tid      ], a0);
        atomicAdd(&gb[tid + 256], a1);
        atomicAdd(&gb[tid + 512], a2);
        atomicAdd(&gb[tid + 768], a3);
    }

    // ---- AV: each thread 2q x 4d over half the keys; shuffle-combine ----
    float* Vs = KV;                        // [128][33]
    int khalf = (tx >> 3) * 512;
    int dgrp  = (tx & 7) * 4;
    float av[2][4];
#pragma unroll
    for (int i = 0; i < 2; i++)
#pragma unroll
        for (int j = 0; j < 4; j++) av[i][j] = 0.f;

    for (int r = 0; r < 8; r++) {
        __syncthreads();                   // prior round reads done
#pragma unroll
        for (int l = 0; l < 4; l++) {
            int idx = tid + l * 256;       // 1024 float4
            int vr = idx >> 3, dq = idx & 7;
            int key = (vr < 64) ? (r*64 + vr) : (512 + r*64 + (vr - 64));
            float4 v = *(const float4*)(Vg + (size_t)key * 256 + dq * 4);
            Vs[vr*33 + dq*4+0] = v.x; Vs[vr*33 + dq*4+1] = v.y;
            Vs[vr*33 + dq*4+2] = v.z; Vs[vr*33 + dq*4+3] = v.w;
        }
        __syncthreads();
        int vbase = (tx >> 3) * 64;
#pragma unroll 4
        for (int kk = 0; kk < 64; kk++) {
            int kabs = khalf + r*64 + kk;
            float e0 = S[(size_t)(ty*2+0)*1024 + kabs];
            float e1 = S[(size_t)(ty*2+1)*1024 + kabs];
            const float* vrow = Vs + (vbase + kk)*33 + dgrp;
            float v0 = vrow[0], v1 = vrow[1], v2 = vrow[2], v3 = vrow[3];
            av[0][0] += e0*v0; av[0][1] += e0*v1; av[0][2] += e0*v2; av[0][3] += e0*v3;
            av[1][0] += e1*v0; av[1][1] += e1*v1; av[1][2] += e1*v2; av[1][3] += e1*v3;
        }
    }
#pragma unroll
    for (int i = 0; i < 2; i++)
#pragma unroll
        for (int j = 0; j < 4; j++)
            av[i][j] += __shfl_xor_sync(0xffffffffu, av[i][j], 8);

    if ((tid & 8) == 0) {
#pragma unroll
        for (int i = 0; i < 2; i++) {
            int q = ty*2 + i;
            float iv = inv[q];
            float4 o = make_float4(av[i][0]*iv, av[i][1]*iv, av[i][2]*iv, av[i][3]*iv);
            *(float4*)&cat[(size_t)(b*NTOK + q0 + q)*256 + h*32 + dgrp] = o;
        }
    }
}

// ---------------------------------------------------------------------------
// Windowed attention (branch 2), unchanged from R1.
// ---------------------------------------------------------------------------
__global__ void attn2_kernel(const float* __restrict__ q2,
                             const float* __restrict__ kv2)
{
    int win = blockIdx.x;
    int b = win >> 8, rem = win & 255, gy = rem >> 4, gx = rem & 15;
    int tid = threadIdx.x, h = tid >> 5, lane = tid & 31;

    __shared__ float Qs[4][16][32];
    __shared__ float Ks[4][16][32];
    __shared__ float Vs[4][16][32];
    __shared__ float csum[16];

    for (int i = lane; i < 16 * 32; i += 32) {
        int t = i >> 5, dd = i & 31;
        int n = (gy * 4 + (t >> 2)) * W_ + gx * 4 + (t & 3);
        Qs[h][t][dd] = q2 [(size_t)(b * NTOK + n) * 128 + h * 32 + dd];
        Ks[h][t][dd] = kv2[(size_t)(b * NTOK + n) * 256 + h * 32 + dd];
        Vs[h][t][dd] = kv2[(size_t)(b * NTOK + n) * 256 + 128 + h * 32 + dd];
    }
    if (tid < 16) csum[tid] = 0.f;
    __syncthreads();

    if (lane < 16) {
        int q = lane;
        float s[16];
        float mx = -1e30f;
#pragma unroll
        for (int m = 0; m < 16; m++) {
            float dot = 0.f;
#pragma unroll
            for (int dd = 0; dd < 32; dd++) dot += Qs[h][q][dd] * Ks[h][m][dd];
            s[m] = dot * ATT_SCALE;
            mx = fmaxf(mx, s[m]);
        }
        float sum = 0.f;
#pragma unroll
        for (int m = 0; m < 16; m++) { s[m] = __expf(s[m] - mx); sum += s[m]; }
        float iv = 1.f / sum;
#pragma unroll
        for (int m = 0; m < 16; m++) {
            s[m] *= iv;
            atomicAdd(&csum[m], s[m]);
        }
        int nq = (gy * 4 + (q >> 2)) * W_ + gx * 4 + (q & 3);
        float* outp = d_cat + (size_t)(b * NTOK + nq) * 256 + 128 + h * 32;
#pragma unroll
        for (int dd = 0; dd < 32; dd++) {
            float o = 0.f;
#pragma unroll
            for (int m = 0; m < 16; m++) o += s[m] * Vs[h][m][dd];
            outp[dd] = o;
        }
    }
    __syncthreads();
    if (tid < 16) {
        int m = tid;
        int np = (gy * 4 + (m >> 2)) * W_ + gx * 4 + (m & 3);
        d_lm[b * NTOK + np] = csum[m] * (1.f / 64.f);
    }
}

// ---------------------------------------------------------------------------
// LePE depthwise 3x3 conv (+bias) added into d_cat. One block per token.
// ---------------------------------------------------------------------------
__global__ void lepe_add_kernel(const float* __restrict__ w9,
                                const float* __restrict__ cb)
{
    int r = blockIdx.x;
    int c = threadIdx.x;
    int b = r >> 12, n = r & 4095, y = n >> 6, x = n & 63;
    float wv[9];
#pragma unroll
    for (int t = 0; t < 9; t++) wv[t] = w9[c * 9 + t];
    float acc = cb[c];
#pragma unroll
    for (int dy = 0; dy < 3; dy++) {
        int yy = y + dy - 1;
        if (yy < 0 || yy >= H_) continue;
#pragma unroll
        for (int dx = 0; dx < 3; dx++) {
            int xx = x + dx - 1;
            if (xx < 0 || xx >= W_) continue;
            acc += wv[dy * 3 + dx] *
                   d_lepe[(size_t)(b * NTOK + yy * W_ + xx) * C_ + c];
        }
    }
    d_cat[(size_t)r * C_ + c] += acc;
}

// ---------------------------------------------------------------------------
// Masks
// ---------------------------------------------------------------------------
__global__ void mask_kernel(float* __restrict__ out)
{
    int idx = blockIdx.x * 256 + threadIdx.x;
    int b = idx >> 12, pos = idx & 4095, y = pos >> 6, x = pos & 63;
    float gv = d_g[b * N1_ + (y >> 1) * 32 + (x >> 1)] * (1.f / (NH2 * NTOK));
    float val = d_lm[idx] + gv;
    out[OUT_M1 + idx] = val;
    out[OUT_M2 + b * NTOK + x * 64 + y] = val;
}

// ---------------------------------------------------------------------------
extern "C" void kernel_launch(void* const* d_in, const int* in_sizes, int n_in,
                              void* d_out, int out_size)
{
    const float* x      = (const float*)d_in[0];
    const float* q1_w   = (const float*)d_in[1];
    const float* q1_b   = (const float*)d_in[2];
    const float* kv1_w  = (const float*)d_in[3];
    const float* kv1_b  = (const float*)d_in[4];
    const float* q2_w   = (const float*)d_in[5];
    const float* q2_b   = (const float*)d_in[6];
    const float* kv2_w  = (const float*)d_in[7];
    const float* kv2_b  = (const float*)d_in[8];
    const float* lepe_w = (const float*)d_in[9];
    const float* lepe_b = (const float*)d_in[10];
    const float* lcw    = (const float*)d_in[11];
    const float* lcb    = (const float*)d_in[12];
    const float* sr_w   = (const float*)d_in[13];
    const float* sr_b   = (const float*)d_in[14];
    const float* nw     = (const float*)d_in[15];
    const float* nb     = (const float*)d_in[16];
    const float* pw     = (const float*)d_in[17];
    const float* pb     = (const float*)d_in[18];
    float* out = (float*)d_out;

    void* p;
    float *q1p, *q2p, *kv2p, *lepep, *xsp, *kv1p, *catp, *gp;
    cudaGetSymbolAddress(&p, d_q1);   q1p   = (float*)p;
    cudaGetSymbolAddress(&p, d_q2);   q2p   = (float*)p;
    cudaGetSymbolAddress(&p, d_kv2);  kv2p  = (float*)p;
    cudaGetSymbolAddress(&p, d_lepe); lepep = (float*)p;
    cudaGetSymbolAddress(&p, d_xs);   xsp   = (float*)p;
    cudaGetSymbolAddress(&p, d_kv1);  kv1p  = (float*)p;
    cudaGetSymbolAddress(&p, d_cat);  catp  = (float*)p;
    cudaGetSymbolAddress(&p, d_g);    gp    = (float*)p;

    const int ATTN_SMEM = (32*1024 + 32*33 + 32 + 2*2112) * 4;  // 152320 B
    cudaFuncSetAttribute(attn1_fused,
                         cudaFuncAttributeMaxDynamicSharedMemorySize, ATTN_SMEM);

    cudaMemsetAsync(gp, 0, B_ * N1_ * sizeof(float));

    repack_srw<<<1024, 256>>>(sr_w);

    // projections from x
    gemm128<<<dim3(2, 128), 256>>>(x, 256, q1_w, 128, q1_b, q1p, 128, 256, 1.f);
    gemm128<<<dim3(2, 128), 256>>>(x, 256, q2_w, 128, q2_b, q2p, 128, 256, 1.f);
    gemm128<<<dim3(4, 128), 256>>>(x, 256, kv2_w, 256, kv2_b, kv2p, 256, 256, 1.f);
    gemm128<<<dim3(4, 128), 256>>>(x, 256, lepe_w, 256, lepe_b, lepep, 256, 256, 1.f);

    // sr conv -> LN+GELU -> kv1
    srconv128<<<dim3(4, 32), 256>>>(x, sr_b);
    ln_gelu_kernel<<<B_ * N1_, 256>>>(nw, nb);
    gemm128<<<dim3(4, 32), 256>>>(xsp, 256, kv1_w, 256, kv1_b, kv1p, 256, 256, 1.f);

    // fused branch-1 attention (all 16 bh slices)
    attn1_fused<<<dim3(128, 16), 256, ATTN_SMEM>>>(q1p, kv1p, catp, gp);

    // branch 2 windowed attention
    attn2_kernel<<<B_ * 16 * 16, 128>>>(q2p, kv2p);

    // lepe depthwise conv + add
    lepe_add_kernel<<<B_ * NTOK, 256>>>(lcw, lcb);

    // final projection: out = 2*(cat @ proj_w + proj_b)
    gemm128<<<dim3(4, 128), 256>>>(catp, 256, pw, 256, pb, out, 256, 256, 2.f);

    // masks
    mask_kernel<<<64, 256>>>(out);
}

// round 4
// speedup vs baseline: 3.0110x; 1.0476x over previous
#include <cuda_runtime.h>
#include <cuda_bf16.h>
#include <math.h>
#include <stdint.h>

#define B_    4
#define NTOK  4096
#define C_    256
#define H_    64
#define W_    64
#define NH2   4
#define N1_   1024

#define OUT_MAIN (B_*NTOK*C_)
#define OUT_M1   (OUT_MAIN)
#define OUT_M2   (OUT_MAIN + B_*NTOK)

// fp32 intermediates
static __device__ float d_q1[B_*NTOK*128];
static __device__ float d_q2[B_*NTOK*128];
static __device__ float d_kv2[B_*NTOK*C_];
static __device__ float d_lepe[B_*NTOK*C_];
static __device__ float d_xsraw[B_*N1_*C_];
static __device__ float d_kv1[B_*N1_*C_];
static __device__ float d_cat[B_*NTOK*C_];
static __device__ float d_g[B_*N1_];
static __device__ float d_lm[B_*NTOK];

// bf16 split buffers
static __device__ __nv_bfloat16 d_xh[B_*NTOK*C_],  d_xl[B_*NTOK*C_];
static __device__ __nv_bfloat16 d_wh[327680],      d_wl[327680];
static __device__ __nv_bfloat16 d_srwh[1024*C_],   d_srwl[1024*C_];
static __device__ __nv_bfloat16 d_agh[4096*1024],  d_agl[4096*1024];
static __device__ __nv_bfloat16 d_xsh[B_*N1_*C_],  d_xsl[B_*N1_*C_];
static __device__ __nv_bfloat16 d_cath[B_*NTOK*C_],d_catl[B_*NTOK*C_];

#define WOFF_Q1   0
#define WOFF_Q2   32768
#define WOFF_KV2  65536
#define WOFF_LEPE 131072
#define WOFF_KV1  196608
#define WOFF_PROJ 262144

__device__ __constant__ float ATT_SCALE = 0.17677669529663687f; // 1/sqrt(32)

#define MMA_BF16(c, a, b) \
  asm volatile("mma.sync.aligned.m16n8k16.row.col.f32.bf16.bf16.f32 " \
    "{%0,%1,%2,%3}, {%4,%5,%6,%7}, {%8,%9}, {%0,%1,%2,%3};" \
    : "+f"((c)[0]), "+f"((c)[1]), "+f"((c)[2]), "+f"((c)[3]) \
    : "r"((a)[0]), "r"((a)[1]), "r"((a)[2]), "r"((a)[3]), \
      "r"((b)[0]), "r"((b)[1]))

// ---------------------------------------------------------------------------
// bf16-split GEMM: C[M,N] = alpha*((Ah+Al)[M,K] @ (Bh+Bl)[K,N] + bias)
// computed as Ah*Bh + Al*Bh + Ah*Bl.  BM=128, BN=64, BK=32, 256 threads.
// ---------------------------------------------------------------------------
__global__ void __launch_bounds__(256) gemm_mma(
    const __nv_bfloat16* __restrict__ Ah, const __nv_bfloat16* __restrict__ Al, int lda,
    const __nv_bfloat16* __restrict__ Bh, const __nv_bfloat16* __restrict__ Bl, int ldb,
    const float* __restrict__ bias, float* __restrict__ Cm, int ldc,
    int K, float alpha)
{
    __shared__ uint16_t sAh[128*40], sAl[128*40];
    __shared__ uint16_t sBh[64*40],  sBl[64*40];
    int tid = threadIdx.x, lane = tid & 31, warp = tid >> 5;
    int wm = warp >> 1, wn = warp & 1;
    int m0 = blockIdx.y * 128, n0 = blockIdx.x * 64;
    int g = lane >> 2, t = lane & 3;

    float acc[2][4][4];
#pragma unroll
    for (int i = 0; i < 2; i++)
#pragma unroll
        for (int j = 0; j < 4; j++)
#pragma unroll
            for (int c = 0; c < 4; c++) acc[i][j][c] = 0.f;

    for (int k0 = 0; k0 < K; k0 += 32) {
#pragma unroll
        for (int s = 0; s < 4; s++) {
            int v = tid + s * 256;
            int row = v >> 3, ko = (v & 7) * 4;
            size_t off = (size_t)(m0 + row) * lda + k0 + ko;
            *(uint2*)&sAh[row*40 + ko] = *(const uint2*)(const void*)(Ah + off);
            *(uint2*)&sAl[row*40 + ko] = *(const uint2*)(const void*)(Al + off);
        }
#pragma unroll
        for (int s = 0; s < 2; s++) {
            int v = tid + s * 256;
            int kr = v >> 4, no = (v & 15) * 4;
            size_t off = (size_t)(k0 + kr) * ldb + n0 + no;
            uint2 hv = *(const uint2*)(const void*)(Bh + off);
            uint2 lv = *(const uint2*)(const void*)(Bl + off);
            const uint16_t* hp = (const uint16_t*)&hv;
            const uint16_t* lp = (const uint16_t*)&lv;
#pragma unroll
            for (int j = 0; j < 4; j++) {
                sBh[(no + j)*40 + kr] = hp[j];
                sBl[(no + j)*40 + kr] = lp[j];
            }
        }
        __syncthreads();

#pragma unroll
        for (int kk = 0; kk < 32; kk += 16) {
            uint32_t ahr[2][4], alr[2][4], bhr[4][2], blr[4][2];
#pragma unroll
            for (int i = 0; i < 2; i++) {
                int r0 = wm*32 + i*16 + g;
                ahr[i][0] = *(const uint32_t*)&sAh[r0*40     + kk + t*2];
                ahr[i][1] = *(const uint32_t*)&sAh[(r0+8)*40 + kk + t*2];
                ahr[i][2] = *(const uint32_t*)&sAh[r0*40     + kk + 8 + t*2];
                ahr[i][3] = *(const uint32_t*)&sAh[(r0+8)*40 + kk + 8 + t*2];
                alr[i][0] = *(const uint32_t*)&sAl[r0*40     + kk + t*2];
                alr[i][1] = *(const uint32_t*)&sAl[(r0+8)*40 + kk + t*2];
                alr[i][2] = *(const uint32_t*)&sAl[r0*40     + kk + 8 + t*2];
                alr[i][3] = *(const uint32_t*)&sAl[(r0+8)*40 + kk + 8 + t*2];
            }
#pragma unroll
            for (int j = 0; j < 4; j++) {
                int nn = wn*32 + j*8 + g;
                bhr[j][0] = *(const uint32_t*)&sBh[nn*40 + kk + t*2];
                bhr[j][1] = *(const uint32_t*)&sBh[nn*40 + kk + 8 + t*2];
                blr[j][0] = *(const uint32_t*)&sBl[nn*40 + kk + t*2];
                blr[j][1] = *(const uint32_t*)&sBl[nn*40 + kk + 8 + t*2];
            }
#pragma unroll
            for (int i = 0; i < 2; i++)
#pragma unroll
                for (int j = 0; j < 4; j++) {
                    MMA_BF16(acc[i][j], ahr[i], bhr[j]);
                    MMA_BF16(acc[i][j], alr[i], bhr[j]);
                    MMA_BF16(acc[i][j], ahr[i], blr[j]);
                }
        }
        __syncthreads();
    }

#pragma unroll
    for (int i = 0; i < 2; i++)
#pragma unroll
        for (int j = 0; j < 4; j++) {
            int row0 = m0 + wm*32 + i*16 + g;
            int col  = n0 + wn*32 + j*8 + t*2;
            float b0 = bias[col], b1 = bias[col+1];
            float2 o0 = make_float2(alpha*(acc[i][j][0]+b0), alpha*(acc[i][j][1]+b1));
            float2 o1 = make_float2(alpha*(acc[i][j][2]+b0), alpha*(acc[i][j][3]+b1));
            *(float2*)(Cm + (size_t)row0    *ldc + col) = o0;
            *(float2*)(Cm + (size_t)(row0+8)*ldc + col) = o1;
        }
}

// ---------------------------------------------------------------------------
__global__ void cvt_split(const float* __restrict__ in,
                          __nv_bfloat16* __restrict__ h,
                          __nv_bfloat16* __restrict__ l, int n4)
{
    int i = blockIdx.x * 256 + threadIdx.x;
    if (i >= n4) return;
    float4 v = ((const float4*)in)[i];
    __nv_bfloat16 h0 = __float2bfloat16(v.x), h1 = __float2bfloat16(v.y);
    __nv_bfloat16 h2 = __float2bfloat16(v.z), h3 = __float2bfloat16(v.w);
    __nv_bfloat16 l0 = __float2bfloat16(v.x - __bfloat162float(h0));
    __nv_bfloat16 l1 = __float2bfloat16(v.y - __bfloat162float(h1));
    __nv_bfloat16 l2 = __float2bfloat16(v.z - __bfloat162float(h2));
    __nv_bfloat16 l3 = __float2bfloat16(v.w - __bfloat162float(h3));
    ((__nv_bfloat162*)h)[i*2]   = __nv_bfloat162(h0, h1);
    ((__nv_bfloat162*)h)[i*2+1] = __nv_bfloat162(h2, h3);
    ((__nv_bfloat162*)l)[i*2]   = __nv_bfloat162(l0, l1);
    ((__nv_bfloat162*)l)[i*2+1] = __nv_bfloat162(l2, l3);
}

// ---------------------------------------------------------------------------
__global__ void repack_srw_bf(const float* __restrict__ w)
{
    int idx = blockIdx.x * 256 + threadIdx.x;   // 262144
    int co = idx & 255;
    int k  = idx >> 8;
    int dd = k >> 8, ci = k & 255;
    float v = w[co * 1024 + ci * 4 + dd];
    __nv_bfloat16 h = __float2bfloat16(v);
    d_srwh[idx] = h;
    d_srwl[idx] = __float2bfloat16(v - __bfloat162float(h));
}

// ---------------------------------------------------------------------------
__global__ void srgather()
{
    int v = blockIdx.x * 256 + threadIdx.x;   // 1,048,576 uint2 groups
    int r = v >> 8, col4 = v & 255;
    int k = col4 * 4;
    int dd = k >> 8, ci = k & 255;
    int b = r >> 10, p = r & 1023;
    int ii = p >> 5, jj = p & 31;
    int di = dd >> 1, dj = dd & 1;
    int n = (2*ii + di) * W_ + 2*jj + dj;
    size_t src = ((size_t)(b * NTOK + n) * C_ + ci) >> 2;
    size_t dst = ((size_t)r * 1024 + k) >> 2;
    ((uint2*)(void*)d_agh)[dst] = ((const uint2*)(const void*)d_xh)[src];
    ((uint2*)(void*)d_agl)[dst] = ((const uint2*)(const void*)d_xl)[src];
}

// ---------------------------------------------------------------------------
__global__ void ln_gelu_kernel(const float* __restrict__ nw,
                               const float* __restrict__ nb)
{
    __shared__ float sh[8];
    int r = blockIdx.x, c = threadIdx.x;
    float v = d_xsraw[(size_t)r * C_ + c];

    float s = v;
#pragma unroll
    for (int o = 16; o > 0; o >>= 1) s += __shfl_xor_sync(0xffffffffu, s, o);
    if ((c & 31) == 0) sh[c >> 5] = s;
    __syncthreads();
    if (c < 32) {
        float t = (c < 8) ? sh[c] : 0.f;
#pragma unroll
        for (int o = 4; o > 0; o >>= 1) t += __shfl_xor_sync(0xffffffffu, t, o);
        if (c == 0) sh[0] = t;
    }
    __syncthreads();
    float mean = sh[0] * (1.f / 256.f);
    __syncthreads();

    float dv = v - mean;
    float q = dv * dv;
#pragma unroll
    for (int o = 16; o > 0; o >>= 1) q += __shfl_xor_sync(0xffffffffu, q, o);
    if ((c & 31) == 0) sh[c >> 5] = q;
    __syncthreads();
    if (c < 32) {
        float t = (c < 8) ? sh[c] : 0.f;
#pragma unroll
        for (int o = 4; o > 0; o >>= 1) t += __shfl_xor_sync(0xffffffffu, t, o);
        if (c == 0) sh[0] = t;
    }
    __syncthreads();
    float var = sh[0] * (1.f / 256.f);

    float y = dv * rsqrtf(var + 1e-5f) * nw[c] + nb[c];
    float ge = 0.5f * y * (1.f + erff(y * 0.70710678118654752f));
    __nv_bfloat16 h = __float2bfloat16(ge);
    d_xsh[(size_t)r * C_ + c] = h;
    d_xsl[(size_t)r * C_ + c] = __float2bfloat16(ge - __bfloat162float(h));
}

// ---------------------------------------------------------------------------
__global__ void __launch_bounds__(256) attn1_fused(
    const float* __restrict__ q1, const float* __restrict__ kv1,
    float* __restrict__ cat, float* __restrict__ g)
{
    extern __shared__ float sm[];
    float* S   = sm;
    float* Qs  = sm + 32*1024;
    float* inv = Qs + 32*33;
    float* KV  = inv + 32;

    int tid = threadIdx.x, tx = tid & 15, ty = tid >> 4;
    int bh = blockIdx.y; int b = bh >> 2, h = bh & 3;
    int q0 = blockIdx.x * 32;

    const float* Qg = q1 + (size_t)(b * NTOK + q0) * 128 + h * 32;
    const float* Kg = kv1 + (size_t)b * N1_ * 256 + h * 32;
    const float* Vg = Kg + 128;

    {
        int qq = tid >> 3, dq = tid & 7;
        float4 v = *(const float4*)(Qg + (size_t)qq * 128 + dq * 4);
        Qs[qq*33 + dq*4+0] = v.x; Qs[qq*33 + dq*4+1] = v.y;
        Qs[qq*33 + dq*4+2] = v.z; Qs[qq*33 + dq*4+3] = v.w;
    }
    {
        int kk = tid >> 3, dq = tid & 7;
        float4 v0 = *(const float4*)(Kg + (size_t)kk * 256 + dq * 4);
        float4 v1 = *(const float4*)(Kg + (size_t)(kk+32) * 256 + dq * 4);
        float* Kb = KV;
        Kb[(dq*4+0)*65 + kk] = v0.x; Kb[(dq*4+1)*65 + kk] = v0.y;
        Kb[(dq*4+2)*65 + kk] = v0.z; Kb[(dq*4+3)*65 + kk] = v0.w;
        Kb[(dq*4+0)*65 + kk+32] = v1.x; Kb[(dq*4+1)*65 + kk+32] = v1.y;
        Kb[(dq*4+2)*65 + kk+32] = v1.z; Kb[(dq*4+3)*65 + kk+32] = v1.w;
    }
    __syncthreads();

    float sc = ATT_SCALE;
    float qr[2][32];
#pragma unroll
    for (int i = 0; i < 2; i++)
#pragma unroll
        for (int d = 0; d < 32; d++)
            qr[i][d] = Qs[(ty*2+i)*33 + d] * sc;

    int kk0 = tid >> 3, dq0 = tid & 7;
    for (int t = 0; t < 16; t++) {
        float4 p0, p1;
        bool pf = (t < 15);
        if (pf) {
            const float* src = Kg + (size_t)((t+1)*64) * 256;
            p0 = *(const float4*)(src + (size_t)kk0 * 256 + dq0 * 4);
            p1 = *(const float4*)(src + (size_t)(kk0+32) * 256 + dq0 * 4);
        }
        const float* Kb = KV + (t & 1) * 2112;
        float acc[2][4];
#pragma unroll
        for (int i = 0; i < 2; i++)
#pragma unroll
            for (int j = 0; j < 4; j++) acc[i][j] = 0.f;
#pragma unroll
        for (int d = 0; d < 32; d++) {
            float b0 = Kb[d*65 + tx*4+0];
            float b1 = Kb[d*65 + tx*4+1];
            float b2 = Kb[d*65 + tx*4+2];
            float b3 = Kb[d*65 + tx*4+3];
#pragma unroll
            for (int i = 0; i < 2; i++) {
                float a = qr[i][d];
                acc[i][0] += a*b0; acc[i][1] += a*b1;
                acc[i][2] += a*b2; acc[i][3] += a*b3;
            }
        }
#pragma unroll
        for (int i = 0; i < 2; i++)
            *(float4*)&S[(size_t)(ty*2+i)*1024 + t*64 + tx*4] =
                make_float4(acc[i][0], acc[i][1], acc[i][2], acc[i][3]);
        if (pf) {
            float* Kn = KV + ((t+1) & 1) * 2112;
            Kn[(dq0*4+0)*65 + kk0] = p0.x; Kn[(dq0*4+1)*65 + kk0] = p0.y;
            Kn[(dq0*4+2)*65 + kk0] = p0.z; Kn[(dq0*4+3)*65 + kk0] = p0.w;
            Kn[(dq0*4+0)*65 + kk0+32] = p1.x; Kn[(dq0*4+1)*65 + kk0+32] = p1.y;
            Kn[(dq0*4+2)*65 + kk0+32] = p1.z; Kn[(dq0*4+3)*65 + kk0+32] = p1.w;
        }
        __syncthreads();
    }

    {
        int warp = tid >> 5, lane = tid & 31;
#pragma unroll
        for (int rr = 0; rr < 4; rr++) {
            int row = warp * 4 + rr;
            float* Sr = S + (size_t)row * 1024;
            float m = -1e30f;
#pragma unroll
            for (int i = 0; i < 32; i++) m = fmaxf(m, Sr[lane + 32*i]);
#pragma unroll
            for (int o = 16; o > 0; o >>= 1)
                m = fmaxf(m, __shfl_xor_sync(0xffffffffu, m, o));
            float s = 0.f;
#pragma unroll
            for (int i = 0; i < 32; i++) {
                float e = __expf(Sr[lane + 32*i] - m);
                Sr[lane + 32*i] = e;
                s += e;
            }
#pragma unroll
            for (int o = 16; o > 0; o >>= 1)
                s += __shfl_xor_sync(0xffffffffu, s, o);
            if (lane == 0) inv[row] = 1.f / s;
        }
    }
    __syncthreads();

    {
        float a0 = 0.f, a1 = 0.f, a2 = 0.f, a3 = 0.f;
#pragma unroll
        for (int q = 0; q < 32; q++) {
            float iv = inv[q];
            const float* Sq = S + (size_t)q * 1024;
            a0 += Sq[tid      ] * iv;
            a1 += Sq[tid + 256] * iv;
            a2 += Sq[tid + 512] * iv;
            a3 += Sq[tid + 768] * iv;
        }
        float* gb = g + b * N1_;
        atomicAdd(&gb[tid      ], a0);
        atomicAdd(&gb[tid + 256], a1);
        atomicAdd(&gb[tid + 512], a2);
        atomicAdd(&gb[tid + 768], a3);
    }

    float* Vs = KV;
    int khalf = (tx >> 3) * 512;
    int dgrp  = (tx & 7) * 4;
    float av[2][4];
#pragma unroll
    for (int i = 0; i < 2; i++)
#pragma unroll
        for (int j = 0; j < 4; j++) av[i][j] = 0.f;

    for (int r = 0; r < 8; r++) {
        __syncthreads();
#pragma unroll
        for (int l = 0; l < 4; l++) {
            int idx = tid + l * 256;
            int vr = idx >> 3, dq = idx & 7;
            int key = (vr < 64) ? (r*64 + vr) : (512 + r*64 + (vr - 64));
            float4 v = *(const float4*)(Vg + (size_t)key * 256 + dq * 4);
            Vs[vr*33 + dq*4+0] = v.x; Vs[vr*33 + dq*4+1] = v.y;
            Vs[vr*33 + dq*4+2] = v.z; Vs[vr*33 + dq*4+3] = v.w;
        }
        __syncthreads();
        int vbase = (tx >> 3) * 64;
#pragma unroll 4
        for (int kk = 0; kk < 64; kk++) {
            int kabs = khalf + r*64 + kk;
            float e0 = S[(size_t)(ty*2+0)*1024 + kabs];
            float e1 = S[(size_t)(ty*2+1)*1024 + kabs];
            const float* vrow = Vs + (vbase + kk)*33 + dgrp;
            float v0 = vrow[0], v1 = vrow[1], v2 = vrow[2], v3 = vrow[3];
            av[0][0] += e0*v0; av[0][1] += e0*v1; av[0][2] += e0*v2; av[0][3] += e0*v3;
            av[1][0] += e1*v0; av[1][1] += e1*v1; av[1][2] += e1*v2; av[1][3] += e1*v3;
        }
    }
#pragma unroll
    for (int i = 0; i < 2; i++)
#pragma unroll
        for (int j = 0; j < 4; j++)
            av[i][j] += __shfl_xor_sync(0xffffffffu, av[i][j], 8);

    if ((tid & 8) == 0) {
#pragma unroll
        for (int i = 0; i < 2; i++) {
            int q = ty*2 + i;
            float iv = inv[q];
            float4 o = make_float4(av[i][0]*iv, av[i][1]*iv, av[i][2]*iv, av[i][3]*iv);
            *(float4*)&cat[(size_t)(b*NTOK + q0 + q)*256 + h*32 + dgrp] = o;
        }
    }
}

// ---------------------------------------------------------------------------
__global__ void attn2_kernel(const float* __restrict__ q2,
                             const float* __restrict__ kv2)
{
    int win = blockIdx.x;
    int b = win >> 8, rem = win & 255, gy = rem >> 4, gx = rem & 15;
    int tid = threadIdx.x, h = tid >> 5, lane = tid & 31;

    __shared__ float Qs[4][16][32];
    __shared__ float Ks[4][16][32];
    __shared__ float Vs[4][16][32];
    __shared__ float csum[16];

    for (int i = lane; i < 16 * 32; i += 32) {
        int t = i >> 5, dd = i & 31;
        int n = (gy * 4 + (t >> 2)) * W_ + gx * 4 + (t & 3);
        Qs[h][t][dd] = q2 [(size_t)(b * NTOK + n) * 128 + h * 32 + dd];
        Ks[h][t][dd] = kv2[(size_t)(b * NTOK + n) * 256 + h * 32 + dd];
        Vs[h][t][dd] = kv2[(size_t)(b * NTOK + n) * 256 + 128 + h * 32 + dd];
    }
    if (tid < 16) csum[tid] = 0.f;
    __syncthreads();

    if (lane < 16) {
        int q = lane;
        float s[16];
        float mx = -1e30f;
#pragma unroll
        for (int m = 0; m < 16; m++) {
            float dot = 0.f;
#pragma unroll
            for (int dd = 0; dd < 32; dd++) dot += Qs[h][q][dd] * Ks[h][m][dd];
            s[m] = dot * ATT_SCALE;
            mx = fmaxf(mx, s[m]);
        }
        float sum = 0.f;
#pragma unroll
        for (int m = 0; m < 16; m++) { s[m] = __expf(s[m] - mx); sum += s[m]; }
        float iv = 1.f / sum;
#pragma unroll
        for (int m = 0; m < 16; m++) {
            s[m] *= iv;
            atomicAdd(&csum[m], s[m]);
        }
        int nq = (gy * 4 + (q >> 2)) * W_ + gx * 4 + (q & 3);
        float* outp = d_cat + (size_t)(b * NTOK + nq) * 256 + 128 + h * 32;
#pragma unroll
        for (int dd = 0; dd < 32; dd++) {
            float o = 0.f;
#pragma unroll
            for (int m = 0; m < 16; m++) o += s[m] * Vs[h][m][dd];
            outp[dd] = o;
        }
    }
    __syncthreads();
    if (tid < 16) {
        int m = tid;
        int np = (gy * 4 + (m >> 2)) * W_ + gx * 4 + (m & 3);
        d_lm[b * NTOK + np] = csum[m] * (1.f / 64.f);
    }
}

// ---------------------------------------------------------------------------
__global__ void lepe_add_kernel(const float* __restrict__ w9,
                                const float* __restrict__ cb)
{
    int r = blockIdx.x;
    int c = threadIdx.x;
    int b = r >> 12, n = r & 4095, y = n >> 6, x = n & 63;
    float wv[9];
#pragma unroll
    for (int t = 0; t < 9; t++) wv[t] = w9[c * 9 + t];
    float acc = cb[c];
#pragma unroll
    for (int dy = 0; dy < 3; dy++) {
        int yy = y + dy - 1;
        if (yy < 0 || yy >= H_) continue;
#pragma unroll
        for (int dx = 0; dx < 3; dx++) {
            int xx = x + dx - 1;
            if (xx < 0 || xx >= W_) continue;
            acc += wv[dy * 3 + dx] *
                   d_lepe[(size_t)(b * NTOK + yy * W_ + xx) * C_ + c];
        }
    }
    d_cat[(size_t)r * C_ + c] += acc;
}

// ---------------------------------------------------------------------------
__global__ void mask_kernel(float* __restrict__ out)
{
    int idx = blockIdx.x * 256 + threadIdx.x;
    int b = idx >> 12, pos = idx & 4095, y = pos >> 6, x = pos & 63;
    float gv = d_g[b * N1_ + (y >> 1) * 32 + (x >> 1)] * (1.f / (NH2 * NTOK));
    float val = d_lm[idx] + gv;
    out[OUT_M1 + idx] = val;
    out[OUT_M2 + b * NTOK + x * 64 + y] = val;
}

// ---------------------------------------------------------------------------
extern "C" void kernel_launch(void* const* d_in, const int* in_sizes, int n_in,
                              void* d_out, int out_size)
{
    const float* x      = (const float*)d_in[0];
    const float* q1_w   = (const float*)d_in[1];
    const float* q1_b   = (const float*)d_in[2];
    const float* kv1_w  = (const float*)d_in[3];
    const float* kv1_b  = (const float*)d_in[4];
    const float* q2_w   = (const float*)d_in[5];
    const float* q2_b   = (const float*)d_in[6];
    const float* kv2_w  = (const float*)d_in[7];
    const float* kv2_b  = (const float*)d_in[8];
    const float* lepe_w = (const float*)d_in[9];
    const float* lepe_b = (const float*)d_in[10];
    const float* lcw    = (const float*)d_in[11];
    const float* lcb    = (const float*)d_in[12];
    const float* sr_w   = (const float*)d_in[13];
    const float* sr_b   = (const float*)d_in[14];
    const float* nw     = (const float*)d_in[15];
    const float* nb     = (const float*)d_in[16];
    const float* pw     = (const float*)d_in[17];
    const float* pb     = (const float*)d_in[18];
    float* out = (float*)d_out;

    void* p;
    float *q1p, *q2p, *kv2p, *lepep, *kv1p, *catp, *gp, *xsraw;
    __nv_bfloat16 *xh, *xl, *wh, *wl, *srwh, *srwl, *agh, *agl, *xsh, *xsl, *cath, *catl;
    cudaGetSymbolAddress(&p, d_q1);    q1p   = (float*)p;
    cudaGetSymbolAddress(&p, d_q2);    q2p   = (float*)p;
    cudaGetSymbolAddress(&p, d_kv2);   kv2p  = (float*)p;
    cudaGetSymbolAddress(&p, d_lepe);  lepep = (float*)p;
    cudaGetSymbolAddress(&p, d_kv1);   kv1p  = (float*)p;
    cudaGetSymbolAddress(&p, d_cat);   catp  = (float*)p;
    cudaGetSymbolAddress(&p, d_g);     gp    = (float*)p;
    cudaGetSymbolAddress(&p, d_xsraw); xsraw = (float*)p;
    cudaGetSymbolAddress(&p, d_xh);    xh    = (__nv_bfloat16*)p;
    cudaGetSymbolAddress(&p, d_xl);    xl    = (__nv_bfloat16*)p;
    cudaGetSymbolAddress(&p, d_wh);    wh    = (__nv_bfloat16*)p;
    cudaGetSymbolAddress(&p, d_wl);    wl    = (__nv_bfloat16*)p;
    cudaGetSymbolAddress(&p, d_srwh);  srwh  = (__nv_bfloat16*)p;
    cudaGetSymbolAddress(&p, d_srwl);  srwl  = (__nv_bfloat16*)p;
    cudaGetSymbolAddress(&p, d_agh);   agh   = (__nv_bfloat16*)p;
    cudaGetSymbolAddress(&p, d_agl);   agl   = (__nv_bfloat16*)p;
    cudaGetSymbolAddress(&p, d_xsh);   xsh   = (__nv_bfloat16*)p;
    cudaGetSymbolAddress(&p, d_xsl);   xsl   = (__nv_bfloat16*)p;
    cudaGetSymbolAddress(&p, d_cath);  cath  = (__nv_bfloat16*)p;
    cudaGetSymbolAddress(&p, d_catl);  catl  = (__nv_bfloat16*)p;

    const int ATTN_SMEM = (32*1024 + 32*33 + 32 + 2*2112) * 4;
    cudaFuncSetAttribute(attn1_fused,
                         cudaFuncAttributeMaxDynamicSharedMemorySize, ATTN_SMEM);

    cudaMemsetAsync(gp, 0, B_ * N1_ * sizeof(float));

    // splits / repacks
    cvt_split<<<4096, 256>>>(x, xh, xl, B_*NTOK*C_/4);
    cvt_split<<<32,  256>>>(q1_w,  wh + WOFF_Q1,   wl + WOFF_Q1,   32768/4);
    cvt_split<<<32,  256>>>(q2_w,  wh + WOFF_Q2,   wl + WOFF_Q2,   32768/4);
    cvt_split<<<64,  256>>>(kv2_w, wh + WOFF_KV2,  wl + WOFF_KV2,  65536/4);
    cvt_split<<<64,  256>>>(lepe_w,wh + WOFF_LEPE, wl + WOFF_LEPE, 65536/4);
    cvt_split<<<64,  256>>>(kv1_w, wh + WOFF_KV1,  wl + WOFF_KV1,  65536/4);
    cvt_split<<<64,  256>>>(pw,    wh + WOFF_PROJ, wl + WOFF_PROJ, 65536/4);
    repack_srw_bf<<<1024, 256>>>(sr_w);
    srgather<<<4096, 256>>>();

    // projections from x (bf16 split mma)
    gemm_mma<<<dim3(2, 128), 256>>>(xh, xl, 256, wh+WOFF_Q1, wl+WOFF_Q1, 128,
                                    q1_b, q1p, 128, 256, 1.f);
    gemm_mma<<<dim3(2, 128), 256>>>(xh, xl, 256, wh+WOFF_Q2, wl+WOFF_Q2, 128,
                                    q2_b, q2p, 128, 256, 1.f);
    gemm_mma<<<dim3(4, 128), 256>>>(xh, xl, 256, wh+WOFF_KV2, wl+WOFF_KV2, 256,
                                    kv2_b, kv2p, 256, 256, 1.f);
    gemm_mma<<<dim3(4, 128), 256>>>(xh, xl, 256, wh+WOFF_LEPE, wl+WOFF_LEPE, 256,
                                    lepe_b, lepep, 256, 256, 1.f);

    // sr conv (gathered GEMM) -> LN+GELU(split) -> kv1
    gemm_mma<<<dim3(4, 32), 256>>>(agh, agl, 1024, srwh, srwl, 256,
                                   sr_b, xsraw, 256, 1024, 1.f);
    ln_gelu_kernel<<<B_ * N1_, 256>>>(nw, nb);
    gemm_mma<<<dim3(4, 32), 256>>>(xsh, xsl, 256, wh+WOFF_KV1, wl+WOFF_KV1, 256,
                                   kv1_b, kv1p, 256, 256, 1.f);

    // fused branch-1 attention (fp32)
    attn1_fused<<<dim3(128, 16), 256, ATTN_SMEM>>>(q1p, kv1p, catp, gp);

    // branch 2 windowed attention
    attn2_kernel<<<B_ * 16 * 16, 128>>>(q2p, kv2p);

    // lepe depthwise conv + add
    lepe_add_kernel<<<B_ * NTOK, 256>>>(lcw, lcb);

    // split cat, then final projection: out = 2*(cat @ proj_w + proj_b)
    cvt_split<<<4096, 256>>>(catp, cath, catl, B_*NTOK*C_/4);
    gemm_mma<<<dim3(4, 128), 256>>>(cath, catl, 256, wh+WOFF_PROJ, wl+WOFF_PROJ, 256,
                                    pb, out, 256, 256, 2.f);

    // masks
    mask_kernel<<<64, 256>>>(out);
}

// round 5
// speedup vs baseline: 3.6704x; 1.2190x over previous
#include <cuda_runtime.h>
#include <cuda_bf16.h>
#include <math.h>
#include <stdint.h>

#define B_    4
#define NTOK  4096
#define C_    256
#define H_    64
#define W_    64
#define NH2   4
#define N1_   1024

#define OUT_MAIN (B_*NTOK*C_)
#define OUT_M1   (OUT_MAIN)
#define OUT_M2   (OUT_MAIN + B_*NTOK)

// fp32 intermediates
static __device__ float d_proj[B_*NTOK*768];   // [q1(128)|q2(128)|kv2(256)|lepe(256)]
static __device__ float d_xsraw[B_*N1_*C_];
static __device__ float d_kv1[B_*N1_*C_];
static __device__ float d_cat[B_*NTOK*C_];
static __device__ float d_g[B_*N1_];
static __device__ float d_lm[B_*NTOK];
static __device__ float d_bcat[768];

// bf16 split buffers
static __device__ __nv_bfloat16 d_xh[B_*NTOK*C_],   d_xl[B_*NTOK*C_];
static __device__ __nv_bfloat16 d_wcath[256*768],   d_wcatl[256*768];
static __device__ __nv_bfloat16 d_w2h[131072],      d_w2l[131072];   // kv1 | proj
static __device__ __nv_bfloat16 d_srwh[1024*C_],    d_srwl[1024*C_];
static __device__ __nv_bfloat16 d_agh[4096*1024],   d_agl[4096*1024];
static __device__ __nv_bfloat16 d_xsh[B_*N1_*C_],   d_xsl[B_*N1_*C_];
static __device__ __nv_bfloat16 d_cath[B_*NTOK*C_], d_catl[B_*NTOK*C_];

__device__ __constant__ float ATT_SCALE = 0.17677669529663687f; // 1/sqrt(32)

#define MMA_BF16(c, a, b) \
  asm volatile("mma.sync.aligned.m16n8k16.row.col.f32.bf16.bf16.f32 " \
    "{%0,%1,%2,%3}, {%4,%5,%6,%7}, {%8,%9}, {%0,%1,%2,%3};" \
    : "+f"((c)[0]), "+f"((c)[1]), "+f"((c)[2]), "+f"((c)[3]) \
    : "r"((a)[0]), "r"((a)[1]), "r"((a)[2]), "r"((a)[3]), \
      "r"((b)[0]), "r"((b)[1]))

// ---------------------------------------------------------------------------
// bf16-split GEMM: C[M,N] = alpha*((Ah+Al)@(Bh+Bl) + bias); BM=128 BN=64 BK=32
// ---------------------------------------------------------------------------
__global__ void __launch_bounds__(256) gemm_mma(
    const __nv_bfloat16* __restrict__ Ah, const __nv_bfloat16* __restrict__ Al, int lda,
    const __nv_bfloat16* __restrict__ Bh, const __nv_bfloat16* __restrict__ Bl, int ldb,
    const float* __restrict__ bias, float* __restrict__ Cm, int ldc,
    int K, float alpha)
{
    __shared__ uint16_t sAh[128*40], sAl[128*40];
    __shared__ uint16_t sBh[64*40],  sBl[64*40];
    int tid = threadIdx.x, lane = tid & 31, warp = tid >> 5;
    int wm = warp >> 1, wn = warp & 1;
    int m0 = blockIdx.y * 128, n0 = blockIdx.x * 64;
    int g = lane >> 2, t = lane & 3;

    float acc[2][4][4];
#pragma unroll
    for (int i = 0; i < 2; i++)
#pragma unroll
        for (int j = 0; j < 4; j++)
#pragma unroll
            for (int c = 0; c < 4; c++) acc[i][j][c] = 0.f;

    for (int k0 = 0; k0 < K; k0 += 32) {
#pragma unroll
        for (int s = 0; s < 4; s++) {
            int v = tid + s * 256;
            int row = v >> 3, ko = (v & 7) * 4;
            size_t off = (size_t)(m0 + row) * lda + k0 + ko;
            *(uint2*)&sAh[row*40 + ko] = *(const uint2*)(const void*)(Ah + off);
            *(uint2*)&sAl[row*40 + ko] = *(const uint2*)(const void*)(Al + off);
        }
#pragma unroll
        for (int s = 0; s < 2; s++) {
            int v = tid + s * 256;
            int kr = v >> 4, no = (v & 15) * 4;
            size_t off = (size_t)(k0 + kr) * ldb + n0 + no;
            uint2 hv = *(const uint2*)(const void*)(Bh + off);
            uint2 lv = *(const uint2*)(const void*)(Bl + off);
            const uint16_t* hp = (const uint16_t*)&hv;
            const uint16_t* lp = (const uint16_t*)&lv;
#pragma unroll
            for (int j = 0; j < 4; j++) {
                sBh[(no + j)*40 + kr] = hp[j];
                sBl[(no + j)*40 + kr] = lp[j];
            }
        }
        __syncthreads();

#pragma unroll
        for (int kk = 0; kk < 32; kk += 16) {
            uint32_t ahr[2][4], alr[2][4], bhr[4][2], blr[4][2];
#pragma unroll
            for (int i = 0; i < 2; i++) {
                int r0 = wm*32 + i*16 + g;
                ahr[i][0] = *(const uint32_t*)&sAh[r0*40     + kk + t*2];
                ahr[i][1] = *(const uint32_t*)&sAh[(r0+8)*40 + kk + t*2];
                ahr[i][2] = *(const uint32_t*)&sAh[r0*40     + kk + 8 + t*2];
                ahr[i][3] = *(const uint32_t*)&sAh[(r0+8)*40 + kk + 8 + t*2];
                alr[i][0] = *(const uint32_t*)&sAl[r0*40     + kk + t*2];
                alr[i][1] = *(const uint32_t*)&sAl[(r0+8)*40 + kk + t*2];
                alr[i][2] = *(const uint32_t*)&sAl[r0*40     + kk + 8 + t*2];
                alr[i][3] = *(const uint32_t*)&sAl[(r0+8)*40 + kk + 8 + t*2];
            }
#pragma unroll
            for (int j = 0; j < 4; j++) {
                int nn = wn*32 + j*8 + g;
                bhr[j][0] = *(const uint32_t*)&sBh[nn*40 + kk + t*2];
                bhr[j][1] = *(const uint32_t*)&sBh[nn*40 + kk + 8 + t*2];
                blr[j][0] = *(const uint32_t*)&sBl[nn*40 + kk + t*2];
                blr[j][1] = *(const uint32_t*)&sBl[nn*40 + kk + 8 + t*2];
            }
#pragma unroll
            for (int i = 0; i < 2; i++)
#pragma unroll
                for (int j = 0; j < 4; j++) {
                    MMA_BF16(acc[i][j], ahr[i], bhr[j]);
                    MMA_BF16(acc[i][j], alr[i], bhr[j]);
                    MMA_BF16(acc[i][j], ahr[i], blr[j]);
                }
        }
        __syncthreads();
    }

#pragma unroll
    for (int i = 0; i < 2; i++)
#pragma unroll
        for (int j = 0; j < 4; j++) {
            int row0 = m0 + wm*32 + i*16 + g;
            int col  = n0 + wn*32 + j*8 + t*2;
            float b0 = bias[col], b1 = bias[col+1];
            float2 o0 = make_float2(alpha*(acc[i][j][0]+b0), alpha*(acc[i][j][1]+b1));
            float2 o1 = make_float2(alpha*(acc[i][j][2]+b0), alpha*(acc[i][j][3]+b1));
            *(float2*)(Cm + (size_t)row0    *ldc + col) = o0;
            *(float2*)(Cm + (size_t)(row0+8)*ldc + col) = o1;
        }
}

// ---------------------------------------------------------------------------
__global__ void cvt_split(const float* __restrict__ in,
                          __nv_bfloat16* __restrict__ h,
                          __nv_bfloat16* __restrict__ l, int n4)
{
    int i = blockIdx.x * 256 + threadIdx.x;
    if (i >= n4) return;
    float4 v = ((const float4*)in)[i];
    __nv_bfloat16 h0 = __float2bfloat16(v.x), h1 = __float2bfloat16(v.y);
    __nv_bfloat16 h2 = __float2bfloat16(v.z), h3 = __float2bfloat16(v.w);
    __nv_bfloat16 l0 = __float2bfloat16(v.x - __bfloat162float(h0));
    __nv_bfloat16 l1 = __float2bfloat16(v.y - __bfloat162float(h1));
    __nv_bfloat16 l2 = __float2bfloat16(v.z - __bfloat162float(h2));
    __nv_bfloat16 l3 = __float2bfloat16(v.w - __bfloat162float(h3));
    ((__nv_bfloat162*)h)[i*2]   = __nv_bfloat162(h0, h1);
    ((__nv_bfloat162*)h)[i*2+1] = __nv_bfloat162(h2, h3);
    ((__nv_bfloat162*)l)[i*2]   = __nv_bfloat162(l0, l1);
    ((__nv_bfloat162*)l)[i*2+1] = __nv_bfloat162(l2, l3);
}

// ---------------------------------------------------------------------------
// Pack concatenated x-projection weights [256][768] + bias [768], bf16 split.
// ---------------------------------------------------------------------------
__global__ void pack_wcat(const float* __restrict__ q1w, const float* __restrict__ q2w,
                          const float* __restrict__ kv2w, const float* __restrict__ lepw,
                          const float* __restrict__ q1b, const float* __restrict__ q2b,
                          const float* __restrict__ kv2b, const float* __restrict__ lepb)
{
    int idx = blockIdx.x * 256 + threadIdx.x;   // 196608
    int k = idx / 768, col = idx - k * 768;
    float v;
    if (col < 128)       v = q1w[k*128 + col];
    else if (col < 256)  v = q2w[k*128 + col - 128];
    else if (col < 512)  v = kv2w[k*256 + col - 256];
    else                 v = lepw[k*256 + col - 512];
    __nv_bfloat16 h = __float2bfloat16(v);
    d_wcath[idx] = h;
    d_wcatl[idx] = __float2bfloat16(v - __bfloat162float(h));
    if (idx < 768) {
        float b = (idx < 128) ? q1b[idx] : (idx < 256) ? q2b[idx-128]
                : (idx < 512) ? kv2b[idx-256] : lepb[idx-512];
        d_bcat[idx] = b;
    }
}

// ---------------------------------------------------------------------------
// Split kv1_w + proj_w, and repack+split sr_w. One kernel, grid 1536.
// ---------------------------------------------------------------------------
__global__ void prep_w2(const float* __restrict__ kv1w,
                        const float* __restrict__ projw,
                        const float* __restrict__ srw)
{
    int idx = blockIdx.x * 256 + threadIdx.x;
    float v;
    if (idx < 65536) {
        v = kv1w[idx];
        __nv_bfloat16 h = __float2bfloat16(v);
        d_w2h[idx] = h; d_w2l[idx] = __float2bfloat16(v - __bfloat162float(h));
    } else if (idx < 131072) {
        v = projw[idx - 65536];
        __nv_bfloat16 h = __float2bfloat16(v);
        d_w2h[idx] = h; d_w2l[idx] = __float2bfloat16(v - __bfloat162float(h));
    } else {
        int i = idx - 131072;          // 262144
        int co = i & 255, kk = i >> 8;
        int dd = kk >> 8, ci = kk & 255;
        v = srw[co * 1024 + ci * 4 + dd];
        __nv_bfloat16 h = __float2bfloat16(v);
        d_srwh[i] = h; d_srwl[i] = __float2bfloat16(v - __bfloat162float(h));
    }
}

// ---------------------------------------------------------------------------
__global__ void srgather()
{
    int v = blockIdx.x * 256 + threadIdx.x;
    int r = v >> 8, col4 = v & 255;
    int k = col4 * 4;
    int dd = k >> 8, ci = k & 255;
    int b = r >> 10, p = r & 1023;
    int ii = p >> 5, jj = p & 31;
    int di = dd >> 1, dj = dd & 1;
    int n = (2*ii + di) * W_ + 2*jj + dj;
    size_t src = ((size_t)(b * NTOK + n) * C_ + ci) >> 2;
    size_t dst = ((size_t)r * 1024 + k) >> 2;
    ((uint2*)(void*)d_agh)[dst] = ((const uint2*)(const void*)d_xh)[src];
    ((uint2*)(void*)d_agl)[dst] = ((const uint2*)(const void*)d_xl)[src];
}

// ---------------------------------------------------------------------------
__global__ void ln_gelu_kernel(const float* __restrict__ nw,
                               const float* __restrict__ nb)
{
    __shared__ float sh[8];
    int r = blockIdx.x, c = threadIdx.x;
    float v = d_xsraw[(size_t)r * C_ + c];

    float s = v;
#pragma unroll
    for (int o = 16; o > 0; o >>= 1) s += __shfl_xor_sync(0xffffffffu, s, o);
    if ((c & 31) == 0) sh[c >> 5] = s;
    __syncthreads();
    if (c < 32) {
        float t = (c < 8) ? sh[c] : 0.f;
#pragma unroll
        for (int o = 4; o > 0; o >>= 1) t += __shfl_xor_sync(0xffffffffu, t, o);
        if (c == 0) sh[0] = t;
    }
    __syncthreads();
    float mean = sh[0] * (1.f / 256.f);
    __syncthreads();

    float dv = v - mean;
    float q = dv * dv;
#pragma unroll
    for (int o = 16; o > 0; o >>= 1) q += __shfl_xor_sync(0xffffffffu, q, o);
    if ((c & 31) == 0) sh[c >> 5] = q;
    __syncthreads();
    if (c < 32) {
        float t = (c < 8) ? sh[c] : 0.f;
#pragma unroll
        for (int o = 4; o > 0; o >>= 1) t += __shfl_xor_sync(0xffffffffu, t, o);
        if (c == 0) sh[0] = t;
    }
    __syncthreads();
    float var = sh[0] * (1.f / 256.f);

    float y = dv * rsqrtf(var + 1e-5f) * nw[c] + nb[c];
    float ge = 0.5f * y * (1.f + erff(y * 0.70710678118654752f));
    __nv_bfloat16 h = __float2bfloat16(ge);
    d_xsh[(size_t)r * C_ + c] = h;
    d_xsl[(size_t)r * C_ + c] = __float2bfloat16(ge - __bfloat162float(h));
}

// ---------------------------------------------------------------------------
// Fused branch-1 attention; K/V smem vectorized (pads 68 / 36).
// Q from d_proj (stride 768, col offset 0), K/V from d_kv1 (stride 256).
// ---------------------------------------------------------------------------
__global__ void __launch_bounds__(256) attn1_fused(
    const float* __restrict__ proj, const float* __restrict__ kv1,
    float* __restrict__ cat, float* __restrict__ g)
{
    extern __shared__ float sm[];
    float* S   = sm;                    // 32*1024
    float* Qs  = sm + 32*1024;          // 32*33
    float* inv = Qs + 32*33;            // 32
    float* KV  = inv + 32;              // 4608 floats (K dbuf 2*2176 / Vs 128*36)

    int tid = threadIdx.x, tx = tid & 15, ty = tid >> 4;
    int bh = blockIdx.y; int b = bh >> 2, h = bh & 3;
    int q0 = blockIdx.x * 32;

    const float* Qg = proj + (size_t)(b * NTOK + q0) * 768 + h * 32;
    const float* Kg = kv1 + (size_t)b * N1_ * 256 + h * 32;
    const float* Vg = Kg + 128;

    {
        int qq = tid >> 3, dq = tid & 7;
        float4 v = *(const float4*)(Qg + (size_t)qq * 768 + dq * 4);
        Qs[qq*33 + dq*4+0] = v.x; Qs[qq*33 + dq*4+1] = v.y;
        Qs[qq*33 + dq*4+2] = v.z; Qs[qq*33 + dq*4+3] = v.w;
    }
    {
        int kk = tid >> 3, dq = tid & 7;
        float4 v0 = *(const float4*)(Kg + (size_t)kk * 256 + dq * 4);
        float4 v1 = *(const float4*)(Kg + (size_t)(kk+32) * 256 + dq * 4);
        float* Kb = KV;
        Kb[(dq*4+0)*68 + kk] = v0.x; Kb[(dq*4+1)*68 + kk] = v0.y;
        Kb[(dq*4+2)*68 + kk] = v0.z; Kb[(dq*4+3)*68 + kk] = v0.w;
        Kb[(dq*4+0)*68 + kk+32] = v1.x; Kb[(dq*4+1)*68 + kk+32] = v1.y;
        Kb[(dq*4+2)*68 + kk+32] = v1.z; Kb[(dq*4+3)*68 + kk+32] = v1.w;
    }
    __syncthreads();

    float sc = ATT_SCALE;
    float qr[2][32];
#pragma unroll
    for (int i = 0; i < 2; i++)
#pragma unroll
        for (int d = 0; d < 32; d++)
            qr[i][d] = Qs[(ty*2+i)*33 + d] * sc;

    int kk0 = tid >> 3, dq0 = tid & 7;
    for (int t = 0; t < 16; t++) {
        float4 p0, p1;
        bool pf = (t < 15);
        if (pf) {
            const float* src = Kg + (size_t)((t+1)*64) * 256;
            p0 = *(const float4*)(src + (size_t)kk0 * 256 + dq0 * 4);
            p1 = *(const float4*)(src + (size_t)(kk0+32) * 256 + dq0 * 4);
        }
        const float* Kb = KV + (t & 1) * 2176;
        float acc[2][4];
#pragma unroll
        for (int i = 0; i < 2; i++)
#pragma unroll
            for (int j = 0; j < 4; j++) acc[i][j] = 0.f;
#pragma unroll
        for (int d = 0; d < 32; d++) {
            float4 bv = *(const float4*)&Kb[d*68 + tx*4];
#pragma unroll
            for (int i = 0; i < 2; i++) {
                float a = qr[i][d];
                acc[i][0] += a*bv.x; acc[i][1] += a*bv.y;
                acc[i][2] += a*bv.z; acc[i][3] += a*bv.w;
            }
        }
#pragma unroll
        for (int i = 0; i < 2; i++)
            *(float4*)&S[(size_t)(ty*2+i)*1024 + t*64 + tx*4] =
                make_float4(acc[i][0], acc[i][1], acc[i][2], acc[i][3]);
        if (pf) {
            float* Kn = KV + ((t+1) & 1) * 2176;
            Kn[(dq0*4+0)*68 + kk0] = p0.x; Kn[(dq0*4+1)*68 + kk0] = p0.y;
            Kn[(dq0*4+2)*68 + kk0] = p0.z; Kn[(dq0*4+3)*68 + kk0] = p0.w;
            Kn[(dq0*4+0)*68 + kk0+32] = p1.x; Kn[(dq0*4+1)*68 + kk0+32] = p1.y;
            Kn[(dq0*4+2)*68 + kk0+32] = p1.z; Kn[(dq0*4+3)*68 + kk0+32] = p1.w;
        }
        __syncthreads();
    }

    {
        int warp = tid >> 5, lane = tid & 31;
#pragma unroll
        for (int rr = 0; rr < 4; rr++) {
            int row = warp * 4 + rr;
            float* Sr = S + (size_t)row * 1024;
            float m = -1e30f;
#pragma unroll
            for (int i = 0; i < 32; i++) m = fmaxf(m, Sr[lane + 32*i]);
#pragma unroll
            for (int o = 16; o > 0; o >>= 1)
                m = fmaxf(m, __shfl_xor_sync(0xffffffffu, m, o));
            float s = 0.f;
#pragma unroll
            for (int i = 0; i < 32; i++) {
                float e = __expf(Sr[lane + 32*i] - m);
                Sr[lane + 32*i] = e;
                s += e;
            }
#pragma unroll
            for (int o = 16; o > 0; o >>= 1)
                s += __shfl_xor_sync(0xffffffffu, s, o);
            if (lane == 0) inv[row] = 1.f / s;
        }
    }
    __syncthreads();

    {
        float a0 = 0.f, a1 = 0.f, a2 = 0.f, a3 = 0.f;
#pragma unroll
        for (int q = 0; q < 32; q++) {
            float iv = inv[q];
            const float* Sq = S + (size_t)q * 1024;
            a0 += Sq[tid      ] * iv;
            a1 += Sq[tid + 256] * iv;
            a2 += Sq[tid + 512] * iv;
            a3 += Sq[tid + 768] * iv;
        }
        float* gb = g + b * N1_;
        atomicAdd(&gb[tid      ], a0);
        atomicAdd(&gb[tid + 256], a1);
        atomicAdd(&gb[tid + 512], a2);
        atomicAdd(&gb[tid + 768], a3);
    }

    float* Vs = KV;                       // [128 keys][36]
    int khalf = (tx >> 3) * 512;
    int dgrp  = (tx & 7) * 4;
    float av[2][4];
#pragma unroll
    for (int i = 0; i < 2; i++)
#pragma unroll
        for (int j = 0; j < 4; j++) av[i][j] = 0.f;

    for (int r = 0; r < 8; r++) {
        __syncthreads();
#pragma unroll
        for (int l = 0; l < 4; l++) {
            int idx = tid + l * 256;
            int vr = idx >> 3, dq = idx & 7;
            int key = (vr < 64) ? (r*64 + vr) : (512 + r*64 + (vr - 64));
            float4 v = *(const float4*)(Vg + (size_t)key * 256 + dq * 4);
            *(float4*)&Vs[vr*36 + dq*4] = v;
        }
        __syncthreads();
        int vbase = (tx >> 3) * 64;
#pragma unroll 4
        for (int kk = 0; kk < 64; kk++) {
            int kabs = khalf + r*64 + kk;
            float e0 = S[(size_t)(ty*2+0)*1024 + kabs];
            float e1 = S[(size_t)(ty*2+1)*1024 + kabs];
            float4 vv = *(const float4*)&Vs[(vbase + kk)*36 + dgrp];
            av[0][0] += e0*vv.x; av[0][1] += e0*vv.y; av[0][2] += e0*vv.z; av[0][3] += e0*vv.w;
            av[1][0] += e1*vv.x; av[1][1] += e1*vv.y; av[1][2] += e1*vv.z; av[1][3] += e1*vv.w;
        }
    }
#pragma unroll
    for (int i = 0; i < 2; i++)
#pragma unroll
        for (int j = 0; j < 4; j++)
            av[i][j] += __shfl_xor_sync(0xffffffffu, av[i][j], 8);

    if ((tid & 8) == 0) {
#pragma unroll
        for (int i = 0; i < 2; i++) {
            int q = ty*2 + i;
            float iv = inv[q];
            float4 o = make_float4(av[i][0]*iv, av[i][1]*iv, av[i][2]*iv, av[i][3]*iv);
            *(float4*)&cat[(size_t)(b*NTOK + q0 + q)*256 + h*32 + dgrp] = o;
        }
    }
}

// ---------------------------------------------------------------------------
// Windowed attention (branch 2); reads q2/kv2 slices from d_proj.
// ---------------------------------------------------------------------------
__global__ void attn2_kernel(const float* __restrict__ proj)
{
    int win = blockIdx.x;
    int b = win >> 8, rem = win & 255, gy = rem >> 4, gx = rem & 15;
    int tid = threadIdx.x, h = tid >> 5, lane = tid & 31;

    __shared__ float Qs[4][16][32];
    __shared__ float Ks[4][16][32];
    __shared__ float Vs[4][16][32];
    __shared__ float csum[16];

    for (int i = lane; i < 16 * 32; i += 32) {
        int t = i >> 5, dd = i & 31;
        int n = (gy * 4 + (t >> 2)) * W_ + gx * 4 + (t & 3);
        const float* base = proj + (size_t)(b * NTOK + n) * 768;
        Qs[h][t][dd] = base[128 + h * 32 + dd];
        Ks[h][t][dd] = base[256 + h * 32 + dd];
        Vs[h][t][dd] = base[256 + 128 + h * 32 + dd];
    }
    if (tid < 16) csum[tid] = 0.f;
    __syncthreads();

    if (lane < 16) {
        int q = lane;
        float s[16];
        float mx = -1e30f;
#pragma unroll
        for (int m = 0; m < 16; m++) {
            float dot = 0.f;
#pragma unroll
            for (int dd = 0; dd < 32; dd++) dot += Qs[h][q][dd] * Ks[h][m][dd];
            s[m] = dot * ATT_SCALE;
            mx = fmaxf(mx, s[m]);
        }
        float sum = 0.f;
#pragma unroll
        for (int m = 0; m < 16; m++) { s[m] = __expf(s[m] - mx); sum += s[m]; }
        float iv = 1.f / sum;
#pragma unroll
        for (int m = 0; m < 16; m++) {
            s[m] *= iv;
            atomicAdd(&csum[m], s[m]);
        }
        int nq = (gy * 4 + (q >> 2)) * W_ + gx * 4 + (q & 3);
        float* outp = d_cat + (size_t)(b * NTOK + nq) * 256 + 128 + h * 32;
#pragma unroll
        for (int dd = 0; dd < 32; dd++) {
            float o = 0.f;
#pragma unroll
            for (int m = 0; m < 16; m++) o += s[m] * Vs[h][m][dd];
            outp[dd] = o;
        }
    }
    __syncthreads();
    if (tid < 16) {
        int m = tid;
        int np = (gy * 4 + (m >> 2)) * W_ + gx * 4 + (m & 3);
        d_lm[b * NTOK + np] = csum[m] * (1.f / 64.f);
    }
}

// ---------------------------------------------------------------------------
// LePE depthwise conv (reads proj cols 512-767) + cat add -> bf16 split out.
// ---------------------------------------------------------------------------
__global__ void lepe_add_kernel(const float* __restrict__ proj,
                                const float* __restrict__ w9,
                                const float* __restrict__ cb)
{
    int r = blockIdx.x;
    int c = threadIdx.x;
    int b = r >> 12, n = r & 4095, y = n >> 6, x = n & 63;
    float wv[9];
#pragma unroll
    for (int t = 0; t < 9; t++) wv[t] = w9[c * 9 + t];
    float acc = cb[c];
#pragma unroll
    for (int dy = 0; dy < 3; dy++) {
        int yy = y + dy - 1;
        if (yy < 0 || yy >= H_) continue;
#pragma unroll
        for (int dx = 0; dx < 3; dx++) {
            int xx = x + dx - 1;
            if (xx < 0 || xx >= W_) continue;
            acc += wv[dy * 3 + dx] *
                   proj[(size_t)(b * NTOK + yy * W_ + xx) * 768 + 512 + c];
        }
    }
    float v = d_cat[(size_t)r * C_ + c] + acc;
    __nv_bfloat16 h = __float2bfloat16(v);
    d_cath[(size_t)r * C_ + c] = h;
    d_catl[(size_t)r * C_ + c] = __float2bfloat16(v - __bfloat162float(h));
}

// ---------------------------------------------------------------------------
__global__ void mask_kernel(float* __restrict__ out)
{
    int idx = blockIdx.x * 256 + threadIdx.x;
    int b = idx >> 12, pos = idx & 4095, y = pos >> 6, x = pos & 63;
    float gv = d_g[b * N1_ + (y >> 1) * 32 + (x >> 1)] * (1.f / (NH2 * NTOK));
    float val = d_lm[idx] + gv;
    out[OUT_M1 + idx] = val;
    out[OUT_M2 + b * NTOK + x * 64 + y] = val;
}

// ---------------------------------------------------------------------------
extern "C" void kernel_launch(void* const* d_in, const int* in_sizes, int n_in,
                              void* d_out, int out_size)
{
    const float* x      = (const float*)d_in[0];
    const float* q1_w   = (const float*)d_in[1];
    const float* q1_b   = (const float*)d_in[2];
    const float* kv1_w  = (const float*)d_in[3];
    const float* kv1_b  = (const float*)d_in[4];
    const float* q2_w   = (const float*)d_in[5];
    const float* q2_b   = (const float*)d_in[6];
    const float* kv2_w  = (const float*)d_in[7];
    const float* kv2_b  = (const float*)d_in[8];
    const float* lepe_w = (const float*)d_in[9];
    const float* lepe_b = (const float*)d_in[10];
    const float* lcw    = (const float*)d_in[11];
    const float* lcb    = (const float*)d_in[12];
    const float* sr_w   = (const float*)d_in[13];
    const float* sr_b   = (const float*)d_in[14];
    const float* nw     = (const float*)d_in[15];
    const float* nb     = (const float*)d_in[16];
    const float* pw     = (const float*)d_in[17];
    const float* pb     = (const float*)d_in[18];
    float* out = (float*)d_out;

    void* p;
    float *projp, *kv1p, *catp, *gp, *xsraw, *bcat;
    __nv_bfloat16 *xh, *xl, *wcath, *wcatl, *w2h, *w2l, *srwh, *srwl;
    __nv_bfloat16 *agh, *agl, *xsh, *xsl, *cath, *catl;
    cudaGetSymbolAddress(&p, d_proj);  projp = (float*)p;
    cudaGetSymbolAddress(&p, d_kv1);   kv1p  = (float*)p;
    cudaGetSymbolAddress(&p, d_cat);   catp  = (float*)p;
    cudaGetSymbolAddress(&p, d_g);     gp    = (float*)p;
    cudaGetSymbolAddress(&p, d_xsraw); xsraw = (float*)p;
    cudaGetSymbolAddress(&p, d_bcat);  bcat  = (float*)p;
    cudaGetSymbolAddress(&p, d_xh);    xh    = (__nv_bfloat16*)p;
    cudaGetSymbolAddress(&p, d_xl);    xl    = (__nv_bfloat16*)p;
    cudaGetSymbolAddress(&p, d_wcath); wcath = (__nv_bfloat16*)p;
    cudaGetSymbolAddress(&p, d_wcatl); wcatl = (__nv_bfloat16*)p;
    cudaGetSymbolAddress(&p, d_w2h);   w2h   = (__nv_bfloat16*)p;
    cudaGetSymbolAddress(&p, d_w2l);   w2l   = (__nv_bfloat16*)p;
    cudaGetSymbolAddress(&p, d_srwh);  srwh  = (__nv_bfloat16*)p;
    cudaGetSymbolAddress(&p, d_srwl);  srwl  = (__nv_bfloat16*)p;
    cudaGetSymbolAddress(&p, d_agh);   agh   = (__nv_bfloat16*)p;
    cudaGetSymbolAddress(&p, d_agl);   agl   = (__nv_bfloat16*)p;
    cudaGetSymbolAddress(&p, d_xsh);   xsh   = (__nv_bfloat16*)p;
    cudaGetSymbolAddress(&p, d_xsl);   xsl   = (__nv_bfloat16*)p;
    cudaGetSymbolAddress(&p, d_cath);  cath  = (__nv_bfloat16*)p;
    cudaGetSymbolAddress(&p, d_catl);  catl  = (__nv_bfloat16*)p;

    const int ATTN_SMEM = (32*1024 + 32*33 + 32 + 4608) * 4;  // 153856 B
    cudaFuncSetAttribute(attn1_fused,
                         cudaFuncAttributeMaxDynamicSharedMemorySize, ATTN_SMEM);

    // 1..5: prep (position 6 = big fused GEMM, for the ncu window)
    cudaMemsetAsync(gp, 0, B_ * N1_ * sizeof(float));
    cvt_split<<<4096, 256>>>(x, xh, xl, B_*NTOK*C_/4);
    srgather<<<4096, 256>>>();
    pack_wcat<<<768, 256>>>(q1_w, q2_w, kv2_w, lepe_w, q1_b, q2_b, kv2_b, lepe_b);
    prep_w2<<<1536, 256>>>(kv1_w, pw, sr_w);

    // 6: fused x-projections -> d_proj [tok][768]
    gemm_mma<<<dim3(12, 128), 256>>>(xh, xl, 256, wcath, wcatl, 768,
                                     bcat, projp, 768, 256, 1.f);

    // sr conv GEMM -> LN+GELU(split) -> kv1
    gemm_mma<<<dim3(4, 32), 256>>>(agh, agl, 1024, srwh, srwl, 256,
                                   sr_b, xsraw, 256, 1024, 1.f);
    ln_gelu_kernel<<<B_ * N1_, 256>>>(nw, nb);
    gemm_mma<<<dim3(4, 32), 256>>>(xsh, xsl, 256, w2h, w2l, 256,
                                   kv1_b, kv1p, 256, 256, 1.f);

    // attention branches
    attn1_fused<<<dim3(128, 16), 256, ATTN_SMEM>>>(projp, kv1p, catp, gp);
    attn2_kernel<<<B_ * 16 * 16, 128>>>(projp);

    // lepe conv + cat add -> bf16 split
    lepe_add_kernel<<<B_ * NTOK, 256>>>(projp, lcw, lcb);

    // final projection: out = 2*(cat @ proj_w + proj_b)
    gemm_mma<<<dim3(4, 128), 256>>>(cath, catl, 256, w2h + 65536, w2l + 65536, 256,
                                    pb, out, 256, 256, 2.f);

    // masks
    mask_kernel<<<64, 256>>>(out);
}

// round 8
// speedup vs baseline: 3.7752x; 1.0286x over previous
#include <cuda_runtime.h>
#include <cuda_bf16.h>
#include <math.h>
#include <stdint.h>

#define B_    4
#define NTOK  4096
#define C_    256
#define H_    64
#define W_    64
#define NH2   4
#define N1_   1024

#define OUT_MAIN (B_*NTOK*C_)
#define OUT_M1   (OUT_MAIN)
#define OUT_M2   (OUT_MAIN + B_*NTOK)

// fp32 intermediates
static __device__ float d_proj[B_*NTOK*768];   // [q1|q2|kv2|lepe]
static __device__ float d_xsraw[B_*N1_*C_];
static __device__ float d_kv1[B_*N1_*C_];
static __device__ float d_cat[B_*NTOK*C_];
static __device__ float d_g[B_*N1_];
static __device__ float d_lm[B_*NTOK];
static __device__ float d_bcat[768];

// bf16 split buffers
static __device__ __nv_bfloat16 d_xh[B_*NTOK*C_],   d_xl[B_*NTOK*C_];
static __device__ __nv_bfloat16 d_wcath[256*768],   d_wcatl[256*768];
static __device__ __nv_bfloat16 d_w2h[131072],      d_w2l[131072];   // kv1 | proj
static __device__ __nv_bfloat16 d_srwh[1024*C_],    d_srwl[1024*C_];
static __device__ __nv_bfloat16 d_agh[4096*1024],   d_agl[4096*1024];
static __device__ __nv_bfloat16 d_xsh[B_*N1_*C_],   d_xsl[B_*N1_*C_];
static __device__ __nv_bfloat16 d_cath[B_*NTOK*C_], d_catl[B_*NTOK*C_];

__device__ __constant__ float ATT_SCALE = 0.17677669529663687f; // 1/sqrt(32)

#define MMA_BF16(c, a, b) \
  asm volatile("mma.sync.aligned.m16n8k16.row.col.f32.bf16.bf16.f32 " \
    "{%0,%1,%2,%3}, {%4,%5,%6,%7}, {%8,%9}, {%0,%1,%2,%3};" \
    : "+f"((c)[0]), "+f"((c)[1]), "+f"((c)[2]), "+f"((c)[3]) \
    : "r"((a)[0]), "r"((a)[1]), "r"((a)[2]), "r"((a)[3]), \
      "r"((b)[0]), "r"((b)[1]))

__device__ __forceinline__ void cpa16(uint32_t saddr, const void* g) {
    asm volatile("cp.async.ca.shared.global [%0], [%1], 16;"
                 :: "r"(saddr), "l"(g));
}

// ---------------------------------------------------------------------------
// bf16-split GEMM with cp.async 2-stage pipeline.
// C = alpha*((Ah+Al)@(Bh+Bl) + bias); BM=128 BN=64 BK=32, 256 thr.
// ---------------------------------------------------------------------------
#define GEMM_SMEM 61440
__global__ void __launch_bounds__(256) gemm_mma(
    const __nv_bfloat16* __restrict__ Ah, const __nv_bfloat16* __restrict__ Al, int lda,
    const __nv_bfloat16* __restrict__ Bh, const __nv_bfloat16* __restrict__ Bl, int ldb,
    const float* __restrict__ bias, float* __restrict__ Cm, int ldc,
    int K, float alpha)
{
    extern __shared__ uint16_t sm16[];
    uint16_t* sAh = sm16;            // 2 x 128*40
    uint16_t* sAl = sm16 + 10240;
    uint16_t* sBh = sm16 + 20480;    // 2 x 64*40
    uint16_t* sBl = sm16 + 25600;
    uint32_t sAh_u = (uint32_t)__cvta_generic_to_shared(sAh);
    uint32_t sAl_u = (uint32_t)__cvta_generic_to_shared(sAl);

    int tid = threadIdx.x, lane = tid & 31, warp = tid >> 5;
    int wm = warp >> 1, wn = warp & 1;
    int m0 = blockIdx.y * 128, n0 = blockIdx.x * 64;
    int g = lane >> 2, t = lane & 3;

    float acc[2][4][4];
#pragma unroll
    for (int i = 0; i < 2; i++)
#pragma unroll
        for (int j = 0; j < 4; j++)
#pragma unroll
            for (int c = 0; c < 4; c++) acc[i][j][c] = 0.f;

    uint2 rbh[2], rbl[2];

    // --- prologue: A chunk 0 via cp.async, B chunk 0 into regs ---
#pragma unroll
    for (int l = 0; l < 2; l++) {
        int v = tid + (l << 8);
        int row = v >> 2, seg = v & 3;
        size_t go = (size_t)(m0 + row) * lda + seg * 8;
        uint32_t so = (uint32_t)((row * 40 + seg * 8) * 2);
        cpa16(sAh_u + so, Ah + go);
        cpa16(sAl_u + so, Al + go);
    }
    asm volatile("cp.async.commit_group;" ::: "memory");
#pragma unroll
    for (int l = 0; l < 2; l++) {
        int v = tid + (l << 8);
        int kr = v >> 4, no = (v & 15) * 4;
        size_t go = (size_t)kr * ldb + n0 + no;
        rbh[l] = *(const uint2*)(const void*)(Bh + go);
        rbl[l] = *(const uint2*)(const void*)(Bl + go);
    }

    int nch = K >> 5;
    for (int c = 0; c < nch; c++) {
        int bi = c & 1;
        // store B regs -> smem[bi]
#pragma unroll
        for (int l = 0; l < 2; l++) {
            int v = tid + (l << 8);
            int kr = v >> 4, no = (v & 15) * 4;
            const uint16_t* hp = (const uint16_t*)&rbh[l];
            const uint16_t* lp = (const uint16_t*)&rbl[l];
#pragma unroll
            for (int j = 0; j < 4; j++) {
                sBh[bi*2560 + (no + j)*40 + kr] = hp[j];
                sBl[bi*2560 + (no + j)*40 + kr] = lp[j];
            }
        }
        asm volatile("cp.async.wait_group 0;" ::: "memory");
        __syncthreads();

        if (c + 1 < nch) {
            int k1 = (c + 1) << 5;
            int bj = bi ^ 1;
#pragma unroll
            for (int l = 0; l < 2; l++) {
                int v = tid + (l << 8);
                int row = v >> 2, seg = v & 3;
                size_t go = (size_t)(m0 + row) * lda + k1 + seg * 8;
                uint32_t so = (uint32_t)((bj*5120 + row * 40 + seg * 8) * 2);
                cpa16(sAh_u + so, Ah + go);
                cpa16(sAl_u + so, Al + go);
            }
            asm volatile("cp.async.commit_group;" ::: "memory");
#pragma unroll
            for (int l = 0; l < 2; l++) {
                int v = tid + (l << 8);
                int kr = v >> 4, no = (v & 15) * 4;
                size_t go = (size_t)(k1 + kr) * ldb + n0 + no;
                rbh[l] = *(const uint2*)(const void*)(Bh + go);
                rbl[l] = *(const uint2*)(const void*)(Bl + go);
            }
        }

        // compute on buffer bi
        const uint16_t* cAh = sAh + bi*5120;
        const uint16_t* cAl = sAl + bi*5120;
        const uint16_t* cBh = sBh + bi*2560;
        const uint16_t* cBl = sBl + bi*2560;
#pragma unroll
        for (int kk = 0; kk < 32; kk += 16) {
            uint32_t ahr[2][4], alr[2][4], bhr[4][2], blr[4][2];
#pragma unroll
            for (int i = 0; i < 2; i++) {
                int r0 = wm*32 + i*16 + g;
                ahr[i][0] = *(const uint32_t*)&cAh[r0*40     + kk + t*2];
                ahr[i][1] = *(const uint32_t*)&cAh[(r0+8)*40 + kk + t*2];
                ahr[i][2] = *(const uint32_t*)&cAh[r0*40     + kk + 8 + t*2];
                ahr[i][3] = *(const uint32_t*)&cAh[(r0+8)*40 + kk + 8 + t*2];
                alr[i][0] = *(const uint32_t*)&cAl[r0*40     + kk + t*2];
                alr[i][1] = *(const uint32_t*)&cAl[(r0+8)*40 + kk + t*2];
                alr[i][2] = *(const uint32_t*)&cAl[r0*40     + kk + 8 + t*2];
                alr[i][3] = *(const uint32_t*)&cAl[(r0+8)*40 + kk + 8 + t*2];
            }
#pragma unroll
            for (int j = 0; j < 4; j++) {
                int nn = wn*32 + j*8 + g;
                bhr[j][0] = *(const uint32_t*)&cBh[nn*40 + kk + t*2];
                bhr[j][1] = *(const uint32_t*)&cBh[nn*40 + kk + 8 + t*2];
                blr[j][0] = *(const uint32_t*)&cBl[nn*40 + kk + t*2];
                blr[j][1] = *(const uint32_t*)&cBl[nn*40 + kk + 8 + t*2];
            }
#pragma unroll
            for (int i = 0; i < 2; i++)
#pragma unroll
                for (int j = 0; j < 4; j++) {
                    MMA_BF16(acc[i][j], ahr[i], bhr[j]);
                    MMA_BF16(acc[i][j], alr[i], bhr[j]);
                    MMA_BF16(acc[i][j], ahr[i], blr[j]);
                }
        }
    }

#pragma unroll
    for (int i = 0; i < 2; i++)
#pragma unroll
        for (int j = 0; j < 4; j++) {
            int row0 = m0 + wm*32 + i*16 + g;
            int col  = n0 + wn*32 + j*8 + t*2;
            float b0 = bias[col], b1 = bias[col+1];
            float2 o0 = make_float2(alpha*(acc[i][j][0]+b0), alpha*(acc[i][j][1]+b1));
            float2 o1 = make_float2(alpha*(acc[i][j][2]+b0), alpha*(acc[i][j][3]+b1));
            *(float2*)(Cm + (size_t)row0    *ldc + col) = o0;
            *(float2*)(Cm + (size_t)(row0+8)*ldc + col) = o1;
        }
}

// ---------------------------------------------------------------------------
// One merged prep kernel.  Grid 10512:
//   [0,4096)      x split            (1,048,576 float4 groups)
//   [4096,8192)   sr gather+split    (1,048,576 groups of 4)
//   [8192,8960)   wcat pack          (196,608)
//   [8960,10496)  kv1/proj/sr wsplit (393,216)
//   [10496,10512) d_g zero           (4096)
// ---------------------------------------------------------------------------
__global__ void prep_all(
    const float* __restrict__ x,
    const float* __restrict__ q1w, const float* __restrict__ q2w,
    const float* __restrict__ kv2w, const float* __restrict__ lepw,
    const float* __restrict__ q1b, const float* __restrict__ q2b,
    const float* __restrict__ kv2b, const float* __restrict__ lepb,
    const float* __restrict__ kv1w, const float* __restrict__ projw,
    const float* __restrict__ srw)
{
    int blk = blockIdx.x, tid = threadIdx.x;
    if (blk < 4096) {
        int i = blk * 256 + tid;                       // 1,048,576 float4 groups
        float4 v = ((const float4*)x)[i];
        __nv_bfloat16 h0 = __float2bfloat16(v.x), h1 = __float2bfloat16(v.y);
        __nv_bfloat16 h2 = __float2bfloat16(v.z), h3 = __float2bfloat16(v.w);
        __nv_bfloat16 l0 = __float2bfloat16(v.x - __bfloat162float(h0));
        __nv_bfloat16 l1 = __float2bfloat16(v.y - __bfloat162float(h1));
        __nv_bfloat16 l2 = __float2bfloat16(v.z - __bfloat162float(h2));
        __nv_bfloat16 l3 = __float2bfloat16(v.w - __bfloat162float(h3));
        ((__nv_bfloat162*)d_xh)[i*2]   = __nv_bfloat162(h0, h1);
        ((__nv_bfloat162*)d_xh)[i*2+1] = __nv_bfloat162(h2, h3);
        ((__nv_bfloat162*)d_xl)[i*2]   = __nv_bfloat162(l0, l1);
        ((__nv_bfloat162*)d_xl)[i*2+1] = __nv_bfloat162(l2, l3);
    } else if (blk < 8192) {
        int v = (blk - 4096) * 256 + tid;              // 1,048,576 groups of 4
        int r = v >> 8, col4 = v & 255;
        int k = col4 * 4;
        int dd = k >> 8, ci = k & 255;
        int b = r >> 10, p = r & 1023;
        int ii = p >> 5, jj = p & 31;
        int di = dd >> 1, dj = dd & 1;
        int n = (2*ii + di) * W_ + 2*jj + dj;
        float4 xv = *(const float4*)(x + (size_t)(b * NTOK + n) * C_ + ci);
        __nv_bfloat16 h0 = __float2bfloat16(xv.x), h1 = __float2bfloat16(xv.y);
        __nv_bfloat16 h2 = __float2bfloat16(xv.z), h3 = __float2bfloat16(xv.w);
        __nv_bfloat16 l0 = __float2bfloat16(xv.x - __bfloat162float(h0));
        __nv_bfloat16 l1 = __float2bfloat16(xv.y - __bfloat162float(h1));
        __nv_bfloat16 l2 = __float2bfloat16(xv.z - __bfloat162float(h2));
        __nv_bfloat16 l3 = __float2bfloat16(xv.w - __bfloat162float(h3));
        size_t o = ((size_t)r * 1024 + k) >> 1;        // bfloat162 index
        ((__nv_bfloat162*)d_agh)[o]   = __nv_bfloat162(h0, h1);
        ((__nv_bfloat162*)d_agh)[o+1] = __nv_bfloat162(h2, h3);
        ((__nv_bfloat162*)d_agl)[o]   = __nv_bfloat162(l0, l1);
        ((__nv_bfloat162*)d_agl)[o+1] = __nv_bfloat162(l2, l3);
    } else if (blk < 8960) {
        int idx = (blk - 8192) * 256 + tid;            // 196,608
        int k = idx / 768, col = idx - k * 768;
        float v;
        if (col < 128)       v = q1w[k*128 + col];
        else if (col < 256)  v = q2w[k*128 + col - 128];
        else if (col < 512)  v = kv2w[k*256 + col - 256];
        else                 v = lepw[k*256 + col - 512];
        __nv_bfloat16 h = __float2bfloat16(v);
        d_wcath[idx] = h;
        d_wcatl[idx] = __float2bfloat16(v - __bfloat162float(h));
        if (idx < 768) {
            float b = (idx < 128) ? q1b[idx] : (idx < 256) ? q2b[idx-128]
                    : (idx < 512) ? kv2b[idx-256] : lepb[idx-512];
            d_bcat[idx] = b;
        }
    } else if (blk < 10496) {
        int idx = (blk - 8960) * 256 + tid;            // 393,216
        float v;
        if (idx < 65536) {
            v = kv1w[idx];
            __nv_bfloat16 h = __float2bfloat16(v);
            d_w2h[idx] = h; d_w2l[idx] = __float2bfloat16(v - __bfloat162float(h));
        } else if (idx < 131072) {
            v = projw[idx - 65536];
            __nv_bfloat16 h = __float2bfloat16(v);
            d_w2h[idx] = h; d_w2l[idx] = __float2bfloat16(v - __bfloat162float(h));
        } else {
            int i = idx - 131072;                      // 262,144
            int co = i & 255, kk = i >> 8;
            int dd = kk >> 8, ci = kk & 255;
            v = srw[co * 1024 + ci * 4 + dd];
            __nv_bfloat16 h = __float2bfloat16(v);
            d_srwh[i] = h; d_srwl[i] = __float2bfloat16(v - __bfloat162float(h));
        }
    } else {
        int i = (blk - 10496) * 256 + tid;
        if (i < B_ * N1_) d_g[i] = 0.f;
    }
}

// ---------------------------------------------------------------------------
__global__ void ln_gelu_kernel(const float* __restrict__ nw,
                               const float* __restrict__ nb)
{
    __shared__ float sh[8];
    int r = blockIdx.x, c = threadIdx.x;
    float v = d_xsraw[(size_t)r * C_ + c];

    float s = v;
#pragma unroll
    for (int o = 16; o > 0; o >>= 1) s += __shfl_xor_sync(0xffffffffu, s, o);
    if ((c & 31) == 0) sh[c >> 5] = s;
    __syncthreads();
    if (c < 32) {
        float t = (c < 8) ? sh[c] : 0.f;
#pragma unroll
        for (int o = 4; o > 0; o >>= 1) t += __shfl_xor_sync(0xffffffffu, t, o);
        if (c == 0) sh[0] = t;
    }
    __syncthreads();
    float mean = sh[0] * (1.f / 256.f);
    __syncthreads();

    float dv = v - mean;
    float q = dv * dv;
#pragma unroll
    for (int o = 16; o > 0; o >>= 1) q += __shfl_xor_sync(0xffffffffu, q, o);
    if ((c & 31) == 0) sh[c >> 5] = q;
    __syncthreads();
    if (c < 32) {
        float t = (c < 8) ? sh[c] : 0.f;
#pragma unroll
        for (int o = 4; o > 0; o >>= 1) t += __shfl_xor_sync(0xffffffffu, t, o);
        if (c == 0) sh[0] = t;
    }
    __syncthreads();
    float var = sh[0] * (1.f / 256.f);

    float y = dv * rsqrtf(var + 1e-5f) * nw[c] + nb[c];
    float ge = 0.5f * y * (1.f + erff(y * 0.70710678118654752f));
    __nv_bfloat16 h = __float2bfloat16(ge);
    d_xsh[(size_t)r * C_ + c] = h;
    d_xsl[(size_t)r * C_ + c] = __float2bfloat16(ge - __bfloat162float(h));
}

// ---------------------------------------------------------------------------
// Fused branch-1 attention (fp32; vectorized smem).
// ---------------------------------------------------------------------------
__global__ void __launch_bounds__(256) attn1_fused(
    const float* __restrict__ proj, const float* __restrict__ kv1,
    float* __restrict__ cat, float* __restrict__ g)
{
    extern __shared__ float sm[];
    float* S   = sm;                    // 32*1024
    float* Qs  = sm + 32*1024;          // 32*33
    float* inv = Qs + 32*33;            // 32
    float* KV  = inv + 32;              // 4608

    int tid = threadIdx.x, tx = tid & 15, ty = tid >> 4;
    int bh = blockIdx.y; int b = bh >> 2, h = bh & 3;
    int q0 = blockIdx.x * 32;

    const float* Qg = proj + (size_t)(b * NTOK + q0) * 768 + h * 32;
    const float* Kg = kv1 + (size_t)b * N1_ * 256 + h * 32;
    const float* Vg = Kg + 128;

    {
        int qq = tid >> 3, dq = tid & 7;
        float4 v = *(const float4*)(Qg + (size_t)qq * 768 + dq * 4);
        Qs[qq*33 + dq*4+0] = v.x; Qs[qq*33 + dq*4+1] = v.y;
        Qs[qq*33 + dq*4+2] = v.z; Qs[qq*33 + dq*4+3] = v.w;
    }
    {
        int kk = tid >> 3, dq = tid & 7;
        float4 v0 = *(const float4*)(Kg + (size_t)kk * 256 + dq * 4);
        float4 v1 = *(const float4*)(Kg + (size_t)(kk+32) * 256 + dq * 4);
        float* Kb = KV;
        Kb[(dq*4+0)*68 + kk] = v0.x; Kb[(dq*4+1)*68 + kk] = v0.y;
        Kb[(dq*4+2)*68 + kk] = v0.z; Kb[(dq*4+3)*68 + kk] = v0.w;
        Kb[(dq*4+0)*68 + kk+32] = v1.x; Kb[(dq*4+1)*68 + kk+32] = v1.y;
        Kb[(dq*4+2)*68 + kk+32] = v1.z; Kb[(dq*4+3)*68 + kk+32] = v1.w;
    }
    __syncthreads();

    float sc = ATT_SCALE;
    float qr[2][32];
#pragma unroll
    for (int i = 0; i < 2; i++)
#pragma unroll
        for (int d = 0; d < 32; d++)
            qr[i][d] = Qs[(ty*2+i)*33 + d] * sc;

    int kk0 = tid >> 3, dq0 = tid & 7;
    for (int t = 0; t < 16; t++) {
        float4 p0, p1;
        bool pf = (t < 15);
        if (pf) {
            const float* src = Kg + (size_t)((t+1)*64) * 256;
            p0 = *(const float4*)(src + (size_t)kk0 * 256 + dq0 * 4);
            p1 = *(const float4*)(src + (size_t)(kk0+32) * 256 + dq0 * 4);
        }
        const float* Kb = KV + (t & 1) * 2176;
        float acc[2][4];
#pragma unroll
        for (int i = 0; i < 2; i++)
#pragma unroll
            for (int j = 0; j < 4; j++) acc[i][j] = 0.f;
#pragma unroll
        for (int d = 0; d < 32; d++) {
            float4 bv = *(const float4*)&Kb[d*68 + tx*4];
#pragma unroll
            for (int i = 0; i < 2; i++) {
                float a = qr[i][d];
                acc[i][0] += a*bv.x; acc[i][1] += a*bv.y;
                acc[i][2] += a*bv.z; acc[i][3] += a*bv.w;
            }
        }
#pragma unroll
        for (int i = 0; i < 2; i++)
            *(float4*)&S[(size_t)(ty*2+i)*1024 + t*64 + tx*4] =
                make_float4(acc[i][0], acc[i][1], acc[i][2], acc[i][3]);
        if (pf) {
            float* Kn = KV + ((t+1) & 1) * 2176;
            Kn[(dq0*4+0)*68 + kk0] = p0.x; Kn[(dq0*4+1)*68 + kk0] = p0.y;
            Kn[(dq0*4+2)*68 + kk0] = p0.z; Kn[(dq0*4+3)*68 + kk0] = p0.w;
            Kn[(dq0*4+0)*68 + kk0+32] = p1.x; Kn[(dq0*4+1)*68 + kk0+32] = p1.y;
            Kn[(dq0*4+2)*68 + kk0+32] = p1.z; Kn[(dq0*4+3)*68 + kk0+32] = p1.w;
        }
        __syncthreads();
    }

    {
        int warp = tid >> 5, lane = tid & 31;
#pragma unroll
        for (int rr = 0; rr < 4; rr++) {
            int row = warp * 4 + rr;
            float* Sr = S + (size_t)row * 1024;
            float m = -1e30f;
#pragma unroll
            for (int i = 0; i < 32; i++) m = fmaxf(m, Sr[lane + 32*i]);
#pragma unroll
            for (int o = 16; o > 0; o >>= 1)
                m = fmaxf(m, __shfl_xor_sync(0xffffffffu, m, o));
            float s = 0.f;
#pragma unroll
            for (int i = 0; i < 32; i++) {
                float e = __expf(Sr[lane + 32*i] - m);
                Sr[lane + 32*i] = e;
                s += e;
            }
#pragma unroll
            for (int o = 16; o > 0; o >>= 1)
                s += __shfl_xor_sync(0xffffffffu, s, o);
            if (lane == 0) inv[row] = 1.f / s;
        }
    }
    __syncthreads();

    {
        float a0 = 0.f, a1 = 0.f, a2 = 0.f, a3 = 0.f;
#pragma unroll
        for (int q = 0; q < 32; q++) {
            float iv = inv[q];
            const float* Sq = S + (size_t)q * 1024;
            a0 += Sq[tid      ] * iv;
            a1 += Sq[tid + 256] * iv;
            a2 += Sq[tid + 512] * iv;
            a3 += Sq[tid + 768] * iv;
        }
        float* gb = g + b * N1_;
        atomicAdd(&gb[tid      ], a0);
        atomicAdd(&gb[tid + 256], a1);
        atomicAdd(&gb[tid + 512], a2);
        atomicAdd(&gb[tid + 768], a3);
    }

    float* Vs = KV;
    int khalf = (tx >> 3) * 512;
    int dgrp  = (tx & 7) * 4;
    float av[2][4];
#pragma unroll
    for (int i = 0; i < 2; i++)
#pragma unroll
        for (int j = 0; j < 4; j++) av[i][j] = 0.f;

    for (int r = 0; r < 8; r++) {
        __syncthreads();
#pragma unroll
        for (int l = 0; l < 4; l++) {
            int idx = tid + l * 256;
            int vr = idx >> 3, dq = idx & 7;
            int key = (vr < 64) ? (r*64 + vr) : (512 + r*64 + (vr - 64));
            float4 v = *(const float4*)(Vg + (size_t)key * 256 + dq * 4);
            *(float4*)&Vs[vr*36 + dq*4] = v;
        }
        __syncthreads();
        int vbase = (tx >> 3) * 64;
#pragma unroll 4
        for (int kk = 0; kk < 64; kk++) {
            int kabs = khalf + r*64 + kk;
            float e0 = S[(size_t)(ty*2+0)*1024 + kabs];
            float e1 = S[(size_t)(ty*2+1)*1024 + kabs];
            float4 vv = *(const float4*)&Vs[(vbase + kk)*36 + dgrp];
            av[0][0] += e0*vv.x; av[0][1] += e0*vv.y; av[0][2] += e0*vv.z; av[0][3] += e0*vv.w;
            av[1][0] += e1*vv.x; av[1][1] += e1*vv.y; av[1][2] += e1*vv.z; av[1][3] += e1*vv.w;
        }
    }
#pragma unroll
    for (int i = 0; i < 2; i++)
#pragma unroll
        for (int j = 0; j < 4; j++)
            av[i][j] += __shfl_xor_sync(0xffffffffu, av[i][j], 8);

    if ((tid & 8) == 0) {
#pragma unroll
        for (int i = 0; i < 2; i++) {
            int q = ty*2 + i;
            float iv = inv[q];
            float4 o = make_float4(av[i][0]*iv, av[i][1]*iv, av[i][2]*iv, av[i][3]*iv);
            *(float4*)&cat[(size_t)(b*NTOK + q0 + q)*256 + h*32 + dgrp] = o;
        }
    }
}

// ---------------------------------------------------------------------------
__global__ void attn2_kernel(const float* __restrict__ proj)
{
    int win = blockIdx.x;
    int b = win >> 8, rem = win & 255, gy = rem >> 4, gx = rem & 15;
    int tid = threadIdx.x, h = tid >> 5, lane = tid & 31;

    __shared__ float Qs[4][16][32];
    __shared__ float Ks[4][16][32];
    __shared__ float Vs[4][16][32];
    __shared__ float csum[16];

    for (int i = lane; i < 16 * 32; i += 32) {
        int t = i >> 5, dd = i & 31;
        int n = (gy * 4 + (t >> 2)) * W_ + gx * 4 + (t & 3);
        const float* base = proj + (size_t)(b * NTOK + n) * 768;
        Qs[h][t][dd] = base[128 + h * 32 + dd];
        Ks[h][t][dd] = base[256 + h * 32 + dd];
        Vs[h][t][dd] = base[256 + 128 + h * 32 + dd];
    }
    if (tid < 16) csum[tid] = 0.f;
    __syncthreads();

    if (lane < 16) {
        int q = lane;
        float s[16];
        float mx = -1e30f;
#pragma unroll
        for (int m = 0; m < 16; m++) {
            float dot = 0.f;
#pragma unroll
            for (int dd = 0; dd < 32; dd++) dot += Qs[h][q][dd] * Ks[h][m][dd];
            s[m] = dot * ATT_SCALE;
            mx = fmaxf(mx, s[m]);
        }
        float sum = 0.f;
#pragma unroll
        for (int m = 0; m < 16; m++) { s[m] = __expf(s[m] - mx); sum += s[m]; }
        float iv = 1.f / sum;
#pragma unroll
        for (int m = 0; m < 16; m++) {
            s[m] *= iv;
            atomicAdd(&csum[m], s[m]);
        }
        int nq = (gy * 4 + (q >> 2)) * W_ + gx * 4 + (q & 3);
        float* outp = d_cat + (size_t)(b * NTOK + nq) * 256 + 128 + h * 32;
#pragma unroll
        for (int dd = 0; dd < 32; dd++) {
            float o = 0.f;
#pragma unroll
            for (int m = 0; m < 16; m++) o += s[m] * Vs[h][m][dd];
            outp[dd] = o;
        }
    }
    __syncthreads();
    if (tid < 16) {
        int m = tid;
        int np = (gy * 4 + (m >> 2)) * W_ + gx * 4 + (m & 3);
        d_lm[b * NTOK + np] = csum[m] * (1.f / 64.f);
    }
}

// ---------------------------------------------------------------------------
__global__ void lepe_add_kernel(const float* __restrict__ proj,
                                const float* __restrict__ w9,
                                const float* __restrict__ cb)
{
    int r = blockIdx.x;
    int c = threadIdx.x;
    int b = r >> 12, n = r & 4095, y = n >> 6, x = n & 63;
    float wv[9];
#pragma unroll
    for (int t = 0; t < 9; t++) wv[t] = w9[c * 9 + t];
    float acc = cb[c];
#pragma unroll
    for (int dy = 0; dy < 3; dy++) {
        int yy = y + dy - 1;
        if (yy < 0 || yy >= H_) continue;
#pragma unroll
        for (int dx = 0; dx < 3; dx++) {
            int xx = x + dx - 1;
            if (xx < 0 || xx >= W_) continue;
            acc += wv[dy * 3 + dx] *
                   proj[(size_t)(b * NTOK + yy * W_ + xx) * 768 + 512 + c];
        }
    }
    float v = d_cat[(size_t)r * C_ + c] + acc;
    __nv_bfloat16 h = __float2bfloat16(v);
    d_cath[(size_t)r * C_ + c] = h;
    d_catl[(size_t)r * C_ + c] = __float2bfloat16(v - __bfloat162float(h));
}

// ---------------------------------------------------------------------------
__global__ void mask_kernel(float* __restrict__ out)
{
    int idx = blockIdx.x * 256 + threadIdx.x;
    int b = idx >> 12, pos = idx & 4095, y = pos >> 6, x = pos & 63;
    float gv = d_g[b * N1_ + (y >> 1) * 32 + (x >> 1)] * (1.f / (NH2 * NTOK));
    float val = d_lm[idx] + gv;
    out[OUT_M1 + idx] = val;
    out[OUT_M2 + b * NTOK + x * 64 + y] = val;
}

// ---------------------------------------------------------------------------
extern "C" void kernel_launch(void* const* d_in, const int* in_sizes, int n_in,
                              void* d_out, int out_size)
{
    const float* x      = (const float*)d_in[0];
    const float* q1_w   = (const float*)d_in[1];
    const float* q1_b   = (const float*)d_in[2];
    const float* kv1_w  = (const float*)d_in[3];
    const float* kv1_b  = (const float*)d_in[4];
    const float* q2_w   = (const float*)d_in[5];
    const float* q2_b   = (const float*)d_in[6];
    const float* kv2_w  = (const float*)d_in[7];
    const float* kv2_b  = (const float*)d_in[8];
    const float* lepe_w = (const float*)d_in[9];
    const float* lepe_b = (const float*)d_in[10];
    const float* lcw    = (const float*)d_in[11];
    const float* lcb    = (const float*)d_in[12];
    const float* sr_w   = (const float*)d_in[13];
    const float* sr_b   = (const float*)d_in[14];
    const float* nw     = (const float*)d_in[15];
    const float* nb     = (const float*)d_in[16];
    const float* pw     = (const float*)d_in[17];
    const float* pb     = (const float*)d_in[18];
    float* out = (float*)d_out;

    void* p;
    float *projp, *kv1p, *catp, *gp, *xsraw, *bcat;
    __nv_bfloat16 *xh, *xl, *wcath, *wcatl, *w2h, *w2l, *srwh, *srwl;
    __nv_bfloat16 *agh, *agl, *xsh, *xsl, *cath, *catl;
    cudaGetSymbolAddress(&p, d_proj);  projp = (float*)p;
    cudaGetSymbolAddress(&p, d_kv1);   kv1p  = (float*)p;
    cudaGetSymbolAddress(&p, d_cat);   catp  = (float*)p;
    cudaGetSymbolAddress(&p, d_g);     gp    = (float*)p;
    cudaGetSymbolAddress(&p, d_xsraw); xsraw = (float*)p;
    cudaGetSymbolAddress(&p, d_bcat);  bcat  = (float*)p;
    cudaGetSymbolAddress(&p, d_xh);    xh    = (__nv_bfloat16*)p;
    cudaGetSymbolAddress(&p, d_xl);    xl    = (__nv_bfloat16*)p;
    cudaGetSymbolAddress(&p, d_wcath); wcath = (__nv_bfloat16*)p;
    cudaGetSymbolAddress(&p, d_wcatl); wcatl = (__nv_bfloat16*)p;
    cudaGetSymbolAddress(&p, d_w2h);   w2h   = (__nv_bfloat16*)p;
    cudaGetSymbolAddress(&p, d_w2l);   w2l   = (__nv_bfloat16*)p;
    cudaGetSymbolAddress(&p, d_srwh);  srwh  = (__nv_bfloat16*)p;
    cudaGetSymbolAddress(&p, d_srwl);  srwl  = (__nv_bfloat16*)p;
    cudaGetSymbolAddress(&p, d_agh);   agh   = (__nv_bfloat16*)p;
    cudaGetSymbolAddress(&p, d_agl);   agl   = (__nv_bfloat16*)p;
    cudaGetSymbolAddress(&p, d_xsh);   xsh   = (__nv_bfloat16*)p;
    cudaGetSymbolAddress(&p, d_xsl);   xsl   = (__nv_bfloat16*)p;
    cudaGetSymbolAddress(&p, d_cath);  cath  = (__nv_bfloat16*)p;
    cudaGetSymbolAddress(&p, d_catl);  catl  = (__nv_bfloat16*)p;

    const int ATTN_SMEM = (32*1024 + 32*33 + 32 + 4608) * 4;  // 153856 B
    cudaFuncSetAttribute(attn1_fused,
                         cudaFuncAttributeMaxDynamicSharedMemorySize, ATTN_SMEM);
    cudaFuncSetAttribute(gemm_mma,
                         cudaFuncAttributeMaxDynamicSharedMemorySize, GEMM_SMEM);

    // 1: all prep in one kernel (includes d_g zero)
    prep_all<<<10512, 256>>>(x, q1_w, q2_w, kv2_w, lepe_w,
                             q1_b, q2_b, kv2_b, lepe_b, kv1_w, pw, sr_w);

    // 2: fused x-projections -> d_proj [tok][768]
    gemm_mma<<<dim3(12, 128), 256, GEMM_SMEM>>>(xh, xl, 256, wcath, wcatl, 768,
                                                bcat, projp, 768, 256, 1.f);
    // 3-5: sr conv GEMM -> LN+GELU(split) -> kv1 GEMM
    gemm_mma<<<dim3(4, 32), 256, GEMM_SMEM>>>(agh, agl, 1024, srwh, srwl, 256,
                                              sr_b, xsraw, 256, 1024, 1.f);
    ln_gelu_kernel<<<B_ * N1_, 256>>>(nw, nb);
    gemm_mma<<<dim3(4, 32), 256, GEMM_SMEM>>>(xsh, xsl, 256, w2h, w2l, 256,
                                              kv1_b, kv1p, 256, 256, 1.f);

    // 6: fused branch-1 attention  (ncu -s 5 window lands here)
    attn1_fused<<<dim3(128, 16), 256, ATTN_SMEM>>>(projp, kv1p, catp, gp);

    // 7-8: branch 2 + lepe/cat split
    attn2_kernel<<<B_ * 16 * 16, 128>>>(projp);
    lepe_add_kernel<<<B_ * NTOK, 256>>>(projp, lcw, lcb);

    // 9: final projection: out = 2*(cat @ proj_w + proj_b)
    gemm_mma<<<dim3(4, 128), 256, GEMM_SMEM>>>(cath, catl, 256,
                                               w2h + 65536, w2l + 65536, 256,
                                               pb, out, 256, 256, 2.f);
    // 10: masks
    mask_kernel<<<64, 256>>>(out);
}

// round 10
// speedup vs baseline: 4.3253x; 1.1457x over previous
#include <cuda_runtime.h>
#include <cuda_bf16.h>
#include <math.h>
#include <stdint.h>

#define B_    4
#define NTOK  4096
#define C_    256
#define H_    64
#define W_    64
#define NH2   4
#define N1_   1024

#define OUT_MAIN (B_*NTOK*C_)
#define OUT_M1   (OUT_MAIN)
#define OUT_M2   (OUT_MAIN + B_*NTOK)

// fp32 intermediates
static __device__ float d_proj[B_*NTOK*768];   // [q1|q2|kv2|lepe]
static __device__ float d_xsraw[4*B_*N1_*C_];  // 4 split-K partials
static __device__ float d_kv1[B_*N1_*C_];
static __device__ float d_cat[B_*NTOK*C_];
static __device__ float d_g[B_*N1_];
static __device__ float d_lm[B_*NTOK];
static __device__ float d_bcat[768];

// bf16 split buffers
static __device__ __nv_bfloat16 d_xh[B_*NTOK*C_],   d_xl[B_*NTOK*C_];
static __device__ __nv_bfloat16 d_wcath[256*768],   d_wcatl[256*768];
static __device__ __nv_bfloat16 d_w2h[131072],      d_w2l[131072];   // kv1 | proj
static __device__ __nv_bfloat16 d_srwh[1024*C_],    d_srwl[1024*C_];
static __device__ __nv_bfloat16 d_agh[4096*1024],   d_agl[4096*1024];
static __device__ __nv_bfloat16 d_xsh[B_*N1_*C_],   d_xsl[B_*N1_*C_];
static __device__ __nv_bfloat16 d_cath[B_*NTOK*C_], d_catl[B_*NTOK*C_];

__device__ __constant__ float ATT_SCALE = 0.17677669529663687f; // 1/sqrt(32)

#define MMA_BF16(c, a, b) \
  asm volatile("mma.sync.aligned.m16n8k16.row.col.f32.bf16.bf16.f32 " \
    "{%0,%1,%2,%3}, {%4,%5,%6,%7}, {%8,%9}, {%0,%1,%2,%3};" \
    : "+f"((c)[0]), "+f"((c)[1]), "+f"((c)[2]), "+f"((c)[3]) \
    : "r"((a)[0]), "r"((a)[1]), "r"((a)[2]), "r"((a)[3]), \
      "r"((b)[0]), "r"((b)[1]))

#define LDSM_X4(r, addr) \
  asm volatile("ldmatrix.sync.aligned.m8n8.x4.shared.b16 {%0,%1,%2,%3}, [%4];" \
    : "=r"((r)[0]), "=r"((r)[1]), "=r"((r)[2]), "=r"((r)[3]) : "r"(addr))

#define LDSM_X4T(r, addr) \
  asm volatile("ldmatrix.sync.aligned.m8n8.x4.trans.shared.b16 {%0,%1,%2,%3}, [%4];" \
    : "=r"((r)[0]), "=r"((r)[1]), "=r"((r)[2]), "=r"((r)[3]) : "r"(addr))

__device__ __forceinline__ void cpa16(uint32_t saddr, const void* g) {
    asm volatile("cp.async.ca.shared.global [%0], [%1], 16;"
                 :: "r"(saddr), "l"(g));
}

// ---------------------------------------------------------------------------
// gemm2: bf16-split GEMM, 128x128 block tile, ldmatrix fragments,
// cp.async double-buffered. 8 warps = 2(m) x 4(n) of 64x32 warp tiles.
// A smem [m][k] stride 40 halfs; B smem [k][n] stride 136 halfs.
// C = alpha*((Ah+Al)@(Bh+Bl) + bias)  (bias!=null)  or raw partial (bias==null).
// blockIdx.z = split-K part (A += z*K, B += z*K*ldb, C += z*cstride).
// ---------------------------------------------------------------------------
#define GEMM2_SMEM 75776
__global__ void __launch_bounds__(256) gemm2(
    const __nv_bfloat16* __restrict__ Ah, const __nv_bfloat16* __restrict__ Al, int lda,
    const __nv_bfloat16* __restrict__ Bh, const __nv_bfloat16* __restrict__ Bl, int ldb,
    const float* __restrict__ bias, float* __restrict__ Cm, int ldc,
    size_t cstride, int K, float alpha)
{
    extern __shared__ uint16_t sm16[];
    uint32_t sb = (uint32_t)__cvta_generic_to_shared(sm16);
    const uint32_t AHo = 0, ALo = 20480, BHo = 40960, BLo = 58368;

    int tid = threadIdx.x, lane = tid & 31, warp = tid >> 5;
    int wm = warp >> 2, wn = warp & 3;
    int m0 = blockIdx.y * 128, n0 = blockIdx.x * 128;
    int kz = blockIdx.z;
    int g = lane >> 2, t = lane & 3;

    const __nv_bfloat16* Ahp = Ah + (size_t)kz * K;
    const __nv_bfloat16* Alp = Al + (size_t)kz * K;
    const __nv_bfloat16* Bhp = Bh + (size_t)kz * K * ldb;
    const __nv_bfloat16* Blp = Bl + (size_t)kz * K * ldb;

    float acc[4][4][4];
#pragma unroll
    for (int i = 0; i < 4; i++)
#pragma unroll
        for (int j = 0; j < 4; j++)
#pragma unroll
            for (int c = 0; c < 4; c++) acc[i][j][c] = 0.f;

    // per-chunk loader: A 128x32 halfs, B 32x128 halfs (hi+lo each)
    int av = tid;                       // A: 2 iters of 256
    int arow0 = av >> 2, aseg0 = av & 3;
    int arow1 = (av + 256) >> 2, aseg1 = (av + 256) & 3;
    int brow0 = av >> 4, bseg0 = av & 15;
    int brow1 = (av + 256) >> 4, bseg1 = (av + 256) & 15;

#define LOAD_CHUNK(bi, k0) do { \
    uint32_t aB = sb + (bi)*10240; \
    uint32_t bB = sb + (bi)*8704; \
    cpa16(aB + AHo + (uint32_t)((arow0*40 + aseg0*8)*2), Ahp + (size_t)(m0+arow0)*lda + (k0) + aseg0*8); \
    cpa16(aB + AHo + (uint32_t)((arow1*40 + aseg1*8)*2), Ahp + (size_t)(m0+arow1)*lda + (k0) + aseg1*8); \
    cpa16(aB + ALo + (uint32_t)((arow0*40 + aseg0*8)*2), Alp + (size_t)(m0+arow0)*lda + (k0) + aseg0*8); \
    cpa16(aB + ALo + (uint32_t)((arow1*40 + aseg1*8)*2), Alp + (size_t)(m0+arow1)*lda + (k0) + aseg1*8); \
    cpa16(bB + BHo + (uint32_t)((brow0*136 + bseg0*8)*2), Bhp + (size_t)((k0)+brow0)*ldb + n0 + bseg0*8); \
    cpa16(bB + BHo + (uint32_t)((brow1*136 + bseg1*8)*2), Bhp + (size_t)((k0)+brow1)*ldb + n0 + bseg1*8); \
    cpa16(bB + BLo + (uint32_t)((brow0*136 + bseg0*8)*2), Blp + (size_t)((k0)+brow0)*ldb + n0 + bseg0*8); \
    cpa16(bB + BLo + (uint32_t)((brow1*136 + bseg1*8)*2), Blp + (size_t)((k0)+brow1)*ldb + n0 + bseg1*8); \
    asm volatile("cp.async.commit_group;" ::: "memory"); \
} while (0)

    LOAD_CHUNK(0, 0);

    // ldmatrix lane addresses
    uint32_t aoff = (uint32_t)(((wm*64 + (lane & 15))*40 + (lane >> 4)*8) * 2);
    uint32_t boff = (uint32_t)(((lane & 15)*136 + wn*32 + (lane >> 4)*8) * 2);

    int nch = K >> 5;
    for (int c = 0; c < nch; c++) {
        int bi = c & 1;
        if (c + 1 < nch) {
            LOAD_CHUNK(bi ^ 1, (c + 1) << 5);
            asm volatile("cp.async.wait_group 1;" ::: "memory");
        } else {
            asm volatile("cp.async.wait_group 0;" ::: "memory");
        }
        __syncthreads();

        uint32_t aH = sb + AHo + bi*10240 + aoff;
        uint32_t aL = sb + ALo + bi*10240 + aoff;
        uint32_t bH = sb + BHo + bi*8704 + boff;
        uint32_t bL = sb + BLo + bi*8704 + boff;
#pragma unroll
        for (int kk = 0; kk < 32; kk += 16) {
            uint32_t afh[4][4], afl[4][4], bfh[4][2], bfl[4][2];
#pragma unroll
            for (int mt = 0; mt < 4; mt++) {
                LDSM_X4(afh[mt], aH + mt*1280 + kk*2);
                LDSM_X4(afl[mt], aL + mt*1280 + kk*2);
            }
#pragma unroll
            for (int jj = 0; jj < 2; jj++) {
                uint32_t r[4];
                LDSM_X4T(r, bH + kk*272 + jj*32);
                bfh[2*jj][0] = r[0]; bfh[2*jj][1] = r[1];
                bfh[2*jj+1][0] = r[2]; bfh[2*jj+1][1] = r[3];
                LDSM_X4T(r, bL + kk*272 + jj*32);
                bfl[2*jj][0] = r[0]; bfl[2*jj][1] = r[1];
                bfl[2*jj+1][0] = r[2]; bfl[2*jj+1][1] = r[3];
            }
#pragma unroll
            for (int mt = 0; mt < 4; mt++)
#pragma unroll
                for (int nj = 0; nj < 4; nj++) {
                    MMA_BF16(acc[mt][nj], afh[mt], bfh[nj]);
                    MMA_BF16(acc[mt][nj], afl[mt], bfh[nj]);
                    MMA_BF16(acc[mt][nj], afh[mt], bfl[nj]);
                }
        }
        __syncthreads();
    }

    float* Co = Cm + (size_t)kz * cstride;
    if (bias) {
#pragma unroll
        for (int mt = 0; mt < 4; mt++)
#pragma unroll
            for (int nj = 0; nj < 4; nj++) {
                int row = m0 + wm*64 + mt*16 + g;
                int col = n0 + wn*32 + nj*8 + t*2;
                float b0 = bias[col], b1 = bias[col+1];
                *(float2*)(Co + (size_t)row*ldc + col) =
                    make_float2(alpha*(acc[mt][nj][0]+b0), alpha*(acc[mt][nj][1]+b1));
                *(float2*)(Co + (size_t)(row+8)*ldc + col) =
                    make_float2(alpha*(acc[mt][nj][2]+b0), alpha*(acc[mt][nj][3]+b1));
            }
    } else {
#pragma unroll
        for (int mt = 0; mt < 4; mt++)
#pragma unroll
            for (int nj = 0; nj < 4; nj++) {
                int row = m0 + wm*64 + mt*16 + g;
                int col = n0 + wn*32 + nj*8 + t*2;
                *(float2*)(Co + (size_t)row*ldc + col) =
                    make_float2(acc[mt][nj][0], acc[mt][nj][1]);
                *(float2*)(Co + (size_t)(row+8)*ldc + col) =
                    make_float2(acc[mt][nj][2], acc[mt][nj][3]);
            }
    }
#undef LOAD_CHUNK
}

// ---------------------------------------------------------------------------
// One merged prep kernel.  Grid 10512 (same partition as R8).
// ---------------------------------------------------------------------------
__global__ void prep_all(
    const float* __restrict__ x,
    const float* __restrict__ q1w, const float* __restrict__ q2w,
    const float* __restrict__ kv2w, const float* __restrict__ lepw,
    const float* __restrict__ q1b, const float* __restrict__ q2b,
    const float* __restrict__ kv2b, const float* __restrict__ lepb,
    const float* __restrict__ kv1w, const float* __restrict__ projw,
    const float* __restrict__ srw)
{
    int blk = blockIdx.x, tid = threadIdx.x;
    if (blk < 4096) {
        int i = blk * 256 + tid;                       // 1,048,576 float4 groups
        float4 v = ((const float4*)x)[i];
        __nv_bfloat16 h0 = __float2bfloat16(v.x), h1 = __float2bfloat16(v.y);
        __nv_bfloat16 h2 = __float2bfloat16(v.z), h3 = __float2bfloat16(v.w);
        __nv_bfloat16 l0 = __float2bfloat16(v.x - __bfloat162float(h0));
        __nv_bfloat16 l1 = __float2bfloat16(v.y - __bfloat162float(h1));
        __nv_bfloat16 l2 = __float2bfloat16(v.z - __bfloat162float(h2));
        __nv_bfloat16 l3 = __float2bfloat16(v.w - __bfloat162float(h3));
        ((__nv_bfloat162*)d_xh)[i*2]   = __nv_bfloat162(h0, h1);
        ((__nv_bfloat162*)d_xh)[i*2+1] = __nv_bfloat162(h2, h3);
        ((__nv_bfloat162*)d_xl)[i*2]   = __nv_bfloat162(l0, l1);
        ((__nv_bfloat162*)d_xl)[i*2+1] = __nv_bfloat162(l2, l3);
    } else if (blk < 8192) {
        int v = (blk - 4096) * 256 + tid;              // 1,048,576 groups of 4
        int r = v >> 8, col4 = v & 255;
        int k = col4 * 4;
        int dd = k >> 8, ci = k & 255;
        int b = r >> 10, p = r & 1023;
        int ii = p >> 5, jj = p & 31;
        int di = dd >> 1, dj = dd & 1;
        int n = (2*ii + di) * W_ + 2*jj + dj;
        float4 xv = *(const float4*)(x + (size_t)(b * NTOK + n) * C_ + ci);
        __nv_bfloat16 h0 = __float2bfloat16(xv.x), h1 = __float2bfloat16(xv.y);
        __nv_bfloat16 h2 = __float2bfloat16(xv.z), h3 = __float2bfloat16(xv.w);
        __nv_bfloat16 l0 = __float2bfloat16(xv.x - __bfloat162float(h0));
        __nv_bfloat16 l1 = __float2bfloat16(xv.y - __bfloat162float(h1));
        __nv_bfloat16 l2 = __float2bfloat16(xv.z - __bfloat162float(h2));
        __nv_bfloat16 l3 = __float2bfloat16(xv.w - __bfloat162float(h3));
        size_t o = ((size_t)r * 1024 + k) >> 1;
        ((__nv_bfloat162*)d_agh)[o]   = __nv_bfloat162(h0, h1);
        ((__nv_bfloat162*)d_agh)[o+1] = __nv_bfloat162(h2, h3);
        ((__nv_bfloat162*)d_agl)[o]   = __nv_bfloat162(l0, l1);
        ((__nv_bfloat162*)d_agl)[o+1] = __nv_bfloat162(l2, l3);
    } else if (blk < 8960) {
        int idx = (blk - 8192) * 256 + tid;            // 196,608
        int k = idx / 768, col = idx - k * 768;
        float v;
        if (col < 128)       v = q1w[k*128 + col];
        else if (col < 256)  v = q2w[k*128 + col - 128];
        else if (col < 512)  v = kv2w[k*256 + col - 256];
        else                 v = lepw[k*256 + col - 512];
        __nv_bfloat16 h = __float2bfloat16(v);
        d_wcath[idx] = h;
        d_wcatl[idx] = __float2bfloat16(v - __bfloat162float(h));
        if (idx < 768) {
            float b = (idx < 128) ? q1b[idx] : (idx < 256) ? q2b[idx-128]
                    : (idx < 512) ? kv2b[idx-256] : lepb[idx-512];
            d_bcat[idx] = b;
        }
    } else if (blk < 10496) {
        int idx = (blk - 8960) * 256 + tid;            // 393,216
        float v;
        if (idx < 65536) {
            v = kv1w[idx];
            __nv_bfloat16 h = __float2bfloat16(v);
            d_w2h[idx] = h; d_w2l[idx] = __float2bfloat16(v - __bfloat162float(h));
        } else if (idx < 131072) {
            v = projw[idx - 65536];
            __nv_bfloat16 h = __float2bfloat16(v);
            d_w2h[idx] = h; d_w2l[idx] = __float2bfloat16(v - __bfloat162float(h));
        } else {
            int i = idx - 131072;                      // 262,144
            int co = i & 255, kk = i >> 8;
            int dd = kk >> 8, ci = kk & 255;
            v = srw[co * 1024 + ci * 4 + dd];
            __nv_bfloat16 h = __float2bfloat16(v);
            d_srwh[i] = h; d_srwl[i] = __float2bfloat16(v - __bfloat162float(h));
        }
    } else {
        int i = (blk - 10496) * 256 + tid;
        if (i < B_ * N1_) d_g[i] = 0.f;
    }
}

// ---------------------------------------------------------------------------
// LayerNorm+GELU; sums 4 split-K partials of the sr conv + bias.
// ---------------------------------------------------------------------------
__global__ void ln_gelu_kernel(const float* __restrict__ nw,
                               const float* __restrict__ nb,
                               const float* __restrict__ srb)
{
    __shared__ float sh[8];
    int r = blockIdx.x, c = threadIdx.x;
    size_t o = (size_t)r * C_ + c;
    const size_t P = (size_t)B_ * N1_ * C_;
    float v = d_xsraw[o] + d_xsraw[o + P] + d_xsraw[o + 2*P] + d_xsraw[o + 3*P]
            + srb[c];

    float s = v;
#pragma unroll
    for (int o2 = 16; o2 > 0; o2 >>= 1) s += __shfl_xor_sync(0xffffffffu, s, o2);
    if ((c & 31) == 0) sh[c >> 5] = s;
    __syncthreads();
    if (c < 32) {
        float t = (c < 8) ? sh[c] : 0.f;
#pragma unroll
        for (int o2 = 4; o2 > 0; o2 >>= 1) t += __shfl_xor_sync(0xffffffffu, t, o2);
        if (c == 0) sh[0] = t;
    }
    __syncthreads();
    float mean = sh[0] * (1.f / 256.f);
    __syncthreads();

    float dv = v - mean;
    float q = dv * dv;
#pragma unroll
    for (int o2 = 16; o2 > 0; o2 >>= 1) q += __shfl_xor_sync(0xffffffffu, q, o2);
    if ((c & 31) == 0) sh[c >> 5] = q;
    __syncthreads();
    if (c < 32) {
        float t = (c < 8) ? sh[c] : 0.f;
#pragma unroll
        for (int o2 = 4; o2 > 0; o2 >>= 1) t += __shfl_xor_sync(0xffffffffu, t, o2);
        if (c == 0) sh[0] = t;
    }
    __syncthreads();
    float var = sh[0] * (1.f / 256.f);

    float y = dv * rsqrtf(var + 1e-5f) * nw[c] + nb[c];
    float ge = 0.5f * y * (1.f + erff(y * 0.70710678118654752f));
    __nv_bfloat16 h = __float2bfloat16(ge);
    d_xsh[o] = h;
    d_xsl[o] = __float2bfloat16(ge - __bfloat162float(h));
}

// ---------------------------------------------------------------------------
// Fused branch-1 attention (unchanged from R8).
// ---------------------------------------------------------------------------
__global__ void __launch_bounds__(256) attn1_fused(
    const float* __restrict__ proj, const float* __restrict__ kv1,
    float* __restrict__ cat, float* __restrict__ g)
{
    extern __shared__ float sm[];
    float* S   = sm;
    float* Qs  = sm + 32*1024;
    float* inv = Qs + 32*33;
    float* KV  = inv + 32;

    int tid = threadIdx.x, tx = tid & 15, ty = tid >> 4;
    int bh = blockIdx.y; int b = bh >> 2, h = bh & 3;
    int q0 = blockIdx.x * 32;

    const float* Qg = proj + (size_t)(b * NTOK + q0) * 768 + h * 32;
    const float* Kg = kv1 + (size_t)b * N1_ * 256 + h * 32;
    const float* Vg = Kg + 128;

    {
        int qq = tid >> 3, dq = tid & 7;
        float4 v = *(const float4*)(Qg + (size_t)qq * 768 + dq * 4);
        Qs[qq*33 + dq*4+0] = v.x; Qs[qq*33 + dq*4+1] = v.y;
        Qs[qq*33 + dq*4+2] = v.z; Qs[qq*33 + dq*4+3] = v.w;
    }
    {
        int kk = tid >> 3, dq = tid & 7;
        float4 v0 = *(const float4*)(Kg + (size_t)kk * 256 + dq * 4);
        float4 v1 = *(const float4*)(Kg + (size_t)(kk+32) * 256 + dq * 4);
        float* Kb = KV;
        Kb[(dq*4+0)*68 + kk] = v0.x; Kb[(dq*4+1)*68 + kk] = v0.y;
        Kb[(dq*4+2)*68 + kk] = v0.z; Kb[(dq*4+3)*68 + kk] = v0.w;
        Kb[(dq*4+0)*68 + kk+32] = v1.x; Kb[(dq*4+1)*68 + kk+32] = v1.y;
        Kb[(dq*4+2)*68 + kk+32] = v1.z; Kb[(dq*4+3)*68 + kk+32] = v1.w;
    }
    __syncthreads();

    float sc = ATT_SCALE;
    float qr[2][32];
#pragma unroll
    for (int i = 0; i < 2; i++)
#pragma unroll
        for (int d = 0; d < 32; d++)
            qr[i][d] = Qs[(ty*2+i)*33 + d] * sc;

    int kk0 = tid >> 3, dq0 = tid & 7;
    for (int t = 0; t < 16; t++) {
        float4 p0, p1;
        bool pf = (t < 15);
        if (pf) {
            const float* src = Kg + (size_t)((t+1)*64) * 256;
            p0 = *(const float4*)(src + (size_t)kk0 * 256 + dq0 * 4);
            p1 = *(const float4*)(src + (size_t)(kk0+32) * 256 + dq0 * 4);
        }
        const float* Kb = KV + (t & 1) * 2176;
        float acc[2][4];
#pragma unroll
        for (int i = 0; i < 2; i++)
#pragma unroll
            for (int j = 0; j < 4; j++) acc[i][j] = 0.f;
#pragma unroll
        for (int d = 0; d < 32; d++) {
            float4 bv = *(const float4*)&Kb[d*68 + tx*4];
#pragma unroll
            for (int i = 0; i < 2; i++) {
                float a = qr[i][d];
                acc[i][0] += a*bv.x; acc[i][1] += a*bv.y;
                acc[i][2] += a*bv.z; acc[i][3] += a*bv.w;
            }
        }
#pragma unroll
        for (int i = 0; i < 2; i++)
            *(float4*)&S[(size_t)(ty*2+i)*1024 + t*64 + tx*4] =
                make_float4(acc[i][0], acc[i][1], acc[i][2], acc[i][3]);
        if (pf) {
            float* Kn = KV + ((t+1) & 1) * 2176;
            Kn[(dq0*4+0)*68 + kk0] = p0.x; Kn[(dq0*4+1)*68 + kk0] = p0.y;
            Kn[(dq0*4+2)*68 + kk0] = p0.z; Kn[(dq0*4+3)*68 + kk0] = p0.w;
            Kn[(dq0*4+0)*68 + kk0+32] = p1.x; Kn[(dq0*4+1)*68 + kk0+32] = p1.y;
            Kn[(dq0*4+2)*68 + kk0+32] = p1.z; Kn[(dq0*4+3)*68 + kk0+32] = p1.w;
        }
        __syncthreads();
    }

    {
        int warp = tid >> 5, lane = tid & 31;
#pragma unroll
        for (int rr = 0; rr < 4; rr++) {
            int row = warp * 4 + rr;
            float* Sr = S + (size_t)row * 1024;
            float m = -1e30f;
#pragma unroll
            for (int i = 0; i < 32; i++) m = fmaxf(m, Sr[lane + 32*i]);
#pragma unroll
            for (int o = 16; o > 0; o >>= 1)
                m = fmaxf(m, __shfl_xor_sync(0xffffffffu, m, o));
            float s = 0.f;
#pragma unroll
            for (int i = 0; i < 32; i++) {
                float e = __expf(Sr[lane + 32*i] - m);
                Sr[lane + 32*i] = e;
                s += e;
            }
#pragma unroll
            for (int o = 16; o > 0; o >>= 1)
                s += __shfl_xor_sync(0xffffffffu, s, o);
            if (lane == 0) inv[row] = 1.f / s;
        }
    }
    __syncthreads();

    {
        float a0 = 0.f, a1 = 0.f, a2 = 0.f, a3 = 0.f;
#pragma unroll
        for (int q = 0; q < 32; q++) {
            float iv = inv[q];
            const float* Sq = S + (size_t)q * 1024;
            a0 += Sq[tid      ] * iv;
            a1 += Sq[tid + 256] * iv;
            a2 += Sq[tid + 512] * iv;
            a3 += Sq[tid + 768] * iv;
        }
        float* gb = g + b * N1_;
        atomicAdd(&gb[tid      ], a0);
        atomicAdd(&gb[tid + 256], a1);
        atomicAdd(&gb[tid + 512], a2);
        atomicAdd(&gb[tid + 768], a3);
    }

    float* Vs = KV;
    int khalf = (tx >> 3) * 512;
    int dgrp  = (tx & 7) * 4;
    float av[2][4];
#pragma unroll
    for (int i = 0; i < 2; i++)
#pragma unroll
        for (int j = 0; j < 4; j++) av[i][j] = 0.f;

    for (int r = 0; r < 8; r++) {
        __syncthreads();
#pragma unroll
        for (int l = 0; l < 4; l++) {
            int idx = tid + l * 256;
            int vr = idx >> 3, dq = idx & 7;
            int key = (vr < 64) ? (r*64 + vr) : (512 + r*64 + (vr - 64));
            float4 v = *(const float4*)(Vg + (size_t)key * 256 + dq * 4);
            *(float4*)&Vs[vr*36 + dq*4] = v;
        }
        __syncthreads();
        int vbase = (tx >> 3) * 64;
#pragma unroll 4
        for (int kk = 0; kk < 64; kk++) {
            int kabs = khalf + r*64 + kk;
            float e0 = S[(size_t)(ty*2+0)*1024 + kabs];
            float e1 = S[(size_t)(ty*2+1)*1024 + kabs];
            float4 vv = *(const float4*)&Vs[(vbase + kk)*36 + dgrp];
            av[0][0] += e0*vv.x; av[0][1] += e0*vv.y; av[0][2] += e0*vv.z; av[0][3] += e0*vv.w;
            av[1][0] += e1*vv.x; av[1][1] += e1*vv.y; av[1][2] += e1*vv.z; av[1][3] += e1*vv.w;
        }
    }
#pragma unroll
    for (int i = 0; i < 2; i++)
#pragma unroll
        for (int j = 0; j < 4; j++)
            av[i][j] += __shfl_xor_sync(0xffffffffu, av[i][j], 8);

    if ((tid & 8) == 0) {
#pragma unroll
        for (int i = 0; i < 2; i++) {
            int q = ty*2 + i;
            float iv = inv[q];
            float4 o = make_float4(av[i][0]*iv, av[i][1]*iv, av[i][2]*iv, av[i][3]*iv);
            *(float4*)&cat[(size_t)(b*NTOK + q0 + q)*256 + h*32 + dgrp] = o;
        }
    }
}

// ---------------------------------------------------------------------------
__global__ void attn2_kernel(const float* __restrict__ proj)
{
    int win = blockIdx.x;
    int b = win >> 8, rem = win & 255, gy = rem >> 4, gx = rem & 15;
    int tid = threadIdx.x, h = tid >> 5, lane = tid & 31;

    __shared__ float Qs[4][16][32];
    __shared__ float Ks[4][16][32];
    __shared__ float Vs[4][16][32];
    __shared__ float csum[16];

    for (int i = lane; i < 16 * 32; i += 32) {
        int t = i >> 5, dd = i & 31;
        int n = (gy * 4 + (t >> 2)) * W_ + gx * 4 + (t & 3);
        const float* base = proj + (size_t)(b * NTOK + n) * 768;
        Qs[h][t][dd] = base[128 + h * 32 + dd];
        Ks[h][t][dd] = base[256 + h * 32 + dd];
        Vs[h][t][dd] = base[256 + 128 + h * 32 + dd];
    }
    if (tid < 16) csum[tid] = 0.f;
    __syncthreads();

    if (lane < 16) {
        int q = lane;
        float s[16];
        float mx = -1e30f;
#pragma unroll
        for (int m = 0; m < 16; m++) {
            float dot = 0.f;
#pragma unroll
            for (int dd = 0; dd < 32; dd++) dot += Qs[h][q][dd] * Ks[h][m][dd];
            s[m] = dot * ATT_SCALE;
            mx = fmaxf(mx, s[m]);
        }
        float sum = 0.f;
#pragma unroll
        for (int m = 0; m < 16; m++) { s[m] = __expf(s[m] - mx); sum += s[m]; }
        float iv = 1.f / sum;
#pragma unroll
        for (int m = 0; m < 16; m++) {
            s[m] *= iv;
            atomicAdd(&csum[m], s[m]);
        }
        int nq = (gy * 4 + (q >> 2)) * W_ + gx * 4 + (q & 3);
        float* outp = d_cat + (size_t)(b * NTOK + nq) * 256 + 128 + h * 32;
#pragma unroll
        for (int dd = 0; dd < 32; dd++) {
            float o = 0.f;
#pragma unroll
            for (int m = 0; m < 16; m++) o += s[m] * Vs[h][m][dd];
            outp[dd] = o;
        }
    }
    __syncthreads();
    if (tid < 16) {
        int m = tid;
        int np = (gy * 4 + (m >> 2)) * W_ + gx * 4 + (m & 3);
        d_lm[b * NTOK + np] = csum[m] * (1.f / 64.f);
    }
}

// ---------------------------------------------------------------------------
__global__ void lepe_add_kernel(const float* __restrict__ proj,
                                const float* __restrict__ w9,
                                const float* __restrict__ cb)
{
    int r = blockIdx.x;
    int c = threadIdx.x;
    int b = r >> 12, n = r & 4095, y = n >> 6, x = n & 63;
    float wv[9];
#pragma unroll
    for (int t = 0; t < 9; t++) wv[t] = w9[c * 9 + t];
    float acc = cb[c];
#pragma unroll
    for (int dy = 0; dy < 3; dy++) {
        int yy = y + dy - 1;
        if (yy < 0 || yy >= H_) continue;
#pragma unroll
        for (int dx = 0; dx < 3; dx++) {
            int xx = x + dx - 1;
            if (xx < 0 || xx >= W_) continue;
            acc += wv[dy * 3 + dx] *
                   proj[(size_t)(b * NTOK + yy * W_ + xx) * 768 + 512 + c];
        }
    }
    float v = d_cat[(size_t)r * C_ + c] + acc;
    __nv_bfloat16 h = __float2bfloat16(v);
    d_cath[(size_t)r * C_ + c] = h;
    d_catl[(size_t)r * C_ + c] = __float2bfloat16(v - __bfloat162float(h));
}

// ---------------------------------------------------------------------------
__global__ void mask_kernel(float* __restrict__ out)
{
    int idx = blockIdx.x * 256 + threadIdx.x;
    int b = idx >> 12, pos = idx & 4095, y = pos >> 6, x = pos & 63;
    float gv = d_g[b * N1_ + (y >> 1) * 32 + (x >> 1)] * (1.f / (NH2 * NTOK));
    float val = d_lm[idx] + gv;
    out[OUT_M1 + idx] = val;
    out[OUT_M2 + b * NTOK + x * 64 + y] = val;
}

// ---------------------------------------------------------------------------
extern "C" void kernel_launch(void* const* d_in, const int* in_sizes, int n_in,
                              void* d_out, int out_size)
{
    const float* x      = (const float*)d_in[0];
    const float* q1_w   = (const float*)d_in[1];
    const float* q1_b   = (const float*)d_in[2];
    const float* kv1_w  = (const float*)d_in[3];
    const float* kv1_b  = (const float*)d_in[4];
    const float* q2_w   = (const float*)d_in[5];
    const float* q2_b   = (const float*)d_in[6];
    const float* kv2_w  = (const float*)d_in[7];
    const float* kv2_b  = (const float*)d_in[8];
    const float* lepe_w = (const float*)d_in[9];
    const float* lepe_b = (const float*)d_in[10];
    const float* lcw    = (const float*)d_in[11];
    const float* lcb    = (const float*)d_in[12];
    const float* sr_w   = (const float*)d_in[13];
    const float* sr_b   = (const float*)d_in[14];
    const float* nw     = (const float*)d_in[15];
    const float* nb     = (const float*)d_in[16];
    const float* pw     = (const float*)d_in[17];
    const float* pb     = (const float*)d_in[18];
    float* out = (float*)d_out;

    void* p;
    float *projp, *kv1p, *catp, *gp, *xsraw, *bcat;
    __nv_bfloat16 *xh, *xl, *wcath, *wcatl, *w2h, *w2l, *srwh, *srwl;
    __nv_bfloat16 *agh, *agl, *xsh, *xsl, *cath, *catl;
    cudaGetSymbolAddress(&p, d_proj);  projp = (float*)p;
    cudaGetSymbolAddress(&p, d_kv1);   kv1p  = (float*)p;
    cudaGetSymbolAddress(&p, d_cat);   catp  = (float*)p;
    cudaGetSymbolAddress(&p, d_g);     gp    = (float*)p;
    cudaGetSymbolAddress(&p, d_xsraw); xsraw = (float*)p;
    cudaGetSymbolAddress(&p, d_bcat);  bcat  = (float*)p;
    cudaGetSymbolAddress(&p, d_xh);    xh    = (__nv_bfloat16*)p;
    cudaGetSymbolAddress(&p, d_xl);    xl    = (__nv_bfloat16*)p;
    cudaGetSymbolAddress(&p, d_wcath); wcath = (__nv_bfloat16*)p;
    cudaGetSymbolAddress(&p, d_wcatl); wcatl = (__nv_bfloat16*)p;
    cudaGetSymbolAddress(&p, d_w2h);   w2h   = (__nv_bfloat16*)p;
    cudaGetSymbolAddress(&p, d_w2l);   w2l   = (__nv_bfloat16*)p;
    cudaGetSymbolAddress(&p, d_srwh);  srwh  = (__nv_bfloat16*)p;
    cudaGetSymbolAddress(&p, d_srwl);  srwl  = (__nv_bfloat16*)p;
    cudaGetSymbolAddress(&p, d_agh);   agh   = (__nv_bfloat16*)p;
    cudaGetSymbolAddress(&p, d_agl);   agl   = (__nv_bfloat16*)p;
    cudaGetSymbolAddress(&p, d_xsh);   xsh   = (__nv_bfloat16*)p;
    cudaGetSymbolAddress(&p, d_xsl);   xsl   = (__nv_bfloat16*)p;
    cudaGetSymbolAddress(&p, d_cath);  cath  = (__nv_bfloat16*)p;
    cudaGetSymbolAddress(&p, d_catl);  catl  = (__nv_bfloat16*)p;

    const int ATTN_SMEM = (32*1024 + 32*33 + 32 + 4608) * 4;  // 153856 B
    cudaFuncSetAttribute(attn1_fused,
                         cudaFuncAttributeMaxDynamicSharedMemorySize, ATTN_SMEM);
    cudaFuncSetAttribute(gemm2,
                         cudaFuncAttributeMaxDynamicSharedMemorySize, GEMM2_SMEM);

    const size_t XS_STRIDE = (size_t)B_ * N1_ * C_;

    // 1: all prep
    prep_all<<<10512, 256>>>(x, q1_w, q2_w, kv2_w, lepe_w,
                             q1_b, q2_b, kv2_b, lepe_b, kv1_w, pw, sr_w);

    // 2: sr conv GEMM, split-K x4 into partial slabs
    gemm2<<<dim3(2, 32, 4), 256, GEMM2_SMEM>>>(agh, agl, 1024, srwh, srwl, 256,
                                               (const float*)0, xsraw, 256,
                                               XS_STRIDE, 256, 1.f);
    // 3: LN+GELU (sums 4 partials + sr_b) -> split bf16
    ln_gelu_kernel<<<B_ * N1_, 256>>>(nw, nb, sr_b);

    // 4: fused x-projections -> d_proj [tok][768]   (ncu profiles this)
    gemm2<<<dim3(6, 128, 1), 256, GEMM2_SMEM>>>(xh, xl, 256, wcath, wcatl, 768,
                                                bcat, projp, 768, 0, 256, 1.f);

    // 5: kv1 GEMM
    gemm2<<<dim3(2, 32, 1), 256, GEMM2_SMEM>>>(xsh, xsl, 256, w2h, w2l, 256,
                                               kv1_b, kv1p, 256, 0, 256, 1.f);

    // 6: fused branch-1 attention
    attn1_fused<<<dim3(128, 16), 256, ATTN_SMEM>>>(projp, kv1p, catp, gp);

    // 7-8: branch 2 + lepe/cat split
    attn2_kernel<<<B_ * 16 * 16, 128>>>(projp);
    lepe_add_kernel<<<B_ * NTOK, 256>>>(projp, lcw, lcb);

    // 9: final projection: out = 2*(cat @ proj_w + proj_b)
    gemm2<<<dim3(2, 128, 1), 256, GEMM2_SMEM>>>(cath, catl, 256,
                                                w2h + 65536, w2l + 65536, 256,
                                                pb, out, 256, 0, 256, 2.f);
    // 10: masks
    mask_kernel<<<64, 256>>>(out);
}

// round 11
// speedup vs baseline: 4.4400x; 1.0265x over previous
#include <cuda_runtime.h>
#include <cuda_bf16.h>
#include <math.h>
#include <stdint.h>

#define B_    4
#define NTOK  4096
#define C_    256
#define H_    64
#define W_    64
#define NH2   4
#define N1_   1024

#define OUT_MAIN (B_*NTOK*C_)
#define OUT_M1   (OUT_MAIN)
#define OUT_M2   (OUT_MAIN + B_*NTOK)

// fp32 intermediates
static __device__ float d_proj[B_*NTOK*768];   // [q1|q2|kv2|lepe]
static __device__ float d_xsraw[4*B_*N1_*C_];  // 4 split-K partials
static __device__ float d_kv1[B_*N1_*C_];
static __device__ float d_cat[B_*NTOK*C_];
static __device__ float d_g[B_*N1_];
static __device__ float d_lm[B_*NTOK];
static __device__ float d_bcat[768];

// bf16 split buffers
static __device__ __nv_bfloat16 d_xh[B_*NTOK*C_],   d_xl[B_*NTOK*C_];
static __device__ __nv_bfloat16 d_wcath[256*768],   d_wcatl[256*768];
static __device__ __nv_bfloat16 d_w2h[131072],      d_w2l[131072];   // kv1 | proj
static __device__ __nv_bfloat16 d_srwh[1024*C_],    d_srwl[1024*C_];
static __device__ __nv_bfloat16 d_agh[4096*1024],   d_agl[4096*1024];
static __device__ __nv_bfloat16 d_xsh[B_*N1_*C_],   d_xsl[B_*N1_*C_];
static __device__ __nv_bfloat16 d_cath[B_*NTOK*C_], d_catl[B_*NTOK*C_];

__device__ __constant__ float ATT_SCALE = 0.17677669529663687f; // 1/sqrt(32)

#define MMA_BF16(c, a, b) \
  asm volatile("mma.sync.aligned.m16n8k16.row.col.f32.bf16.bf16.f32 " \
    "{%0,%1,%2,%3}, {%4,%5,%6,%7}, {%8,%9}, {%0,%1,%2,%3};" \
    : "+f"((c)[0]), "+f"((c)[1]), "+f"((c)[2]), "+f"((c)[3]) \
    : "r"((a)[0]), "r"((a)[1]), "r"((a)[2]), "r"((a)[3]), \
      "r"((b)[0]), "r"((b)[1]))

#define LDSM_X4(r, addr) \
  asm volatile("ldmatrix.sync.aligned.m8n8.x4.shared.b16 {%0,%1,%2,%3}, [%4];" \
    : "=r"((r)[0]), "=r"((r)[1]), "=r"((r)[2]), "=r"((r)[3]) : "r"(addr))

#define LDSM_X4T(r, addr) \
  asm volatile("ldmatrix.sync.aligned.m8n8.x4.trans.shared.b16 {%0,%1,%2,%3}, [%4];" \
    : "=r"((r)[0]), "=r"((r)[1]), "=r"((r)[2]), "=r"((r)[3]) : "r"(addr))

__device__ __forceinline__ void cpa16(uint32_t saddr, const void* g) {
    asm volatile("cp.async.ca.shared.global [%0], [%1], 16;"
                 :: "r"(saddr), "l"(g));
}

// ---------------------------------------------------------------------------
// gemm2: bf16-split GEMM, 128x128 block tile, ldmatrix fragments,
// cp.async double-buffered, 2 CTAs/SM (A-frags loaded per-mt to cut regs).
// 8 warps = 2(m) x 4(n) of 64x32 warp tiles.
// ---------------------------------------------------------------------------
#define GEMM2_SMEM 75776
__global__ void __launch_bounds__(256, 2) gemm2(
    const __nv_bfloat16* __restrict__ Ah, const __nv_bfloat16* __restrict__ Al, int lda,
    const __nv_bfloat16* __restrict__ Bh, const __nv_bfloat16* __restrict__ Bl, int ldb,
    const float* __restrict__ bias, float* __restrict__ Cm, int ldc,
    size_t cstride, int K, float alpha)
{
    extern __shared__ uint16_t sm16[];
    uint32_t sb = (uint32_t)__cvta_generic_to_shared(sm16);
    const uint32_t AHo = 0, ALo = 20480, BHo = 40960, BLo = 58368;

    int tid = threadIdx.x, lane = tid & 31, warp = tid >> 5;
    int wm = warp >> 2, wn = warp & 3;
    int m0 = blockIdx.y * 128, n0 = blockIdx.x * 128;
    int kz = blockIdx.z;
    int g = lane >> 2, t = lane & 3;

    const __nv_bfloat16* Ahp = Ah + (size_t)kz * K;
    const __nv_bfloat16* Alp = Al + (size_t)kz * K;
    const __nv_bfloat16* Bhp = Bh + (size_t)kz * K * ldb;
    const __nv_bfloat16* Blp = Bl + (size_t)kz * K * ldb;

    float acc[4][4][4];
#pragma unroll
    for (int i = 0; i < 4; i++)
#pragma unroll
        for (int j = 0; j < 4; j++)
#pragma unroll
            for (int c = 0; c < 4; c++) acc[i][j][c] = 0.f;

    int av = tid;
    int arow0 = av >> 2, aseg0 = av & 3;
    int arow1 = (av + 256) >> 2, aseg1 = (av + 256) & 3;
    int brow0 = av >> 4, bseg0 = av & 15;
    int brow1 = (av + 256) >> 4, bseg1 = (av + 256) & 15;

#define LOAD_CHUNK(bi, k0) do { \
    uint32_t aB = sb + (bi)*10240; \
    uint32_t bB = sb + (bi)*8704; \
    cpa16(aB + AHo + (uint32_t)((arow0*40 + aseg0*8)*2), Ahp + (size_t)(m0+arow0)*lda + (k0) + aseg0*8); \
    cpa16(aB + AHo + (uint32_t)((arow1*40 + aseg1*8)*2), Ahp + (size_t)(m0+arow1)*lda + (k0) + aseg1*8); \
    cpa16(aB + ALo + (uint32_t)((arow0*40 + aseg0*8)*2), Alp + (size_t)(m0+arow0)*lda + (k0) + aseg0*8); \
    cpa16(aB + ALo + (uint32_t)((arow1*40 + aseg1*8)*2), Alp + (size_t)(m0+arow1)*lda + (k0) + aseg1*8); \
    cpa16(bB + BHo + (uint32_t)((brow0*136 + bseg0*8)*2), Bhp + (size_t)((k0)+brow0)*ldb + n0 + bseg0*8); \
    cpa16(bB + BHo + (uint32_t)((brow1*136 + bseg1*8)*2), Bhp + (size_t)((k0)+brow1)*ldb + n0 + bseg1*8); \
    cpa16(bB + BLo + (uint32_t)((brow0*136 + bseg0*8)*2), Blp + (size_t)((k0)+brow0)*ldb + n0 + bseg0*8); \
    cpa16(bB + BLo + (uint32_t)((brow1*136 + bseg1*8)*2), Blp + (size_t)((k0)+brow1)*ldb + n0 + bseg1*8); \
    asm volatile("cp.async.commit_group;" ::: "memory"); \
} while (0)

    LOAD_CHUNK(0, 0);

    uint32_t aoff = (uint32_t)(((wm*64 + (lane & 15))*40 + (lane >> 4)*8) * 2);
    uint32_t boff = (uint32_t)(((lane & 15)*136 + wn*32 + (lane >> 4)*8) * 2);

    int nch = K >> 5;
    for (int c = 0; c < nch; c++) {
        int bi = c & 1;
        if (c + 1 < nch) {
            LOAD_CHUNK(bi ^ 1, (c + 1) << 5);
            asm volatile("cp.async.wait_group 1;" ::: "memory");
        } else {
            asm volatile("cp.async.wait_group 0;" ::: "memory");
        }
        __syncthreads();

        uint32_t aH = sb + AHo + bi*10240 + aoff;
        uint32_t aL = sb + ALo + bi*10240 + aoff;
        uint32_t bH = sb + BHo + bi*8704 + boff;
        uint32_t bL = sb + BLo + bi*8704 + boff;
#pragma unroll
        for (int kk = 0; kk < 32; kk += 16) {
            uint32_t bfh[4][2], bfl[4][2];
#pragma unroll
            for (int jj = 0; jj < 2; jj++) {
                uint32_t r[4];
                LDSM_X4T(r, bH + kk*272 + jj*32);
                bfh[2*jj][0] = r[0]; bfh[2*jj][1] = r[1];
                bfh[2*jj+1][0] = r[2]; bfh[2*jj+1][1] = r[3];
                LDSM_X4T(r, bL + kk*272 + jj*32);
                bfl[2*jj][0] = r[0]; bfl[2*jj][1] = r[1];
                bfl[2*jj+1][0] = r[2]; bfl[2*jj+1][1] = r[3];
            }
#pragma unroll
            for (int mt = 0; mt < 4; mt++) {
                uint32_t afh[4], afl[4];
                LDSM_X4(afh, aH + mt*1280 + kk*2);
                LDSM_X4(afl, aL + mt*1280 + kk*2);
#pragma unroll
                for (int nj = 0; nj < 4; nj++) {
                    MMA_BF16(acc[mt][nj], afh, bfh[nj]);
                    MMA_BF16(acc[mt][nj], afl, bfh[nj]);
                    MMA_BF16(acc[mt][nj], afh, bfl[nj]);
                }
            }
        }
        __syncthreads();
    }

    float* Co = Cm + (size_t)kz * cstride;
    if (bias) {
#pragma unroll
        for (int mt = 0; mt < 4; mt++)
#pragma unroll
            for (int nj = 0; nj < 4; nj++) {
                int row = m0 + wm*64 + mt*16 + g;
                int col = n0 + wn*32 + nj*8 + t*2;
                float b0 = bias[col], b1 = bias[col+1];
                *(float2*)(Co + (size_t)row*ldc + col) =
                    make_float2(alpha*(acc[mt][nj][0]+b0), alpha*(acc[mt][nj][1]+b1));
                *(float2*)(Co + (size_t)(row+8)*ldc + col) =
                    make_float2(alpha*(acc[mt][nj][2]+b0), alpha*(acc[mt][nj][3]+b1));
            }
    } else {
#pragma unroll
        for (int mt = 0; mt < 4; mt++)
#pragma unroll
            for (int nj = 0; nj < 4; nj++) {
                int row = m0 + wm*64 + mt*16 + g;
                int col = n0 + wn*32 + nj*8 + t*2;
                *(float2*)(Co + (size_t)row*ldc + col) =
                    make_float2(acc[mt][nj][0], acc[mt][nj][1]);
                *(float2*)(Co + (size_t)(row+8)*ldc + col) =
                    make_float2(acc[mt][nj][2], acc[mt][nj][3]);
            }
    }
#undef LOAD_CHUNK
}

// ---------------------------------------------------------------------------
// One merged prep kernel.  Grid 10512.
// ---------------------------------------------------------------------------
__global__ void prep_all(
    const float* __restrict__ x,
    const float* __restrict__ q1w, const float* __restrict__ q2w,
    const float* __restrict__ kv2w, const float* __restrict__ lepw,
    const float* __restrict__ q1b, const float* __restrict__ q2b,
    const float* __restrict__ kv2b, const float* __restrict__ lepb,
    const float* __restrict__ kv1w, const float* __restrict__ projw,
    const float* __restrict__ srw)
{
    int blk = blockIdx.x, tid = threadIdx.x;
    if (blk < 4096) {
        int i = blk * 256 + tid;
        float4 v = ((const float4*)x)[i];
        __nv_bfloat16 h0 = __float2bfloat16(v.x), h1 = __float2bfloat16(v.y);
        __nv_bfloat16 h2 = __float2bfloat16(v.z), h3 = __float2bfloat16(v.w);
        __nv_bfloat16 l0 = __float2bfloat16(v.x - __bfloat162float(h0));
        __nv_bfloat16 l1 = __float2bfloat16(v.y - __bfloat162float(h1));
        __nv_bfloat16 l2 = __float2bfloat16(v.z - __bfloat162float(h2));
        __nv_bfloat16 l3 = __float2bfloat16(v.w - __bfloat162float(h3));
        ((__nv_bfloat162*)d_xh)[i*2]   = __nv_bfloat162(h0, h1);
        ((__nv_bfloat162*)d_xh)[i*2+1] = __nv_bfloat162(h2, h3);
        ((__nv_bfloat162*)d_xl)[i*2]   = __nv_bfloat162(l0, l1);
        ((__nv_bfloat162*)d_xl)[i*2+1] = __nv_bfloat162(l2, l3);
    } else if (blk < 8192) {
        int v = (blk - 4096) * 256 + tid;
        int r = v >> 8, col4 = v & 255;
        int k = col4 * 4;
        int dd = k >> 8, ci = k & 255;
        int b = r >> 10, p = r & 1023;
        int ii = p >> 5, jj = p & 31;
        int di = dd >> 1, dj = dd & 1;
        int n = (2*ii + di) * W_ + 2*jj + dj;
        float4 xv = *(const float4*)(x + (size_t)(b * NTOK + n) * C_ + ci);
        __nv_bfloat16 h0 = __float2bfloat16(xv.x), h1 = __float2bfloat16(xv.y);
        __nv_bfloat16 h2 = __float2bfloat16(xv.z), h3 = __float2bfloat16(xv.w);
        __nv_bfloat16 l0 = __float2bfloat16(xv.x - __bfloat162float(h0));
        __nv_bfloat16 l1 = __float2bfloat16(xv.y - __bfloat162float(h1));
        __nv_bfloat16 l2 = __float2bfloat16(xv.z - __bfloat162float(h2));
        __nv_bfloat16 l3 = __float2bfloat16(xv.w - __bfloat162float(h3));
        size_t o = ((size_t)r * 1024 + k) >> 1;
        ((__nv_bfloat162*)d_agh)[o]   = __nv_bfloat162(h0, h1);
        ((__nv_bfloat162*)d_agh)[o+1] = __nv_bfloat162(h2, h3);
        ((__nv_bfloat162*)d_agl)[o]   = __nv_bfloat162(l0, l1);
        ((__nv_bfloat162*)d_agl)[o+1] = __nv_bfloat162(l2, l3);
    } else if (blk < 8960) {
        int idx = (blk - 8192) * 256 + tid;
        int k = idx / 768, col = idx - k * 768;
        float v;
        if (col < 128)       v = q1w[k*128 + col];
        else if (col < 256)  v = q2w[k*128 + col - 128];
        else if (col < 512)  v = kv2w[k*256 + col - 256];
        else                 v = lepw[k*256 + col - 512];
        __nv_bfloat16 h = __float2bfloat16(v);
        d_wcath[idx] = h;
        d_wcatl[idx] = __float2bfloat16(v - __bfloat162float(h));
        if (idx < 768) {
            float b = (idx < 128) ? q1b[idx] : (idx < 256) ? q2b[idx-128]
                    : (idx < 512) ? kv2b[idx-256] : lepb[idx-512];
            d_bcat[idx] = b;
        }
    } else if (blk < 10496) {
        int idx = (blk - 8960) * 256 + tid;
        float v;
        if (idx < 65536) {
            v = kv1w[idx];
            __nv_bfloat16 h = __float2bfloat16(v);
            d_w2h[idx] = h; d_w2l[idx] = __float2bfloat16(v - __bfloat162float(h));
        } else if (idx < 131072) {
            v = projw[idx - 65536];
            __nv_bfloat16 h = __float2bfloat16(v);
            d_w2h[idx] = h; d_w2l[idx] = __float2bfloat16(v - __bfloat162float(h));
        } else {
            int i = idx - 131072;
            int co = i & 255, kk = i >> 8;
            int dd = kk >> 8, ci = kk & 255;
            v = srw[co * 1024 + ci * 4 + dd];
            __nv_bfloat16 h = __float2bfloat16(v);
            d_srwh[i] = h; d_srwl[i] = __float2bfloat16(v - __bfloat162float(h));
        }
    } else {
        int i = (blk - 10496) * 256 + tid;
        if (i < B_ * N1_) d_g[i] = 0.f;
    }
}

// ---------------------------------------------------------------------------
__global__ void ln_gelu_kernel(const float* __restrict__ nw,
                               const float* __restrict__ nb,
                               const float* __restrict__ srb)
{
    __shared__ float sh[8];
    int r = blockIdx.x, c = threadIdx.x;
    size_t o = (size_t)r * C_ + c;
    const size_t P = (size_t)B_ * N1_ * C_;
    float v = d_xsraw[o] + d_xsraw[o + P] + d_xsraw[o + 2*P] + d_xsraw[o + 3*P]
            + srb[c];

    float s = v;
#pragma unroll
    for (int o2 = 16; o2 > 0; o2 >>= 1) s += __shfl_xor_sync(0xffffffffu, s, o2);
    if ((c & 31) == 0) sh[c >> 5] = s;
    __syncthreads();
    if (c < 32) {
        float t = (c < 8) ? sh[c] : 0.f;
#pragma unroll
        for (int o2 = 4; o2 > 0; o2 >>= 1) t += __shfl_xor_sync(0xffffffffu, t, o2);
        if (c == 0) sh[0] = t;
    }
    __syncthreads();
    float mean = sh[0] * (1.f / 256.f);
    __syncthreads();

    float dv = v - mean;
    float q = dv * dv;
#pragma unroll
    for (int o2 = 16; o2 > 0; o2 >>= 1) q += __shfl_xor_sync(0xffffffffu, q, o2);
    if ((c & 31) == 0) sh[c >> 5] = q;
    __syncthreads();
    if (c < 32) {
        float t = (c < 8) ? sh[c] : 0.f;
#pragma unroll
        for (int o2 = 4; o2 > 0; o2 >>= 1) t += __shfl_xor_sync(0xffffffffu, t, o2);
        if (c == 0) sh[0] = t;
    }
    __syncthreads();
    float var = sh[0] * (1.f / 256.f);

    float y = dv * rsqrtf(var + 1e-5f) * nw[c] + nb[c];
    float ge = 0.5f * y * (1.f + erff(y * 0.70710678118654752f));
    __nv_bfloat16 h = __float2bfloat16(ge);
    d_xsh[o] = h;
    d_xsl[o] = __float2bfloat16(ge - __bfloat162float(h));
}

// ---------------------------------------------------------------------------
// Fused branch-1 attention (unchanged).
// ---------------------------------------------------------------------------
__global__ void __launch_bounds__(256) attn1_fused(
    const float* __restrict__ proj, const float* __restrict__ kv1,
    float* __restrict__ cat, float* __restrict__ g)
{
    extern __shared__ float sm[];
    float* S   = sm;
    float* Qs  = sm + 32*1024;
    float* inv = Qs + 32*33;
    float* KV  = inv + 32;

    int tid = threadIdx.x, tx = tid & 15, ty = tid >> 4;
    int bh = blockIdx.y; int b = bh >> 2, h = bh & 3;
    int q0 = blockIdx.x * 32;

    const float* Qg = proj + (size_t)(b * NTOK + q0) * 768 + h * 32;
    const float* Kg = kv1 + (size_t)b * N1_ * 256 + h * 32;
    const float* Vg = Kg + 128;

    {
        int qq = tid >> 3, dq = tid & 7;
        float4 v = *(const float4*)(Qg + (size_t)qq * 768 + dq * 4);
        Qs[qq*33 + dq*4+0] = v.x; Qs[qq*33 + dq*4+1] = v.y;
        Qs[qq*33 + dq*4+2] = v.z; Qs[qq*33 + dq*4+3] = v.w;
    }
    {
        int kk = tid >> 3, dq = tid & 7;
        float4 v0 = *(const float4*)(Kg + (size_t)kk * 256 + dq * 4);
        float4 v1 = *(const float4*)(Kg + (size_t)(kk+32) * 256 + dq * 4);
        float* Kb = KV;
        Kb[(dq*4+0)*68 + kk] = v0.x; Kb[(dq*4+1)*68 + kk] = v0.y;
        Kb[(dq*4+2)*68 + kk] = v0.z; Kb[(dq*4+3)*68 + kk] = v0.w;
        Kb[(dq*4+0)*68 + kk+32] = v1.x; Kb[(dq*4+1)*68 + kk+32] = v1.y;
        Kb[(dq*4+2)*68 + kk+32] = v1.z; Kb[(dq*4+3)*68 + kk+32] = v1.w;
    }
    __syncthreads();

    float sc = ATT_SCALE;
    float qr[2][32];
#pragma unroll
    for (int i = 0; i < 2; i++)
#pragma unroll
        for (int d = 0; d < 32; d++)
            qr[i][d] = Qs[(ty*2+i)*33 + d] * sc;

    int kk0 = tid >> 3, dq0 = tid & 7;
    for (int t = 0; t < 16; t++) {
        float4 p0, p1;
        bool pf = (t < 15);
        if (pf) {
            const float* src = Kg + (size_t)((t+1)*64) * 256;
            p0 = *(const float4*)(src + (size_t)kk0 * 256 + dq0 * 4);
            p1 = *(const float4*)(src + (size_t)(kk0+32) * 256 + dq0 * 4);
        }
        const float* Kb = KV + (t & 1) * 2176;
        float acc[2][4];
#pragma unroll
        for (int i = 0; i < 2; i++)
#pragma unroll
            for (int j = 0; j < 4; j++) acc[i][j] = 0.f;
#pragma unroll
        for (int d = 0; d < 32; d++) {
            float4 bv = *(const float4*)&Kb[d*68 + tx*4];
#pragma unroll
            for (int i = 0; i < 2; i++) {
                float a = qr[i][d];
                acc[i][0] += a*bv.x; acc[i][1] += a*bv.y;
                acc[i][2] += a*bv.z; acc[i][3] += a*bv.w;
            }
        }
#pragma unroll
        for (int i = 0; i < 2; i++)
            *(float4*)&S[(size_t)(ty*2+i)*1024 + t*64 + tx*4] =
                make_float4(acc[i][0], acc[i][1], acc[i][2], acc[i][3]);
        if (pf) {
            float* Kn = KV + ((t+1) & 1) * 2176;
            Kn[(dq0*4+0)*68 + kk0] = p0.x; Kn[(dq0*4+1)*68 + kk0] = p0.y;
            Kn[(dq0*4+2)*68 + kk0] = p0.z; Kn[(dq0*4+3)*68 + kk0] = p0.w;
            Kn[(dq0*4+0)*68 + kk0+32] = p1.x; Kn[(dq0*4+1)*68 + kk0+32] = p1.y;
            Kn[(dq0*4+2)*68 + kk0+32] = p1.z; Kn[(dq0*4+3)*68 + kk0+32] = p1.w;
        }
        __syncthreads();
    }

    {
        int warp = tid >> 5, lane = tid & 31;
#pragma unroll
        for (int rr = 0; rr < 4; rr++) {
            int row = warp * 4 + rr;
            float* Sr = S + (size_t)row * 1024;
            float m = -1e30f;
#pragma unroll
            for (int i = 0; i < 32; i++) m = fmaxf(m, Sr[lane + 32*i]);
#pragma unroll
            for (int o = 16; o > 0; o >>= 1)
                m = fmaxf(m, __shfl_xor_sync(0xffffffffu, m, o));
            float s = 0.f;
#pragma unroll
            for (int i = 0; i < 32; i++) {
                float e = __expf(Sr[lane + 32*i] - m);
                Sr[lane + 32*i] = e;
                s += e;
            }
#pragma unroll
            for (int o = 16; o > 0; o >>= 1)
                s += __shfl_xor_sync(0xffffffffu, s, o);
            if (lane == 0) inv[row] = 1.f / s;
        }
    }
    __syncthreads();

    {
        float a0 = 0.f, a1 = 0.f, a2 = 0.f, a3 = 0.f;
#pragma unroll
        for (int q = 0; q < 32; q++) {
            float iv = inv[q];
            const float* Sq = S + (size_t)q * 1024;
            a0 += Sq[tid      ] * iv;
            a1 += Sq[tid + 256] * iv;
            a2 += Sq[tid + 512] * iv;
            a3 += Sq[tid + 768] * iv;
        }
        float* gb = g + b * N1_;
        atomicAdd(&gb[tid      ], a0);
        atomicAdd(&gb[tid + 256], a1);
        atomicAdd(&gb[tid + 512], a2);
        atomicAdd(&gb[tid + 768], a3);
    }

    float* Vs = KV;
    int khalf = (tx >> 3) * 512;
    int dgrp  = (tx & 7) * 4;
    float av[2][4];
#pragma unroll
    for (int i = 0; i < 2; i++)
#pragma unroll
        for (int j = 0; j < 4; j++) av[i][j] = 0.f;

    for (int r = 0; r < 8; r++) {
        __syncthreads();
#pragma unroll
        for (int l = 0; l < 4; l++) {
            int idx = tid + l * 256;
            int vr = idx >> 3, dq = idx & 7;
            int key = (vr < 64) ? (r*64 + vr) : (512 + r*64 + (vr - 64));
            float4 v = *(const float4*)(Vg + (size_t)key * 256 + dq * 4);
            *(float4*)&Vs[vr*36 + dq*4] = v;
        }
        __syncthreads();
        int vbase = (tx >> 3) * 64;
#pragma unroll 4
        for (int kk = 0; kk < 64; kk++) {
            int kabs = khalf + r*64 + kk;
            float e0 = S[(size_t)(ty*2+0)*1024 + kabs];
            float e1 = S[(size_t)(ty*2+1)*1024 + kabs];
            float4 vv = *(const float4*)&Vs[(vbase + kk)*36 + dgrp];
            av[0][0] += e0*vv.x; av[0][1] += e0*vv.y; av[0][2] += e0*vv.z; av[0][3] += e0*vv.w;
            av[1][0] += e1*vv.x; av[1][1] += e1*vv.y; av[1][2] += e1*vv.z; av[1][3] += e1*vv.w;
        }
    }
#pragma unroll
    for (int i = 0; i < 2; i++)
#pragma unroll
        for (int j = 0; j < 4; j++)
            av[i][j] += __shfl_xor_sync(0xffffffffu, av[i][j], 8);

    if ((tid & 8) == 0) {
#pragma unroll
        for (int i = 0; i < 2; i++) {
            int q = ty*2 + i;
            float iv = inv[q];
            float4 o = make_float4(av[i][0]*iv, av[i][1]*iv, av[i][2]*iv, av[i][3]*iv);
            *(float4*)&cat[(size_t)(b*NTOK + q0 + q)*256 + h*32 + dgrp] = o;
        }
    }
}

// ---------------------------------------------------------------------------
__global__ void attn2_kernel(const float* __restrict__ proj)
{
    int win = blockIdx.x;
    int b = win >> 8, rem = win & 255, gy = rem >> 4, gx = rem & 15;
    int tid = threadIdx.x, h = tid >> 5, lane = tid & 31;

    __shared__ float Qs[4][16][32];
    __shared__ float Ks[4][16][32];
    __shared__ float Vs[4][16][32];
    __shared__ float csum[16];

    for (int i = lane; i < 16 * 32; i += 32) {
        int t = i >> 5, dd = i & 31;
        int n = (gy * 4 + (t >> 2)) * W_ + gx * 4 + (t & 3);
        const float* base = proj + (size_t)(b * NTOK + n) * 768;
        Qs[h][t][dd] = base[128 + h * 32 + dd];
        Ks[h][t][dd] = base[256 + h * 32 + dd];
        Vs[h][t][dd] = base[256 + 128 + h * 32 + dd];
    }
    if (tid < 16) csum[tid] = 0.f;
    __syncthreads();

    if (lane < 16) {
        int q = lane;
        float s[16];
        float mx = -1e30f;
#pragma unroll
        for (int m = 0; m < 16; m++) {
            float dot = 0.f;
#pragma unroll
            for (int dd = 0; dd < 32; dd++) dot += Qs[h][q][dd] * Ks[h][m][dd];
            s[m] = dot * ATT_SCALE;
            mx = fmaxf(mx, s[m]);
        }
        float sum = 0.f;
#pragma unroll
        for (int m = 0; m < 16; m++) { s[m] = __expf(s[m] - mx); sum += s[m]; }
        float iv = 1.f / sum;
#pragma unroll
        for (int m = 0; m < 16; m++) {
            s[m] *= iv;
            atomicAdd(&csum[m], s[m]);
        }
        int nq = (gy * 4 + (q >> 2)) * W_ + gx * 4 + (q & 3);
        float* outp = d_cat + (size_t)(b * NTOK + nq) * 256 + 128 + h * 32;
#pragma unroll
        for (int dd = 0; dd < 32; dd++) {
            float o = 0.f;
#pragma unroll
            for (int m = 0; m < 16; m++) o += s[m] * Vs[h][m][dd];
            outp[dd] = o;
        }
    }
    __syncthreads();
    if (tid < 16) {
        int m = tid;
        int np = (gy * 4 + (m >> 2)) * W_ + gx * 4 + (m & 3);
        d_lm[b * NTOK + np] = csum[m] * (1.f / 64.f);
    }
}

// ---------------------------------------------------------------------------
__global__ void lepe_add_kernel(const float* __restrict__ proj,
                                const float* __restrict__ w9,
                                const float* __restrict__ cb)
{
    int r = blockIdx.x;
    int c = threadIdx.x;
    int b = r >> 12, n = r & 4095, y = n >> 6, x = n & 63;
    float wv[9];
#pragma unroll
    for (int t = 0; t < 9; t++) wv[t] = w9[c * 9 + t];
    float acc = cb[c];
#pragma unroll
    for (int dy = 0; dy < 3; dy++) {
        int yy = y + dy - 1;
        if (yy < 0 || yy >= H_) continue;
#pragma unroll
        for (int dx = 0; dx < 3; dx++) {
            int xx = x + dx - 1;
            if (xx < 0 || xx >= W_) continue;
            acc += wv[dy * 3 + dx] *
                   proj[(size_t)(b * NTOK + yy * W_ + xx) * 768 + 512 + c];
        }
    }
    float v = d_cat[(size_t)r * C_ + c] + acc;
    __nv_bfloat16 h = __float2bfloat16(v);
    d_cath[(size_t)r * C_ + c] = h;
    d_catl[(size_t)r * C_ + c] = __float2bfloat16(v - __bfloat162float(h));
}

// ---------------------------------------------------------------------------
__global__ void mask_kernel(float* __restrict__ out)
{
    int idx = blockIdx.x * 256 + threadIdx.x;
    int b = idx >> 12, pos = idx & 4095, y = pos >> 6, x = pos & 63;
    float gv = d_g[b * N1_ + (y >> 1) * 32 + (x >> 1)] * (1.f / (NH2 * NTOK));
    float val = d_lm[idx] + gv;
    out[OUT_M1 + idx] = val;
    out[OUT_M2 + b * NTOK + x * 64 + y] = val;
}

// ---------------------------------------------------------------------------
extern "C" void kernel_launch(void* const* d_in, const int* in_sizes, int n_in,
                              void* d_out, int out_size)
{
    const float* x      = (const float*)d_in[0];
    const float* q1_w   = (const float*)d_in[1];
    const float* q1_b   = (const float*)d_in[2];
    const float* kv1_w  = (const float*)d_in[3];
    const float* kv1_b  = (const float*)d_in[4];
    const float* q2_w   = (const float*)d_in[5];
    const float* q2_b   = (const float*)d_in[6];
    const float* kv2_w  = (const float*)d_in[7];
    const float* kv2_b  = (const float*)d_in[8];
    const float* lepe_w = (const float*)d_in[9];
    const float* lepe_b = (const float*)d_in[10];
    const float* lcw    = (const float*)d_in[11];
    const float* lcb    = (const float*)d_in[12];
    const float* sr_w   = (const float*)d_in[13];
    const float* sr_b   = (const float*)d_in[14];
    const float* nw     = (const float*)d_in[15];
    const float* nb     = (const float*)d_in[16];
    const float* pw     = (const float*)d_in[17];
    const float* pb     = (const float*)d_in[18];
    float* out = (float*)d_out;

    void* p;
    float *projp, *kv1p, *catp, *gp, *xsraw, *bcat;
    __nv_bfloat16 *xh, *xl, *wcath, *wcatl, *w2h, *w2l, *srwh, *srwl;
    __nv_bfloat16 *agh, *agl, *xsh, *xsl, *cath, *catl;
    cudaGetSymbolAddress(&p, d_proj);  projp = (float*)p;
    cudaGetSymbolAddress(&p, d_kv1);   kv1p  = (float*)p;
    cudaGetSymbolAddress(&p, d_cat);   catp  = (float*)p;
    cudaGetSymbolAddress(&p, d_g);     gp    = (float*)p;
    cudaGetSymbolAddress(&p, d_xsraw); xsraw = (float*)p;
    cudaGetSymbolAddress(&p, d_bcat);  bcat  = (float*)p;
    cudaGetSymbolAddress(&p, d_xh);    xh    = (__nv_bfloat16*)p;
    cudaGetSymbolAddress(&p, d_xl);    xl    = (__nv_bfloat16*)p;
    cudaGetSymbolAddress(&p, d_wcath); wcath = (__nv_bfloat16*)p;
    cudaGetSymbolAddress(&p, d_wcatl); wcatl = (__nv_bfloat16*)p;
    cudaGetSymbolAddress(&p, d_w2h);   w2h   = (__nv_bfloat16*)p;
    cudaGetSymbolAddress(&p, d_w2l);   w2l   = (__nv_bfloat16*)p;
    cudaGetSymbolAddress(&p, d_srwh);  srwh  = (__nv_bfloat16*)p;
    cudaGetSymbolAddress(&p, d_srwl);  srwl  = (__nv_bfloat16*)p;
    cudaGetSymbolAddress(&p, d_agh);   agh   = (__nv_bfloat16*)p;
    cudaGetSymbolAddress(&p, d_agl);   agl   = (__nv_bfloat16*)p;
    cudaGetSymbolAddress(&p, d_xsh);   xsh   = (__nv_bfloat16*)p;
    cudaGetSymbolAddress(&p, d_xsl);   xsl   = (__nv_bfloat16*)p;
    cudaGetSymbolAddress(&p, d_cath);  cath  = (__nv_bfloat16*)p;
    cudaGetSymbolAddress(&p, d_catl);  catl  = (__nv_bfloat16*)p;

    const int ATTN_SMEM = (32*1024 + 32*33 + 32 + 4608) * 4;  // 153856 B
    cudaFuncSetAttribute(attn1_fused,
                         cudaFuncAttributeMaxDynamicSharedMemorySize, ATTN_SMEM);
    cudaFuncSetAttribute(gemm2,
                         cudaFuncAttributeMaxDynamicSharedMemorySize, GEMM2_SMEM);

    const size_t XS_STRIDE = (size_t)B_ * N1_ * C_;

    // 1: all prep
    prep_all<<<10512, 256>>>(x, q1_w, q2_w, kv2_w, lepe_w,
                             q1_b, q2_b, kv2_b, lepe_b, kv1_w, pw, sr_w);

    // 2: sr conv GEMM, split-K x4 into partial slabs
    gemm2<<<dim3(2, 32, 4), 256, GEMM2_SMEM>>>(agh, agl, 1024, srwh, srwl, 256,
                                               (const float*)0, xsraw, 256,
                                               XS_STRIDE, 256, 1.f);
    // 3: LN+GELU (sums 4 partials + sr_b) -> split bf16
    ln_gelu_kernel<<<B_ * N1_, 256>>>(nw, nb, sr_b);

    // 4: fused x-projections -> d_proj [tok][768]   (ncu profiles this)
    gemm2<<<dim3(6, 128, 1), 256, GEMM2_SMEM>>>(xh, xl, 256, wcath, wcatl, 768,
                                                bcat, projp, 768, 0, 256, 1.f);

    // 5: kv1 GEMM
    gemm2<<<dim3(2, 32, 1), 256, GEMM2_SMEM>>>(xsh, xsl, 256, w2h, w2l, 256,
                                               kv1_b, kv1p, 256, 0, 256, 1.f);

    // 6: fused branch-1 attention
    attn1_fused<<<dim3(128, 16), 256, ATTN_SMEM>>>(projp, kv1p, catp, gp);

    // 7-8: branch 2 + lepe/cat split
    attn2_kernel<<<B_ * 16 * 16, 128>>>(projp);
    lepe_add_kernel<<<B_ * NTOK, 256>>>(projp, lcw, lcb);

    // 9: final projection: out = 2*(cat @ proj_w + proj_b)
    gemm2<<<dim3(2, 128, 1), 256, GEMM2_SMEM>>>(cath, catl, 256,
                                                w2h + 65536, w2l + 65536, 256,
                                                pb, out, 256, 0, 256, 2.f);
    // 10: masks
    mask_kernel<<<64, 256>>>(out);
}

// round 13
// speedup vs baseline: 5.4759x; 1.2333x over previous
#include <cuda_runtime.h>
#include <cuda_bf16.h>
#include <math.h>
#include <stdint.h>

#define B_    4
#define NTOK  4096
#define C_    256
#define H_    64
#define W_    64
#define NH2   4
#define N1_   1024

#define OUT_MAIN (B_*NTOK*C_)
#define OUT_M1   (OUT_MAIN)
#define OUT_M2   (OUT_MAIN + B_*NTOK)

// fp32 intermediates
static __device__ float d_proj[B_*NTOK*768];   // [q1|q2|kv2|lepe]
static __device__ float d_xsraw[4*B_*N1_*C_];  // 4 split-K partials
static __device__ float d_kv1[B_*N1_*C_];
static __device__ float d_cat[B_*NTOK*C_];
static __device__ float d_g[B_*N1_];
static __device__ float d_lm[B_*NTOK];
static __device__ float d_bcat[768];

// bf16 split buffers
static __device__ __nv_bfloat16 d_xh[B_*NTOK*C_],   d_xl[B_*NTOK*C_];
static __device__ __nv_bfloat16 d_wcath[256*768],   d_wcatl[256*768];
static __device__ __nv_bfloat16 d_w2h[131072],      d_w2l[131072];   // kv1 | proj
static __device__ __nv_bfloat16 d_srwh[1024*C_],    d_srwl[1024*C_];
static __device__ __nv_bfloat16 d_agh[4096*1024],   d_agl[4096*1024];
static __device__ __nv_bfloat16 d_xsh[B_*N1_*C_],   d_xsl[B_*N1_*C_];
static __device__ __nv_bfloat16 d_cath[B_*NTOK*C_], d_catl[B_*NTOK*C_];
static __device__ __nv_bfloat16 d_kv1h[B_*N1_*C_],  d_kv1l[B_*N1_*C_];

__device__ __constant__ float ATT_SCALE = 0.17677669529663687f; // 1/sqrt(32)

#define MMA_BF16(c, a, b) \
  asm volatile("mma.sync.aligned.m16n8k16.row.col.f32.bf16.bf16.f32 " \
    "{%0,%1,%2,%3}, {%4,%5,%6,%7}, {%8,%9}, {%0,%1,%2,%3};" \
    : "+f"((c)[0]), "+f"((c)[1]), "+f"((c)[2]), "+f"((c)[3]) \
    : "r"((a)[0]), "r"((a)[1]), "r"((a)[2]), "r"((a)[3]), \
      "r"((b)[0]), "r"((b)[1]))

#define LDSM_X4(r, addr) \
  asm volatile("ldmatrix.sync.aligned.m8n8.x4.shared.b16 {%0,%1,%2,%3}, [%4];" \
    : "=r"((r)[0]), "=r"((r)[1]), "=r"((r)[2]), "=r"((r)[3]) : "r"(addr))

#define LDSM_X4T(r, addr) \
  asm volatile("ldmatrix.sync.aligned.m8n8.x4.trans.shared.b16 {%0,%1,%2,%3}, [%4];" \
    : "=r"((r)[0]), "=r"((r)[1]), "=r"((r)[2]), "=r"((r)[3]) : "r"(addr))

__device__ __forceinline__ void cpa16(uint32_t saddr, const void* g) {
    asm volatile("cp.async.ca.shared.global [%0], [%1], 16;"
                 :: "r"(saddr), "l"(g));
}

// ---------------------------------------------------------------------------
// gemm2 (unchanged from R11): bf16-split GEMM, 128x128, ldmatrix, cp.async.
// ---------------------------------------------------------------------------
#define GEMM2_SMEM 75776
__global__ void __launch_bounds__(256, 2) gemm2(
    const __nv_bfloat16* __restrict__ Ah, const __nv_bfloat16* __restrict__ Al, int lda,
    const __nv_bfloat16* __restrict__ Bh, const __nv_bfloat16* __restrict__ Bl, int ldb,
    const float* __restrict__ bias, float* __restrict__ Cm, int ldc,
    size_t cstride, int K, float alpha)
{
    extern __shared__ uint16_t sm16[];
    uint32_t sb = (uint32_t)__cvta_generic_to_shared(sm16);
    const uint32_t AHo = 0, ALo = 20480, BHo = 40960, BLo = 58368;

    int tid = threadIdx.x, lane = tid & 31, warp = tid >> 5;
    int wm = warp >> 2, wn = warp & 3;
    int m0 = blockIdx.y * 128, n0 = blockIdx.x * 128;
    int kz = blockIdx.z;
    int g = lane >> 2, t = lane & 3;

    const __nv_bfloat16* Ahp = Ah + (size_t)kz * K;
    const __nv_bfloat16* Alp = Al + (size_t)kz * K;
    const __nv_bfloat16* Bhp = Bh + (size_t)kz * K * ldb;
    const __nv_bfloat16* Blp = Bl + (size_t)kz * K * ldb;

    float acc[4][4][4];
#pragma unroll
    for (int i = 0; i < 4; i++)
#pragma unroll
        for (int j = 0; j < 4; j++)
#pragma unroll
            for (int c = 0; c < 4; c++) acc[i][j][c] = 0.f;

    int av = tid;
    int arow0 = av >> 2, aseg0 = av & 3;
    int arow1 = (av + 256) >> 2, aseg1 = (av + 256) & 3;
    int brow0 = av >> 4, bseg0 = av & 15;
    int brow1 = (av + 256) >> 4, bseg1 = (av + 256) & 15;

#define LOAD_CHUNK(bi, k0) do { \
    uint32_t aB = sb + (bi)*10240; \
    uint32_t bB = sb + (bi)*8704; \
    cpa16(aB + AHo + (uint32_t)((arow0*40 + aseg0*8)*2), Ahp + (size_t)(m0+arow0)*lda + (k0) + aseg0*8); \
    cpa16(aB + AHo + (uint32_t)((arow1*40 + aseg1*8)*2), Ahp + (size_t)(m0+arow1)*lda + (k0) + aseg1*8); \
    cpa16(aB + ALo + (uint32_t)((arow0*40 + aseg0*8)*2), Alp + (size_t)(m0+arow0)*lda + (k0) + aseg0*8); \
    cpa16(aB + ALo + (uint32_t)((arow1*40 + aseg1*8)*2), Alp + (size_t)(m0+arow1)*lda + (k0) + aseg1*8); \
    cpa16(bB + BHo + (uint32_t)((brow0*136 + bseg0*8)*2), Bhp + (size_t)((k0)+brow0)*ldb + n0 + bseg0*8); \
    cpa16(bB + BHo + (uint32_t)((brow1*136 + bseg1*8)*2), Bhp + (size_t)((k0)+brow1)*ldb + n0 + bseg1*8); \
    cpa16(bB + BLo + (uint32_t)((brow0*136 + bseg0*8)*2), Blp + (size_t)((k0)+brow0)*ldb + n0 + bseg0*8); \
    cpa16(bB + BLo + (uint32_t)((brow1*136 + bseg1*8)*2), Blp + (size_t)((k0)+brow1)*ldb + n0 + bseg1*8); \
    asm volatile("cp.async.commit_group;" ::: "memory"); \
} while (0)

    LOAD_CHUNK(0, 0);

    uint32_t aoff = (uint32_t)(((wm*64 + (lane & 15))*40 + (lane >> 4)*8) * 2);
    uint32_t boff = (uint32_t)(((lane & 15)*136 + wn*32 + (lane >> 4)*8) * 2);

    int nch = K >> 5;
    for (int c = 0; c < nch; c++) {
        int bi = c & 1;
        if (c + 1 < nch) {
            LOAD_CHUNK(bi ^ 1, (c + 1) << 5);
            asm volatile("cp.async.wait_group 1;" ::: "memory");
        } else {
            asm volatile("cp.async.wait_group 0;" ::: "memory");
        }
        __syncthreads();

        uint32_t aH = sb + AHo + bi*10240 + aoff;
        uint32_t aL = sb + ALo + bi*10240 + aoff;
        uint32_t bH = sb + BHo + bi*8704 + boff;
        uint32_t bL = sb + BLo + bi*8704 + boff;
#pragma unroll
        for (int kk = 0; kk < 32; kk += 16) {
            uint32_t bfh[4][2], bfl[4][2];
#pragma unroll
            for (int jj = 0; jj < 2; jj++) {
                uint32_t r[4];
                LDSM_X4T(r, bH + kk*272 + jj*32);
                bfh[2*jj][0] = r[0]; bfh[2*jj][1] = r[1];
                bfh[2*jj+1][0] = r[2]; bfh[2*jj+1][1] = r[3];
                LDSM_X4T(r, bL + kk*272 + jj*32);
                bfl[2*jj][0] = r[0]; bfl[2*jj][1] = r[1];
                bfl[2*jj+1][0] = r[2]; bfl[2*jj+1][1] = r[3];
            }
#pragma unroll
            for (int mt = 0; mt < 4; mt++) {
                uint32_t afh[4], afl[4];
                LDSM_X4(afh, aH + mt*1280 + kk*2);
                LDSM_X4(afl, aL + mt*1280 + kk*2);
#pragma unroll
                for (int nj = 0; nj < 4; nj++) {
                    MMA_BF16(acc[mt][nj], afh, bfh[nj]);
                    MMA_BF16(acc[mt][nj], afl, bfh[nj]);
                    MMA_BF16(acc[mt][nj], afh, bfl[nj]);
                }
            }
        }
        __syncthreads();
    }

    float* Co = Cm + (size_t)kz * cstride;
    if (bias) {
#pragma unroll
        for (int mt = 0; mt < 4; mt++)
#pragma unroll
            for (int nj = 0; nj < 4; nj++) {
                int row = m0 + wm*64 + mt*16 + g;
                int col = n0 + wn*32 + nj*8 + t*2;
                float b0 = bias[col], b1 = bias[col+1];
                *(float2*)(Co + (size_t)row*ldc + col) =
                    make_float2(alpha*(acc[mt][nj][0]+b0), alpha*(acc[mt][nj][1]+b1));
                *(float2*)(Co + (size_t)(row+8)*ldc + col) =
                    make_float2(alpha*(acc[mt][nj][2]+b0), alpha*(acc[mt][nj][3]+b1));
            }
    } else {
#pragma unroll
        for (int mt = 0; mt < 4; mt++)
#pragma unroll
            for (int nj = 0; nj < 4; nj++) {
                int row = m0 + wm*64 + mt*16 + g;
                int col = n0 + wn*32 + nj*8 + t*2;
                *(float2*)(Co + (size_t)row*ldc + col) =
                    make_float2(acc[mt][nj][0], acc[mt][nj][1]);
                *(float2*)(Co + (size_t)(row+8)*ldc + col) =
                    make_float2(acc[mt][nj][2], acc[mt][nj][3]);
            }
    }
#undef LOAD_CHUNK
}

// ---------------------------------------------------------------------------
// prep_all (unchanged from R11). Grid 10512.
// ---------------------------------------------------------------------------
__global__ void prep_all(
    const float* __restrict__ x,
    const float* __restrict__ q1w, const float* __restrict__ q2w,
    const float* __restrict__ kv2w, const float* __restrict__ lepw,
    const float* __restrict__ q1b, const float* __restrict__ q2b,
    const float* __restrict__ kv2b, const float* __restrict__ lepb,
    const float* __restrict__ kv1w, const float* __restrict__ projw,
    const float* __restrict__ srw)
{
    int blk = blockIdx.x, tid = threadIdx.x;
    if (blk < 4096) {
        int i = blk * 256 + tid;
        float4 v = ((const float4*)x)[i];
        __nv_bfloat16 h0 = __float2bfloat16(v.x), h1 = __float2bfloat16(v.y);
        __nv_bfloat16 h2 = __float2bfloat16(v.z), h3 = __float2bfloat16(v.w);
        __nv_bfloat16 l0 = __float2bfloat16(v.x - __bfloat162float(h0));
        __nv_bfloat16 l1 = __float2bfloat16(v.y - __bfloat162float(h1));
        __nv_bfloat16 l2 = __float2bfloat16(v.z - __bfloat162float(h2));
        __nv_bfloat16 l3 = __float2bfloat16(v.w - __bfloat162float(h3));
        ((__nv_bfloat162*)d_xh)[i*2]   = __nv_bfloat162(h0, h1);
        ((__nv_bfloat162*)d_xh)[i*2+1] = __nv_bfloat162(h2, h3);
        ((__nv_bfloat162*)d_xl)[i*2]   = __nv_bfloat162(l0, l1);
        ((__nv_bfloat162*)d_xl)[i*2+1] = __nv_bfloat162(l2, l3);
    } else if (blk < 8192) {
        int v = (blk - 4096) * 256 + tid;
        int r = v >> 8, col4 = v & 255;
        int k = col4 * 4;
        int dd = k >> 8, ci = k & 255;
        int b = r >> 10, p = r & 1023;
        int ii = p >> 5, jj = p & 31;
        int di = dd >> 1, dj = dd & 1;
        int n = (2*ii + di) * W_ + 2*jj + dj;
        float4 xv = *(const float4*)(x + (size_t)(b * NTOK + n) * C_ + ci);
        __nv_bfloat16 h0 = __float2bfloat16(xv.x), h1 = __float2bfloat16(xv.y);
        __nv_bfloat16 h2 = __float2bfloat16(xv.z), h3 = __float2bfloat16(xv.w);
        __nv_bfloat16 l0 = __float2bfloat16(xv.x - __bfloat162float(h0));
        __nv_bfloat16 l1 = __float2bfloat16(xv.y - __bfloat162float(h1));
        __nv_bfloat16 l2 = __float2bfloat16(xv.z - __bfloat162float(h2));
        __nv_bfloat16 l3 = __float2bfloat16(xv.w - __bfloat162float(h3));
        size_t o = ((size_t)r * 1024 + k) >> 1;
        ((__nv_bfloat162*)d_agh)[o]   = __nv_bfloat162(h0, h1);
        ((__nv_bfloat162*)d_agh)[o+1] = __nv_bfloat162(h2, h3);
        ((__nv_bfloat162*)d_agl)[o]   = __nv_bfloat162(l0, l1);
        ((__nv_bfloat162*)d_agl)[o+1] = __nv_bfloat162(l2, l3);
    } else if (blk < 8960) {
        int idx = (blk - 8192) * 256 + tid;
        int k = idx / 768, col = idx - k * 768;
        float v;
        if (col < 128)       v = q1w[k*128 + col];
        else if (col < 256)  v = q2w[k*128 + col - 128];
        else if (col < 512)  v = kv2w[k*256 + col - 256];
        else                 v = lepw[k*256 + col - 512];
        __nv_bfloat16 h = __float2bfloat16(v);
        d_wcath[idx] = h;
        d_wcatl[idx] = __float2bfloat16(v - __bfloat162float(h));
        if (idx < 768) {
            float b = (idx < 128) ? q1b[idx] : (idx < 256) ? q2b[idx-128]
                    : (idx < 512) ? kv2b[idx-256] : lepb[idx-512];
            d_bcat[idx] = b;
        }
    } else if (blk < 10496) {
        int idx = (blk - 8960) * 256 + tid;
        float v;
        if (idx < 65536) {
            v = kv1w[idx];
            __nv_bfloat16 h = __float2bfloat16(v);
            d_w2h[idx] = h; d_w2l[idx] = __float2bfloat16(v - __bfloat162float(h));
        } else if (idx < 131072) {
            v = projw[idx - 65536];
            __nv_bfloat16 h = __float2bfloat16(v);
            d_w2h[idx] = h; d_w2l[idx] = __float2bfloat16(v - __bfloat162float(h));
        } else {
            int i = idx - 131072;
            int co = i & 255, kk = i >> 8;
            int dd = kk >> 8, ci = kk & 255;
            v = srw[co * 1024 + ci * 4 + dd];
            __nv_bfloat16 h = __float2bfloat16(v);
            d_srwh[i] = h; d_srwl[i] = __float2bfloat16(v - __bfloat162float(h));
        }
    } else {
        int i = (blk - 10496) * 256 + tid;
        if (i < B_ * N1_) d_g[i] = 0.f;
    }
}

// ---------------------------------------------------------------------------
// ln_gelu (unchanged from R11)
// ---------------------------------------------------------------------------
__global__ void ln_gelu_kernel(const float* __restrict__ nw,
                               const float* __restrict__ nb,
                               const float* __restrict__ srb)
{
    __shared__ float sh[8];
    int r = blockIdx.x, c = threadIdx.x;
    size_t o = (size_t)r * C_ + c;
    const size_t P = (size_t)B_ * N1_ * C_;
    float v = d_xsraw[o] + d_xsraw[o + P] + d_xsraw[o + 2*P] + d_xsraw[o + 3*P]
            + srb[c];

    float s = v;
#pragma unroll
    for (int o2 = 16; o2 > 0; o2 >>= 1) s += __shfl_xor_sync(0xffffffffu, s, o2);
    if ((c & 31) == 0) sh[c >> 5] = s;
    __syncthreads();
    if (c < 32) {
        float t = (c < 8) ? sh[c] : 0.f;
#pragma unroll
        for (int o2 = 4; o2 > 0; o2 >>= 1) t += __shfl_xor_sync(0xffffffffu, t, o2);
        if (c == 0) sh[0] = t;
    }
    __syncthreads();
    float mean = sh[0] * (1.f / 256.f);
    __syncthreads();

    float dv = v - mean;
    float q = dv * dv;
#pragma unroll
    for (int o2 = 16; o2 > 0; o2 >>= 1) q += __shfl_xor_sync(0xffffffffu, q, o2);
    if ((c & 31) == 0) sh[c >> 5] = q;
    __syncthreads();
    if (c < 32) {
        float t = (c < 8) ? sh[c] : 0.f;
#pragma unroll
        for (int o2 = 4; o2 > 0; o2 >>= 1) t += __shfl_xor_sync(0xffffffffu, t, o2);
        if (c == 0) sh[0] = t;
    }
    __syncthreads();
    float var = sh[0] * (1.f / 256.f);

    float y = dv * rsqrtf(var + 1e-5f) * nw[c] + nb[c];
    float ge = 0.5f * y * (1.f + erff(y * 0.70710678118654752f));
    __nv_bfloat16 h = __float2bfloat16(ge);
    d_xsh[o] = h;
    d_xsl[o] = __float2bfloat16(ge - __bfloat162float(h));
}

// ---------------------------------------------------------------------------
// kv1 fp32 -> bf16 split
// ---------------------------------------------------------------------------
__global__ void kv1split()
{
    int i = blockIdx.x * 256 + threadIdx.x;   // 262144 float4 groups
    float4 v = ((const float4*)d_kv1)[i];
    __nv_bfloat16 h0 = __float2bfloat16(v.x), h1 = __float2bfloat16(v.y);
    __nv_bfloat16 h2 = __float2bfloat16(v.z), h3 = __float2bfloat16(v.w);
    __nv_bfloat16 l0 = __float2bfloat16(v.x - __bfloat162float(h0));
    __nv_bfloat16 l1 = __float2bfloat16(v.y - __bfloat162float(h1));
    __nv_bfloat16 l2 = __float2bfloat16(v.z - __bfloat162float(h2));
    __nv_bfloat16 l3 = __float2bfloat16(v.w - __bfloat162float(h3));
    ((__nv_bfloat162*)d_kv1h)[i*2]   = __nv_bfloat162(h0, h1);
    ((__nv_bfloat162*)d_kv1h)[i*2+1] = __nv_bfloat162(h2, h3);
    ((__nv_bfloat162*)d_kv1l)[i*2]   = __nv_bfloat162(l0, l1);
    ((__nv_bfloat162*)d_kv1l)[i*2+1] = __nv_bfloat162(l2, l3);
}

// ---------------------------------------------------------------------------
// attn1_mma: tensor-core branch-1 attention.
// grid (128 q-tiles, 16 bh), 256 threads, ~166KB smem.
// smem: S fp32 [32][1024] | Qh/Ql [32][40] | inv[32] | KV 2buf x (h,l) 5120B |
//       Ph/Pl [32][72]
// ---------------------------------------------------------------------------
#define ATTN_SMEM 166016
__global__ void __launch_bounds__(256) attn1_mma(
    const float* __restrict__ proj,
    const __nv_bfloat16* __restrict__ kvh,
    const __nv_bfloat16* __restrict__ kvl,
    float* __restrict__ cat, float* __restrict__ g)
{
    extern __shared__ char smc[];
    float* S = (float*)smc;                          // 131072
    __nv_bfloat16* Qh = (__nv_bfloat16*)(smc + 131072);  // 2560
    __nv_bfloat16* Ql = (__nv_bfloat16*)(smc + 133632);  // 2560
    float* inv = (float*)(smc + 136192);             // 128
    __nv_bfloat16* Ph = (__nv_bfloat16*)(smc + 156800);  // 4608
    __nv_bfloat16* Pl = (__nv_bfloat16*)(smc + 161408);  // 4608
    uint32_t sb  = (uint32_t)__cvta_generic_to_shared(smc);
    uint32_t ktb = sb + 136320;                      // KV tiles, 20480 B
    uint32_t qhb = sb + 131072, qlb = sb + 133632;
    uint32_t phb = sb + 156800, plb = sb + 161408;

    int tid = threadIdx.x, lane = tid & 31, warp = tid >> 5;
    int bh = blockIdx.y, b = bh >> 2, h = bh & 3;
    int q0 = blockIdx.x * 32;
    int gq = lane >> 2, tl = lane & 3;

    const float* Qg = proj + (size_t)(b * NTOK + q0) * 768 + h * 32;
    const __nv_bfloat16* Kh = kvh + (size_t)b * N1_ * 256 + h * 32;
    const __nv_bfloat16* Kl = kvl + (size_t)b * N1_ * 256 + h * 32;

    // ---- Q load + scale + split ----
    {
        int q = tid >> 3, dg = (tid & 7) * 4;
        float4 v = *(const float4*)(Qg + (size_t)q * 768 + dg);
        float sc = ATT_SCALE;
        float a0 = v.x*sc, a1 = v.y*sc, a2 = v.z*sc, a3 = v.w*sc;
        __nv_bfloat16 h0 = __float2bfloat16(a0), h1 = __float2bfloat16(a1);
        __nv_bfloat16 h2 = __float2bfloat16(a2), h3 = __float2bfloat16(a3);
        Qh[q*40+dg+0] = h0; Qh[q*40+dg+1] = h1;
        Qh[q*40+dg+2] = h2; Qh[q*40+dg+3] = h3;
        Ql[q*40+dg+0] = __float2bfloat16(a0 - __bfloat162float(h0));
        Ql[q*40+dg+1] = __float2bfloat16(a1 - __bfloat162float(h1));
        Ql[q*40+dg+2] = __float2bfloat16(a2 - __bfloat162float(h2));
        Ql[q*40+dg+3] = __float2bfloat16(a3 - __bfloat162float(h3));
    }
    // tile loader lanes: key = tid>>2 (0..63), seg = tid&3
    int lkey = tid >> 2, lseg = tid & 3;
#define LOAD_K(t_, buf_) do { \
    cpa16(ktb + (buf_)*10240 + (uint32_t)((lkey*40 + lseg*8)*2), \
          Kh + (size_t)((t_)*64 + lkey)*256 + lseg*8); \
    cpa16(ktb + (buf_)*10240 + 5120 + (uint32_t)((lkey*40 + lseg*8)*2), \
          Kl + (size_t)((t_)*64 + lkey)*256 + lseg*8); \
    asm volatile("cp.async.commit_group;" ::: "memory"); \
} while (0)
#define LOAD_V(t_, buf_) do { \
    cpa16(ktb + (buf_)*10240 + (uint32_t)((lkey*40 + lseg*8)*2), \
          Kh + (size_t)((t_)*64 + lkey)*256 + 128 + lseg*8); \
    cpa16(ktb + (buf_)*10240 + 5120 + (uint32_t)((lkey*40 + lseg*8)*2), \
          Kl + (size_t)((t_)*64 + lkey)*256 + 128 + lseg*8); \
    asm volatile("cp.async.commit_group;" ::: "memory"); \
} while (0)

    LOAD_K(0, 0);
    __syncthreads();   // Q in smem

    // Q fragments (persistent)
    uint32_t qfh[2][2][4], qfl[2][2][4];
#pragma unroll
    for (int mt = 0; mt < 2; mt++)
#pragma unroll
        for (int ks = 0; ks < 2; ks++) {
            uint32_t off = (uint32_t)(((mt*16 + (lane&15))*40 + ks*16 + (lane>>4)*8)*2);
            LDSM_X4(qfh[mt][ks], qhb + off);
            LDSM_X4(qfl[mt][ks], qlb + off);
        }

    // ---- QK loop ----
    for (int t = 0; t < 16; t++) {
        int bi = t & 1;
        if (t < 15) {
            LOAD_K(t+1, bi^1);
            asm volatile("cp.async.wait_group 1;" ::: "memory");
        } else {
            asm volatile("cp.async.wait_group 0;" ::: "memory");
        }
        __syncthreads();

        uint32_t kb = ktb + bi*10240 +
                      (uint32_t)(((warp*8 + (lane&7))*40 + (lane>>3)*8)*2);
        uint32_t rh[4], rl[4];
        LDSM_X4(rh, kb);
        LDSM_X4(rl, kb + 5120);

        float acc[2][4];
#pragma unroll
        for (int i = 0; i < 2; i++)
#pragma unroll
            for (int j = 0; j < 4; j++) acc[i][j] = 0.f;
#pragma unroll
        for (int ks = 0; ks < 2; ks++) {
#pragma unroll
            for (int mt = 0; mt < 2; mt++) {
                MMA_BF16(acc[mt], qfh[mt][ks], (&rh[2*ks]));
                MMA_BF16(acc[mt], qfl[mt][ks], (&rh[2*ks]));
                MMA_BF16(acc[mt], qfh[mt][ks], (&rl[2*ks]));
            }
        }
        int kb0 = t*64 + warp*8 + tl*2;
#pragma unroll
        for (int mt = 0; mt < 2; mt++) {
            *(float2*)&S[(size_t)(mt*16+gq)*1024 + kb0]   = make_float2(acc[mt][0], acc[mt][1]);
            *(float2*)&S[(size_t)(mt*16+gq+8)*1024 + kb0] = make_float2(acc[mt][2], acc[mt][3]);
        }
        __syncthreads();
    }

    // issue V tile0 load early (overlaps softmax)
    LOAD_V(0, 0);

    // ---- softmax ----
    {
#pragma unroll
        for (int rr = 0; rr < 4; rr++) {
            int row = warp * 4 + rr;
            float* Sr = S + (size_t)row * 1024;
            float m = -1e30f;
#pragma unroll
            for (int i = 0; i < 32; i++) m = fmaxf(m, Sr[lane + 32*i]);
#pragma unroll
            for (int o = 16; o > 0; o >>= 1)
                m = fmaxf(m, __shfl_xor_sync(0xffffffffu, m, o));
            float s = 0.f;
#pragma unroll
            for (int i = 0; i < 32; i++) {
                float e = __expf(Sr[lane + 32*i] - m);
                Sr[lane + 32*i] = e;
                s += e;
            }
#pragma unroll
            for (int o = 16; o > 0; o >>= 1)
                s += __shfl_xor_sync(0xffffffffu, s, o);
            if (lane == 0) inv[row] = 1.f / s;
        }
    }
    __syncthreads();

    // ---- column sums -> g ----
    {
        float a0 = 0.f, a1 = 0.f, a2 = 0.f, a3 = 0.f;
#pragma unroll
        for (int q = 0; q < 32; q++) {
            float iv = inv[q];
            const float* Sq = S + (size_t)q * 1024;
            a0 += Sq[tid      ] * iv;
            a1 += Sq[tid + 256] * iv;
            a2 += Sq[tid + 512] * iv;
            a3 += Sq[tid + 768] * iv;
        }
        float* gb = g + b * N1_;
        atomicAdd(&gb[tid      ], a0);
        atomicAdd(&gb[tid + 256], a1);
        atomicAdd(&gb[tid + 512], a2);
        atomicAdd(&gb[tid + 768], a3);
    }
    __syncthreads();

    // ---- AV loop ----
    int wm = warp >> 2, wk = (warp >> 1) & 1, wd = warp & 1;
    float av[2][4];
#pragma unroll
    for (int j = 0; j < 2; j++)
#pragma unroll
        for (int c = 0; c < 4; c++) av[j][c] = 0.f;

    for (int t = 0; t < 16; t++) {
        int bi = t & 1;
        if (t < 15) LOAD_V(t+1, bi^1);
        // convert P tile (S values are exp, unnormalized)
#pragma unroll
        for (int i = 0; i < 8; i++) {
            int idx = tid + i*256;
            int q = idx >> 6, k = idx & 63;
            float val = S[(size_t)q*1024 + t*64 + k];
            __nv_bfloat16 hh = __float2bfloat16(val);
            Ph[q*72 + k] = hh;
            Pl[q*72 + k] = __float2bfloat16(val - __bfloat162float(hh));
        }
        if (t < 15) asm volatile("cp.async.wait_group 1;" ::: "memory");
        else        asm volatile("cp.async.wait_group 0;" ::: "memory");
        __syncthreads();

#pragma unroll
        for (int ks = 0; ks < 2; ks++) {
            uint32_t poff = (uint32_t)(((wm*16 + (lane&15))*72 + wk*32 + ks*16 + (lane>>4)*8)*2);
            uint32_t pah[4], pal[4];
            LDSM_X4(pah, phb + poff);
            LDSM_X4(pal, plb + poff);
            uint32_t vb = ktb + bi*10240 +
                (uint32_t)(((wk*32 + ks*16 + (lane&15))*40 + wd*16 + (lane>>4)*8)*2);
            uint32_t vh4[4], vl4[4];
            LDSM_X4T(vh4, vb);
            LDSM_X4T(vl4, vb + 5120);
#pragma unroll
            for (int j = 0; j < 2; j++) {
                MMA_BF16(av[j], pah, (&vh4[2*j]));
                MMA_BF16(av[j], pah, (&vl4[2*j]));
                MMA_BF16(av[j], pal, (&vh4[2*j]));
            }
        }
        __syncthreads();
    }

    // ---- reduce wk halves and write out ----
    float* red = (float*)(smc + 156800);   // 4KB, reuse P region
    if (wk == 1) {
        float* d = red + (size_t)((wm*2 + wd)*32 + lane)*8;
        d[0] = av[0][0]; d[1] = av[0][1]; d[2] = av[0][2]; d[3] = av[0][3];
        d[4] = av[1][0]; d[5] = av[1][1]; d[6] = av[1][2]; d[7] = av[1][3];
    }
    __syncthreads();
    if (wk == 0) {
        const float* s = red + (size_t)((wm*2 + wd)*32 + lane)*8;
        av[0][0] += s[0]; av[0][1] += s[1]; av[0][2] += s[2]; av[0][3] += s[3];
        av[1][0] += s[4]; av[1][1] += s[5]; av[1][2] += s[6]; av[1][3] += s[7];
        float i0 = inv[wm*16 + gq], i1 = inv[wm*16 + gq + 8];
        size_t r0 = (size_t)(b*NTOK + q0 + wm*16 + gq) * 256;
#pragma unroll
        for (int j = 0; j < 2; j++) {
            int col = h*32 + wd*16 + j*8 + tl*2;
            *(float2*)&cat[r0 + col] = make_float2(av[j][0]*i0, av[j][1]*i0);
            *(float2*)&cat[r0 + 8*256 + col] = make_float2(av[j][2]*i1, av[j][3]*i1);
        }
    }
#undef LOAD_K
#undef LOAD_V
}

// ---------------------------------------------------------------------------
__global__ void attn2_kernel(const float* __restrict__ proj)
{
    int win = blockIdx.x;
    int b = win >> 8, rem = win & 255, gy = rem >> 4, gx = rem & 15;
    int tid = threadIdx.x, h = tid >> 5, lane = tid & 31;

    __shared__ float Qs[4][16][32];
    __shared__ float Ks[4][16][32];
    __shared__ float Vs[4][16][32];
    __shared__ float csum[16];

    for (int i = lane; i < 16 * 32; i += 32) {
        int t = i >> 5, dd = i & 31;
        int n = (gy * 4 + (t >> 2)) * W_ + gx * 4 + (t & 3);
        const float* base = proj + (size_t)(b * NTOK + n) * 768;
        Qs[h][t][dd] = base[128 + h * 32 + dd];
        Ks[h][t][dd] = base[256 + h * 32 + dd];
        Vs[h][t][dd] = base[256 + 128 + h * 32 + dd];
    }
    if (tid < 16) csum[tid] = 0.f;
    __syncthreads();

    if (lane < 16) {
        int q = lane;
        float s[16];
        float mx = -1e30f;
#pragma unroll
        for (int m = 0; m < 16; m++) {
            float dot = 0.f;
#pragma unroll
            for (int dd = 0; dd < 32; dd++) dot += Qs[h][q][dd] * Ks[h][m][dd];
            s[m] = dot * ATT_SCALE;
            mx = fmaxf(mx, s[m]);
        }
        float sum = 0.f;
#pragma unroll
        for (int m = 0; m < 16; m++) { s[m] = __expf(s[m] - mx); sum += s[m]; }
        float iv = 1.f / sum;
#pragma unroll
        for (int m = 0; m < 16; m++) {
            s[m] *= iv;
            atomicAdd(&csum[m], s[m]);
        }
        int nq = (gy * 4 + (q >> 2)) * W_ + gx * 4 + (q & 3);
        float* outp = d_cat + (size_t)(b * NTOK + nq) * 256 + 128 + h * 32;
#pragma unroll
        for (int dd = 0; dd < 32; dd++) {
            float o = 0.f;
#pragma unroll
            for (int m = 0; m < 16; m++) o += s[m] * Vs[h][m][dd];
            outp[dd] = o;
        }
    }
    __syncthreads();
    if (tid < 16) {
        int m = tid;
        int np = (gy * 4 + (m >> 2)) * W_ + gx * 4 + (m & 3);
        d_lm[b * NTOK + np] = csum[m] * (1.f / 64.f);
    }
}

// ---------------------------------------------------------------------------
__global__ void lepe_add_kernel(const float* __restrict__ proj,
                                const float* __restrict__ w9,
                                const float* __restrict__ cb)
{
    int r = blockIdx.x;
    int c = threadIdx.x;
    int b = r >> 12, n = r & 4095, y = n >> 6, x = n & 63;
    float wv[9];
#pragma unroll
    for (int t = 0; t < 9; t++) wv[t] = w9[c * 9 + t];
    float acc = cb[c];
#pragma unroll
    for (int dy = 0; dy < 3; dy++) {
        int yy = y + dy - 1;
        if (yy < 0 || yy >= H_) continue;
#pragma unroll
        for (int dx = 0; dx < 3; dx++) {
            int xx = x + dx - 1;
            if (xx < 0 || xx >= W_) continue;
            acc += wv[dy * 3 + dx] *
                   proj[(size_t)(b * NTOK + yy * W_ + xx) * 768 + 512 + c];
        }
    }
    float v = d_cat[(size_t)r * C_ + c] + acc;
    __nv_bfloat16 h = __float2bfloat16(v);
    d_cath[(size_t)r * C_ + c] = h;
    d_catl[(size_t)r * C_ + c] = __float2bfloat16(v - __bfloat162float(h));
}

// ---------------------------------------------------------------------------
__global__ void mask_kernel(float* __restrict__ out)
{
    int idx = blockIdx.x * 256 + threadIdx.x;
    int b = idx >> 12, pos = idx & 4095, y = pos >> 6, x = pos & 63;
    float gv = d_g[b * N1_ + (y >> 1) * 32 + (x >> 1)] * (1.f / (NH2 * NTOK));
    float val = d_lm[idx] + gv;
    out[OUT_M1 + idx] = val;
    out[OUT_M2 + b * NTOK + x * 64 + y] = val;
}

// ---------------------------------------------------------------------------
extern "C" void kernel_launch(void* const* d_in, const int* in_sizes, int n_in,
                              void* d_out, int out_size)
{
    const float* x      = (const float*)d_in[0];
    const float* q1_w   = (const float*)d_in[1];
    const float* q1_b   = (const float*)d_in[2];
    const float* kv1_w  = (const float*)d_in[3];
    const float* kv1_b  = (const float*)d_in[4];
    const float* q2_w   = (const float*)d_in[5];
    const float* q2_b   = (const float*)d_in[6];
    const float* kv2_w  = (const float*)d_in[7];
    const float* kv2_b  = (const float*)d_in[8];
    const float* lepe_w = (const float*)d_in[9];
    const float* lepe_b = (const float*)d_in[10];
    const float* lcw    = (const float*)d_in[11];
    const float* lcb    = (const float*)d_in[12];
    const float* sr_w   = (const float*)d_in[13];
    const float* sr_b   = (const float*)d_in[14];
    const float* nw     = (const float*)d_in[15];
    const float* nb     = (const float*)d_in[16];
    const float* pw     = (const float*)d_in[17];
    const float* pb     = (const float*)d_in[18];
    float* out = (float*)d_out;

    void* p;
    float *projp, *kv1p, *catp, *gp, *xsraw, *bcat;
    __nv_bfloat16 *xh, *xl, *wcath, *wcatl, *w2h, *w2l, *srwh, *srwl;
    __nv_bfloat16 *agh, *agl, *xsh, *xsl, *cath, *catl, *kv1h, *kv1l;
    cudaGetSymbolAddress(&p, d_proj);  projp = (float*)p;
    cudaGetSymbolAddress(&p, d_kv1);   kv1p  = (float*)p;
    cudaGetSymbolAddress(&p, d_cat);   catp  = (float*)p;
    cudaGetSymbolAddress(&p, d_g);     gp    = (float*)p;
    cudaGetSymbolAddress(&p, d_xsraw); xsraw = (float*)p;
    cudaGetSymbolAddress(&p, d_bcat);  bcat  = (float*)p;
    cudaGetSymbolAddress(&p, d_xh);    xh    = (__nv_bfloat16*)p;
    cudaGetSymbolAddress(&p, d_xl);    xl    = (__nv_bfloat16*)p;
    cudaGetSymbolAddress(&p, d_wcath); wcath = (__nv_bfloat16*)p;
    cudaGetSymbolAddress(&p, d_wcatl); wcatl = (__nv_bfloat16*)p;
    cudaGetSymbolAddress(&p, d_w2h);   w2h   = (__nv_bfloat16*)p;
    cudaGetSymbolAddress(&p, d_w2l);   w2l   = (__nv_bfloat16*)p;
    cudaGetSymbolAddress(&p, d_srwh);  srwh  = (__nv_bfloat16*)p;
    cudaGetSymbolAddress(&p, d_srwl);  srwl  = (__nv_bfloat16*)p;
    cudaGetSymbolAddress(&p, d_agh);   agh   = (__nv_bfloat16*)p;
    cudaGetSymbolAddress(&p, d_agl);   agl   = (__nv_bfloat16*)p;
    cudaGetSymbolAddress(&p, d_xsh);   xsh   = (__nv_bfloat16*)p;
    cudaGetSymbolAddress(&p, d_xsl);   xsl   = (__nv_bfloat16*)p;
    cudaGetSymbolAddress(&p, d_cath);  cath  = (__nv_bfloat16*)p;
    cudaGetSymbolAddress(&p, d_catl);  catl  = (__nv_bfloat16*)p;
    cudaGetSymbolAddress(&p, d_kv1h);  kv1h  = (__nv_bfloat16*)p;
    cudaGetSymbolAddress(&p, d_kv1l);  kv1l  = (__nv_bfloat16*)p;

    cudaFuncSetAttribute(attn1_mma,
                         cudaFuncAttributeMaxDynamicSharedMemorySize, ATTN_SMEM);
    cudaFuncSetAttribute(gemm2,
                         cudaFuncAttributeMaxDynamicSharedMemorySize, GEMM2_SMEM);

    const size_t XS_STRIDE = (size_t)B_ * N1_ * C_;

    // 1: all prep
    prep_all<<<10512, 256>>>(x, q1_w, q2_w, kv2_w, lepe_w,
                             q1_b, q2_b, kv2_b, lepe_b, kv1_w, pw, sr_w);

    // 2: sr conv GEMM, split-K x4
    gemm2<<<dim3(2, 32, 4), 256, GEMM2_SMEM>>>(agh, agl, 1024, srwh, srwl, 256,
                                               (const float*)0, xsraw, 256,
                                               XS_STRIDE, 256, 1.f);
    // 3: LN+GELU
    ln_gelu_kernel<<<B_ * N1_, 256>>>(nw, nb, sr_b);

    // 4: fused x-projections (profiled)
    gemm2<<<dim3(6, 128, 1), 256, GEMM2_SMEM>>>(xh, xl, 256, wcath, wcatl, 768,
                                                bcat, projp, 768, 0, 256, 1.f);

    // 5: kv1 GEMM
    gemm2<<<dim3(2, 32, 1), 256, GEMM2_SMEM>>>(xsh, xsl, 256, w2h, w2l, 256,
                                               kv1_b, kv1p, 256, 0, 256, 1.f);
    // 6: kv1 -> bf16 split
    kv1split<<<1024, 256>>>();

    // 7: tensor-core branch-1 attention
    attn1_mma<<<dim3(128, 16), 256, ATTN_SMEM>>>(projp, kv1h, kv1l, catp, gp);

    // 8-9: branch 2 + lepe/cat split
    attn2_kernel<<<B_ * 16 * 16, 128>>>(projp);
    lepe_add_kernel<<<B_ * NTOK, 256>>>(projp, lcw, lcb);

    // 10: final projection
    gemm2<<<dim3(2, 128, 1), 256, GEMM2_SMEM>>>(cath, catl, 256,
                                                w2h + 65536, w2l + 65536, 256,
                                                pb, out, 256, 0, 256, 2.f);
    // 11: masks
    mask_kernel<<<64, 256>>>(out);
}

// round 15
// speedup vs baseline: 5.7043x; 1.0417x over previous
#include <cuda_runtime.h>
#include <cuda_bf16.h>
#include <math.h>
#include <stdint.h>

#define B_    4
#define NTOK  4096
#define C_    256
#define H_    64
#define W_    64
#define NH2   4
#define N1_   1024

#define OUT_MAIN (B_*NTOK*C_)
#define OUT_M1   (OUT_MAIN)
#define OUT_M2   (OUT_MAIN + B_*NTOK)

// fp32 intermediates
static __device__ float d_proj[B_*NTOK*768];   // [q1|q2|kv2|lepe]
static __device__ float d_xsraw[4*B_*N1_*C_];  // 4 split-K partials
static __device__ float d_kv1[B_*N1_*C_];
static __device__ float d_cat[B_*NTOK*C_];
static __device__ float d_g[B_*N1_];
static __device__ float d_lm[B_*NTOK];
static __device__ float d_bcat[768];

// bf16 split buffers
static __device__ __nv_bfloat16 d_xh[B_*NTOK*C_],   d_xl[B_*NTOK*C_];
static __device__ __nv_bfloat16 d_wcath[256*768],   d_wcatl[256*768];
static __device__ __nv_bfloat16 d_w2h[131072],      d_w2l[131072];   // kv1 | proj
static __device__ __nv_bfloat16 d_srwh[1024*C_],    d_srwl[1024*C_];
static __device__ __nv_bfloat16 d_agh[4096*1024],   d_agl[4096*1024];
static __device__ __nv_bfloat16 d_xsh[B_*N1_*C_],   d_xsl[B_*N1_*C_];
static __device__ __nv_bfloat16 d_cath[B_*NTOK*C_], d_catl[B_*NTOK*C_];
static __device__ __nv_bfloat16 d_kv1h[B_*N1_*C_],  d_kv1l[B_*N1_*C_];

__device__ __constant__ float ATT_SCALE = 0.17677669529663687f; // 1/sqrt(32)

#define MMA_BF16(c, a, b) \
  asm volatile("mma.sync.aligned.m16n8k16.row.col.f32.bf16.bf16.f32 " \
    "{%0,%1,%2,%3}, {%4,%5,%6,%7}, {%8,%9}, {%0,%1,%2,%3};" \
    : "+f"((c)[0]), "+f"((c)[1]), "+f"((c)[2]), "+f"((c)[3]) \
    : "r"((a)[0]), "r"((a)[1]), "r"((a)[2]), "r"((a)[3]), \
      "r"((b)[0]), "r"((b)[1]))

#define LDSM_X4(r, addr) \
  asm volatile("ldmatrix.sync.aligned.m8n8.x4.shared.b16 {%0,%1,%2,%3}, [%4];" \
    : "=r"((r)[0]), "=r"((r)[1]), "=r"((r)[2]), "=r"((r)[3]) : "r"(addr))

#define LDSM_X4T(r, addr) \
  asm volatile("ldmatrix.sync.aligned.m8n8.x4.trans.shared.b16 {%0,%1,%2,%3}, [%4];" \
    : "=r"((r)[0]), "=r"((r)[1]), "=r"((r)[2]), "=r"((r)[3]) : "r"(addr))

__device__ __forceinline__ void cpa16(uint32_t saddr, const void* g) {
    asm volatile("cp.async.ca.shared.global [%0], [%1], 16;"
                 :: "r"(saddr), "l"(g));
}

// ---------------------------------------------------------------------------
// gemm2 (unchanged): bf16-split GEMM, 128x128, ldmatrix, cp.async.
// ---------------------------------------------------------------------------
#define GEMM2_SMEM 75776
__global__ void __launch_bounds__(256, 2) gemm2(
    const __nv_bfloat16* __restrict__ Ah, const __nv_bfloat16* __restrict__ Al, int lda,
    const __nv_bfloat16* __restrict__ Bh, const __nv_bfloat16* __restrict__ Bl, int ldb,
    const float* __restrict__ bias, float* __restrict__ Cm, int ldc,
    size_t cstride, int K, float alpha)
{
    extern __shared__ uint16_t sm16[];
    uint32_t sb = (uint32_t)__cvta_generic_to_shared(sm16);
    const uint32_t AHo = 0, ALo = 20480, BHo = 40960, BLo = 58368;

    int tid = threadIdx.x, lane = tid & 31, warp = tid >> 5;
    int wm = warp >> 2, wn = warp & 3;
    int m0 = blockIdx.y * 128, n0 = blockIdx.x * 128;
    int kz = blockIdx.z;
    int g = lane >> 2, t = lane & 3;

    const __nv_bfloat16* Ahp = Ah + (size_t)kz * K;
    const __nv_bfloat16* Alp = Al + (size_t)kz * K;
    const __nv_bfloat16* Bhp = Bh + (size_t)kz * K * ldb;
    const __nv_bfloat16* Blp = Bl + (size_t)kz * K * ldb;

    float acc[4][4][4];
#pragma unroll
    for (int i = 0; i < 4; i++)
#pragma unroll
        for (int j = 0; j < 4; j++)
#pragma unroll
            for (int c = 0; c < 4; c++) acc[i][j][c] = 0.f;

    int av = tid;
    int arow0 = av >> 2, aseg0 = av & 3;
    int arow1 = (av + 256) >> 2, aseg1 = (av + 256) & 3;
    int brow0 = av >> 4, bseg0 = av & 15;
    int brow1 = (av + 256) >> 4, bseg1 = (av + 256) & 15;

#define LOAD_CHUNK(bi, k0) do { \
    uint32_t aB = sb + (bi)*10240; \
    uint32_t bB = sb + (bi)*8704; \
    cpa16(aB + AHo + (uint32_t)((arow0*40 + aseg0*8)*2), Ahp + (size_t)(m0+arow0)*lda + (k0) + aseg0*8); \
    cpa16(aB + AHo + (uint32_t)((arow1*40 + aseg1*8)*2), Ahp + (size_t)(m0+arow1)*lda + (k0) + aseg1*8); \
    cpa16(aB + ALo + (uint32_t)((arow0*40 + aseg0*8)*2), Alp + (size_t)(m0+arow0)*lda + (k0) + aseg0*8); \
    cpa16(aB + ALo + (uint32_t)((arow1*40 + aseg1*8)*2), Alp + (size_t)(m0+arow1)*lda + (k0) + aseg1*8); \
    cpa16(bB + BHo + (uint32_t)((brow0*136 + bseg0*8)*2), Bhp + (size_t)((k0)+brow0)*ldb + n0 + bseg0*8); \
    cpa16(bB + BHo + (uint32_t)((brow1*136 + bseg1*8)*2), Bhp + (size_t)((k0)+brow1)*ldb + n0 + bseg1*8); \
    cpa16(bB + BLo + (uint32_t)((brow0*136 + bseg0*8)*2), Blp + (size_t)((k0)+brow0)*ldb + n0 + bseg0*8); \
    cpa16(bB + BLo + (uint32_t)((brow1*136 + bseg1*8)*2), Blp + (size_t)((k0)+brow1)*ldb + n0 + bseg1*8); \
    asm volatile("cp.async.commit_group;" ::: "memory"); \
} while (0)

    LOAD_CHUNK(0, 0);

    uint32_t aoff = (uint32_t)(((wm*64 + (lane & 15))*40 + (lane >> 4)*8) * 2);
    uint32_t boff = (uint32_t)(((lane & 15)*136 + wn*32 + (lane >> 4)*8) * 2);

    int nch = K >> 5;
    for (int c = 0; c < nch; c++) {
        int bi = c & 1;
        if (c + 1 < nch) {
            LOAD_CHUNK(bi ^ 1, (c + 1) << 5);
            asm volatile("cp.async.wait_group 1;" ::: "memory");
        } else {
            asm volatile("cp.async.wait_group 0;" ::: "memory");
        }
        __syncthreads();

        uint32_t aH = sb + AHo + bi*10240 + aoff;
        uint32_t aL = sb + ALo + bi*10240 + aoff;
        uint32_t bH = sb + BHo + bi*8704 + boff;
        uint32_t bL = sb + BLo + bi*8704 + boff;
#pragma unroll
        for (int kk = 0; kk < 32; kk += 16) {
            uint32_t bfh[4][2], bfl[4][2];
#pragma unroll
            for (int jj = 0; jj < 2; jj++) {
                uint32_t r[4];
                LDSM_X4T(r, bH + kk*272 + jj*32);
                bfh[2*jj][0] = r[0]; bfh[2*jj][1] = r[1];
                bfh[2*jj+1][0] = r[2]; bfh[2*jj+1][1] = r[3];
                LDSM_X4T(r, bL + kk*272 + jj*32);
                bfl[2*jj][0] = r[0]; bfl[2*jj][1] = r[1];
                bfl[2*jj+1][0] = r[2]; bfl[2*jj+1][1] = r[3];
            }
#pragma unroll
            for (int mt = 0; mt < 4; mt++) {
                uint32_t afh[4], afl[4];
                LDSM_X4(afh, aH + mt*1280 + kk*2);
                LDSM_X4(afl, aL + mt*1280 + kk*2);
#pragma unroll
                for (int nj = 0; nj < 4; nj++) {
                    MMA_BF16(acc[mt][nj], afh, bfh[nj]);
                    MMA_BF16(acc[mt][nj], afl, bfh[nj]);
                    MMA_BF16(acc[mt][nj], afh, bfl[nj]);
                }
            }
        }
        __syncthreads();
    }

    float* Co = Cm + (size_t)kz * cstride;
    if (bias) {
#pragma unroll
        for (int mt = 0; mt < 4; mt++)
#pragma unroll
            for (int nj = 0; nj < 4; nj++) {
                int row = m0 + wm*64 + mt*16 + g;
                int col = n0 + wn*32 + nj*8 + t*2;
                float b0 = bias[col], b1 = bias[col+1];
                *(float2*)(Co + (size_t)row*ldc + col) =
                    make_float2(alpha*(acc[mt][nj][0]+b0), alpha*(acc[mt][nj][1]+b1));
                *(float2*)(Co + (size_t)(row+8)*ldc + col) =
                    make_float2(alpha*(acc[mt][nj][2]+b0), alpha*(acc[mt][nj][3]+b1));
            }
    } else {
#pragma unroll
        for (int mt = 0; mt < 4; mt++)
#pragma unroll
            for (int nj = 0; nj < 4; nj++) {
                int row = m0 + wm*64 + mt*16 + g;
                int col = n0 + wn*32 + nj*8 + t*2;
                *(float2*)(Co + (size_t)row*ldc + col) =
                    make_float2(acc[mt][nj][0], acc[mt][nj][1]);
                *(float2*)(Co + (size_t)(row+8)*ldc + col) =
                    make_float2(acc[mt][nj][2], acc[mt][nj][3]);
            }
    }
#undef LOAD_CHUNK
}

// ---------------------------------------------------------------------------
// prep_all (unchanged). Grid 10512.
// ---------------------------------------------------------------------------
__global__ void prep_all(
    const float* __restrict__ x,
    const float* __restrict__ q1w, const float* __restrict__ q2w,
    const float* __restrict__ kv2w, const float* __restrict__ lepw,
    const float* __restrict__ q1b, const float* __restrict__ q2b,
    const float* __restrict__ kv2b, const float* __restrict__ lepb,
    const float* __restrict__ kv1w, const float* __restrict__ projw,
    const float* __restrict__ srw)
{
    int blk = blockIdx.x, tid = threadIdx.x;
    if (blk < 4096) {
        int i = blk * 256 + tid;
        float4 v = ((const float4*)x)[i];
        __nv_bfloat16 h0 = __float2bfloat16(v.x), h1 = __float2bfloat16(v.y);
        __nv_bfloat16 h2 = __float2bfloat16(v.z), h3 = __float2bfloat16(v.w);
        __nv_bfloat16 l0 = __float2bfloat16(v.x - __bfloat162float(h0));
        __nv_bfloat16 l1 = __float2bfloat16(v.y - __bfloat162float(h1));
        __nv_bfloat16 l2 = __float2bfloat16(v.z - __bfloat162float(h2));
        __nv_bfloat16 l3 = __float2bfloat16(v.w - __bfloat162float(h3));
        ((__nv_bfloat162*)d_xh)[i*2]   = __nv_bfloat162(h0, h1);
        ((__nv_bfloat162*)d_xh)[i*2+1] = __nv_bfloat162(h2, h3);
        ((__nv_bfloat162*)d_xl)[i*2]   = __nv_bfloat162(l0, l1);
        ((__nv_bfloat162*)d_xl)[i*2+1] = __nv_bfloat162(l2, l3);
    } else if (blk < 8192) {
        int v = (blk - 4096) * 256 + tid;
        int r = v >> 8, col4 = v & 255;
        int k = col4 * 4;
        int dd = k >> 8, ci = k & 255;
        int b = r >> 10, p = r & 1023;
        int ii = p >> 5, jj = p & 31;
        int di = dd >> 1, dj = dd & 1;
        int n = (2*ii + di) * W_ + 2*jj + dj;
        float4 xv = *(const float4*)(x + (size_t)(b * NTOK + n) * C_ + ci);
        __nv_bfloat16 h0 = __float2bfloat16(xv.x), h1 = __float2bfloat16(xv.y);
        __nv_bfloat16 h2 = __float2bfloat16(xv.z), h3 = __float2bfloat16(xv.w);
        __nv_bfloat16 l0 = __float2bfloat16(xv.x - __bfloat162float(h0));
        __nv_bfloat16 l1 = __float2bfloat16(xv.y - __bfloat162float(h1));
        __nv_bfloat16 l2 = __float2bfloat16(xv.z - __bfloat162float(h2));
        __nv_bfloat16 l3 = __float2bfloat16(xv.w - __bfloat162float(h3));
        size_t o = ((size_t)r * 1024 + k) >> 1;
        ((__nv_bfloat162*)d_agh)[o]   = __nv_bfloat162(h0, h1);
        ((__nv_bfloat162*)d_agh)[o+1] = __nv_bfloat162(h2, h3);
        ((__nv_bfloat162*)d_agl)[o]   = __nv_bfloat162(l0, l1);
        ((__nv_bfloat162*)d_agl)[o+1] = __nv_bfloat162(l2, l3);
    } else if (blk < 8960) {
        int idx = (blk - 8192) * 256 + tid;
        int k = idx / 768, col = idx - k * 768;
        float v;
        if (col < 128)       v = q1w[k*128 + col];
        else if (col < 256)  v = q2w[k*128 + col - 128];
        else if (col < 512)  v = kv2w[k*256 + col - 256];
        else                 v = lepw[k*256 + col - 512];
        __nv_bfloat16 h = __float2bfloat16(v);
        d_wcath[idx] = h;
        d_wcatl[idx] = __float2bfloat16(v - __bfloat162float(h));
        if (idx < 768) {
            float b = (idx < 128) ? q1b[idx] : (idx < 256) ? q2b[idx-128]
                    : (idx < 512) ? kv2b[idx-256] : lepb[idx-512];
            d_bcat[idx] = b;
        }
    } else if (blk < 10496) {
        int idx = (blk - 8960) * 256 + tid;
        float v;
        if (idx < 65536) {
            v = kv1w[idx];
            __nv_bfloat16 h = __float2bfloat16(v);
            d_w2h[idx] = h; d_w2l[idx] = __float2bfloat16(v - __bfloat162float(h));
        } else if (idx < 131072) {
            v = projw[idx - 65536];
            __nv_bfloat16 h = __float2bfloat16(v);
            d_w2h[idx] = h; d_w2l[idx] = __float2bfloat16(v - __bfloat162float(h));
        } else {
            int i = idx - 131072;
            int co = i & 255, kk = i >> 8;
            int dd = kk >> 8, ci = kk & 255;
            v = srw[co * 1024 + ci * 4 + dd];
            __nv_bfloat16 h = __float2bfloat16(v);
            d_srwh[i] = h; d_srwl[i] = __float2bfloat16(v - __bfloat162float(h));
        }
    } else {
        int i = (blk - 10496) * 256 + tid;
        if (i < B_ * N1_) d_g[i] = 0.f;
    }
}

// ---------------------------------------------------------------------------
__global__ void ln_gelu_kernel(const float* __restrict__ nw,
                               const float* __restrict__ nb,
                               const float* __restrict__ srb)
{
    __shared__ float sh[8];
    int r = blockIdx.x, c = threadIdx.x;
    size_t o = (size_t)r * C_ + c;
    const size_t P = (size_t)B_ * N1_ * C_;
    float v = d_xsraw[o] + d_xsraw[o + P] + d_xsraw[o + 2*P] + d_xsraw[o + 3*P]
            + srb[c];

    float s = v;
#pragma unroll
    for (int o2 = 16; o2 > 0; o2 >>= 1) s += __shfl_xor_sync(0xffffffffu, s, o2);
    if ((c & 31) == 0) sh[c >> 5] = s;
    __syncthreads();
    if (c < 32) {
        float t = (c < 8) ? sh[c] : 0.f;
#pragma unroll
        for (int o2 = 4; o2 > 0; o2 >>= 1) t += __shfl_xor_sync(0xffffffffu, t, o2);
        if (c == 0) sh[0] = t;
    }
    __syncthreads();
    float mean = sh[0] * (1.f / 256.f);
    __syncthreads();

    float dv = v - mean;
    float q = dv * dv;
#pragma unroll
    for (int o2 = 16; o2 > 0; o2 >>= 1) q += __shfl_xor_sync(0xffffffffu, q, o2);
    if ((c & 31) == 0) sh[c >> 5] = q;
    __syncthreads();
    if (c < 32) {
        float t = (c < 8) ? sh[c] : 0.f;
#pragma unroll
        for (int o2 = 4; o2 > 0; o2 >>= 1) t += __shfl_xor_sync(0xffffffffu, t, o2);
        if (c == 0) sh[0] = t;
    }
    __syncthreads();
    float var = sh[0] * (1.f / 256.f);

    float y = dv * rsqrtf(var + 1e-5f) * nw[c] + nb[c];
    float ge = 0.5f * y * (1.f + erff(y * 0.70710678118654752f));
    __nv_bfloat16 h = __float2bfloat16(ge);
    d_xsh[o] = h;
    d_xsl[o] = __float2bfloat16(ge - __bfloat162float(h));
}

// ---------------------------------------------------------------------------
__global__ void kv1split()
{
    int i = blockIdx.x * 256 + threadIdx.x;
    float4 v = ((const float4*)d_kv1)[i];
    __nv_bfloat16 h0 = __float2bfloat16(v.x), h1 = __float2bfloat16(v.y);
    __nv_bfloat16 h2 = __float2bfloat16(v.z), h3 = __float2bfloat16(v.w);
    __nv_bfloat16 l0 = __float2bfloat16(v.x - __bfloat162float(h0));
    __nv_bfloat16 l1 = __float2bfloat16(v.y - __bfloat162float(h1));
    __nv_bfloat16 l2 = __float2bfloat16(v.z - __bfloat162float(h2));
    __nv_bfloat16 l3 = __float2bfloat16(v.w - __bfloat162float(h3));
    ((__nv_bfloat162*)d_kv1h)[i*2]   = __nv_bfloat162(h0, h1);
    ((__nv_bfloat162*)d_kv1h)[i*2+1] = __nv_bfloat162(h2, h3);
    ((__nv_bfloat162*)d_kv1l)[i*2]   = __nv_bfloat162(l0, l1);
    ((__nv_bfloat162*)d_kv1l)[i*2+1] = __nv_bfloat162(l2, l3);
}

// ---------------------------------------------------------------------------
// attn1_mma: tensor-core branch-1 attention, 16 queries/block (2 CTAs/SM).
// grid (256 q-tiles, 16 bh), 256 threads, 93248B smem.
// smem: S fp32[16][1024] | Qh/Ql[16][40] | inv[16] | KV 2buf | Ph/Pl[16][72]
// ---------------------------------------------------------------------------
#define ATTN_SMEM 93248
__global__ void __launch_bounds__(256) attn1_mma(
    const float* __restrict__ proj,
    const __nv_bfloat16* __restrict__ kvh,
    const __nv_bfloat16* __restrict__ kvl,
    float* __restrict__ cat, float* __restrict__ g)
{
    extern __shared__ char smc[];
    float* S = (float*)smc;                              // 65536
    __nv_bfloat16* Qh = (__nv_bfloat16*)(smc + 65536);   // 1280
    __nv_bfloat16* Ql = (__nv_bfloat16*)(smc + 66816);   // 1280
    float* inv = (float*)(smc + 68096);                  // 64
    __nv_bfloat16* Ph = (__nv_bfloat16*)(smc + 88640);   // 2304
    __nv_bfloat16* Pl = (__nv_bfloat16*)(smc + 90944);   // 2304
    uint32_t sb  = (uint32_t)__cvta_generic_to_shared(smc);
    uint32_t ktb = sb + 68160;                           // KV tiles, 20480B
    uint32_t qhb = sb + 65536, qlb = sb + 66816;
    uint32_t phb = sb + 88640, plb = sb + 90944;

    int tid = threadIdx.x, lane = tid & 31, warp = tid >> 5;
    int bh = blockIdx.y, b = bh >> 2, h = bh & 3;
    int q0 = blockIdx.x * 16;
    int gq = lane >> 2, tl = lane & 3;

    const float* Qg = proj + (size_t)(b * NTOK + q0) * 768 + h * 32;
    const __nv_bfloat16* Kh = kvh + (size_t)b * N1_ * 256 + h * 32;
    const __nv_bfloat16* Kl = kvl + (size_t)b * N1_ * 256 + h * 32;

    // ---- Q load + scale + split (threads 0-127) ----
    if (tid < 128) {
        int q = tid >> 3, dg = (tid & 7) * 4;
        float4 v = *(const float4*)(Qg + (size_t)q * 768 + dg);
        float sc = ATT_SCALE;
        float a0 = v.x*sc, a1 = v.y*sc, a2 = v.z*sc, a3 = v.w*sc;
        __nv_bfloat16 h0 = __float2bfloat16(a0), h1 = __float2bfloat16(a1);
        __nv_bfloat16 h2 = __float2bfloat16(a2), h3 = __float2bfloat16(a3);
        Qh[q*40+dg+0] = h0; Qh[q*40+dg+1] = h1;
        Qh[q*40+dg+2] = h2; Qh[q*40+dg+3] = h3;
        Ql[q*40+dg+0] = __float2bfloat16(a0 - __bfloat162float(h0));
        Ql[q*40+dg+1] = __float2bfloat16(a1 - __bfloat162float(h1));
        Ql[q*40+dg+2] = __float2bfloat16(a2 - __bfloat162float(h2));
        Ql[q*40+dg+3] = __float2bfloat16(a3 - __bfloat162float(h3));
    }
    int lkey = tid >> 2, lseg = tid & 3;
#define LOAD_K(t_, buf_) do { \
    cpa16(ktb + (buf_)*10240 + (uint32_t)((lkey*40 + lseg*8)*2), \
          Kh + (size_t)((t_)*64 + lkey)*256 + lseg*8); \
    cpa16(ktb + (buf_)*10240 + 5120 + (uint32_t)((lkey*40 + lseg*8)*2), \
          Kl + (size_t)((t_)*64 + lkey)*256 + lseg*8); \
    asm volatile("cp.async.commit_group;" ::: "memory"); \
} while (0)
#define LOAD_V(t_, buf_) do { \
    cpa16(ktb + (buf_)*10240 + (uint32_t)((lkey*40 + lseg*8)*2), \
          Kh + (size_t)((t_)*64 + lkey)*256 + 128 + lseg*8); \
    cpa16(ktb + (buf_)*10240 + 5120 + (uint32_t)((lkey*40 + lseg*8)*2), \
          Kl + (size_t)((t_)*64 + lkey)*256 + 128 + lseg*8); \
    asm volatile("cp.async.commit_group;" ::: "memory"); \
} while (0)

    LOAD_K(0, 0);
    __syncthreads();   // Q in smem

    // Q fragments (persistent): 1 m-tile x 2 k-steps
    uint32_t qfh[2][4], qfl[2][4];
#pragma unroll
    for (int ks = 0; ks < 2; ks++) {
        uint32_t off = (uint32_t)((((lane&15))*40 + ks*16 + (lane>>4)*8)*2);
        LDSM_X4(qfh[ks], qhb + off);
        LDSM_X4(qfl[ks], qlb + off);
    }

    // ---- QK loop ----
    for (int t = 0; t < 16; t++) {
        int bi = t & 1;
        if (t < 15) {
            LOAD_K(t+1, bi^1);
            asm volatile("cp.async.wait_group 1;" ::: "memory");
        } else {
            asm volatile("cp.async.wait_group 0;" ::: "memory");
        }
        __syncthreads();

        uint32_t kb = ktb + bi*10240 +
                      (uint32_t)(((warp*8 + (lane&7))*40 + (lane>>3)*8)*2);
        uint32_t rh[4], rl[4];
        LDSM_X4(rh, kb);
        LDSM_X4(rl, kb + 5120);

        float acc[4];
#pragma unroll
        for (int j = 0; j < 4; j++) acc[j] = 0.f;
#pragma unroll
        for (int ks = 0; ks < 2; ks++) {
            MMA_BF16(acc, qfh[ks], (&rh[2*ks]));
            MMA_BF16(acc, qfl[ks], (&rh[2*ks]));
            MMA_BF16(acc, qfh[ks], (&rl[2*ks]));
        }
        int kb0 = t*64 + warp*8 + tl*2;
        *(float2*)&S[(size_t)gq*1024 + kb0]     = make_float2(acc[0], acc[1]);
        *(float2*)&S[(size_t)(gq+8)*1024 + kb0] = make_float2(acc[2], acc[3]);
        __syncthreads();
    }

    LOAD_V(0, 0);   // overlaps softmax

    // ---- softmax: 16 rows, 2 per warp ----
    {
#pragma unroll
        for (int rr = 0; rr < 2; rr++) {
            int row = warp * 2 + rr;
            float* Sr = S + (size_t)row * 1024;
            float m = -1e30f;
#pragma unroll
            for (int i = 0; i < 32; i++) m = fmaxf(m, Sr[lane + 32*i]);
#pragma unroll
            for (int o = 16; o > 0; o >>= 1)
                m = fmaxf(m, __shfl_xor_sync(0xffffffffu, m, o));
            float s = 0.f;
#pragma unroll
            for (int i = 0; i < 32; i++) {
                float e = __expf(Sr[lane + 32*i] - m);
                Sr[lane + 32*i] = e;
                s += e;
            }
#pragma unroll
            for (int o = 16; o > 0; o >>= 1)
                s += __shfl_xor_sync(0xffffffffu, s, o);
            if (lane == 0) inv[row] = 1.f / s;
        }
    }
    __syncthreads();

    // ---- column sums -> g ----
    {
        float a0 = 0.f, a1 = 0.f, a2 = 0.f, a3 = 0.f;
#pragma unroll
        for (int q = 0; q < 16; q++) {
            float iv = inv[q];
            const float* Sq = S + (size_t)q * 1024;
            a0 += Sq[tid      ] * iv;
            a1 += Sq[tid + 256] * iv;
            a2 += Sq[tid + 512] * iv;
            a3 += Sq[tid + 768] * iv;
        }
        float* gb = g + b * N1_;
        atomicAdd(&gb[tid      ], a0);
        atomicAdd(&gb[tid + 256], a1);
        atomicAdd(&gb[tid + 512], a2);
        atomicAdd(&gb[tid + 768], a3);
    }
    __syncthreads();

    // ---- AV loop: wk2 = warp>>1 (k-quarter, 16 keys), wd = warp&1 (d-half) ----
    int wk2 = warp >> 1, wd = warp & 1;
    float av[2][4];
#pragma unroll
    for (int j = 0; j < 2; j++)
#pragma unroll
        for (int c = 0; c < 4; c++) av[j][c] = 0.f;

    for (int t = 0; t < 16; t++) {
        int bi = t & 1;
        if (t < 15) LOAD_V(t+1, bi^1);
        // convert P tile (16x64, 4 elements/thread)
#pragma unroll
        for (int i = 0; i < 4; i++) {
            int idx = tid + i*256;
            int q = idx >> 6, k = idx & 63;
            float val = S[(size_t)q*1024 + t*64 + k];
            __nv_bfloat16 hh = __float2bfloat16(val);
            Ph[q*72 + k] = hh;
            Pl[q*72 + k] = __float2bfloat16(val - __bfloat162float(hh));
        }
        if (t < 15) asm volatile("cp.async.wait_group 1;" ::: "memory");
        else        asm volatile("cp.async.wait_group 0;" ::: "memory");
        __syncthreads();

        uint32_t poff = (uint32_t)((((lane&15))*72 + wk2*16 + (lane>>4)*8)*2);
        uint32_t pah[4], pal[4];
        LDSM_X4(pah, phb + poff);
        LDSM_X4(pal, plb + poff);
        uint32_t vb = ktb + bi*10240 +
            (uint32_t)(((wk2*16 + (lane&15))*40 + wd*16 + (lane>>4)*8)*2);
        uint32_t vh4[4], vl4[4];
        LDSM_X4T(vh4, vb);
        LDSM_X4T(vl4, vb + 5120);
#pragma unroll
        for (int j = 0; j < 2; j++) {
            MMA_BF16(av[j], pah, (&vh4[2*j]));
            MMA_BF16(av[j], pah, (&vl4[2*j]));
            MMA_BF16(av[j], pal, (&vh4[2*j]));
        }
        __syncthreads();
    }

    // ---- reduce 4 k-quarters (S region is dead now) ----
    float* red = (float*)smc;
    if (wk2 > 0) {
        float* d = red + (size_t)((((wk2-1)*2 + wd)*32) + lane)*8;
        d[0] = av[0][0]; d[1] = av[0][1]; d[2] = av[0][2]; d[3] = av[0][3];
        d[4] = av[1][0]; d[5] = av[1][1]; d[6] = av[1][2]; d[7] = av[1][3];
    }
    __syncthreads();
    if (wk2 == 0) {
#pragma unroll
        for (int pp = 0; pp < 3; pp++) {
            const float* s = red + (size_t)(((pp*2 + wd)*32) + lane)*8;
            av[0][0] += s[0]; av[0][1] += s[1]; av[0][2] += s[2]; av[0][3] += s[3];
            av[1][0] += s[4]; av[1][1] += s[5]; av[1][2] += s[6]; av[1][3] += s[7];
        }
        float i0 = inv[gq], i1 = inv[gq + 8];
        size_t r0 = (size_t)(b*NTOK + q0 + gq) * 256;
#pragma unroll
        for (int j = 0; j < 2; j++) {
            int col = h*32 + wd*16 + j*8 + tl*2;
            *(float2*)&cat[r0 + col] = make_float2(av[j][0]*i0, av[j][1]*i0);
            *(float2*)&cat[r0 + 8*256 + col] = make_float2(av[j][2]*i1, av[j][3]*i1);
        }
    }
#undef LOAD_K
#undef LOAD_V
}

// ---------------------------------------------------------------------------
__global__ void attn2_kernel(const float* __restrict__ proj)
{
    int win = blockIdx.x;
    int b = win >> 8, rem = win & 255, gy = rem >> 4, gx = rem & 15;
    int tid = threadIdx.x, h = tid >> 5, lane = tid & 31;

    __shared__ float Qs[4][16][32];
    __shared__ float Ks[4][16][32];
    __shared__ float Vs[4][16][32];
    __shared__ float csum[16];

    for (int i = lane; i < 16 * 32; i += 32) {
        int t = i >> 5, dd = i & 31;
        int n = (gy * 4 + (t >> 2)) * W_ + gx * 4 + (t & 3);
        const float* base = proj + (size_t)(b * NTOK + n) * 768;
        Qs[h][t][dd] = base[128 + h * 32 + dd];
        Ks[h][t][dd] = base[256 + h * 32 + dd];
        Vs[h][t][dd] = base[256 + 128 + h * 32 + dd];
    }
    if (tid < 16) csum[tid] = 0.f;
    __syncthreads();

    if (lane < 16) {
        int q = lane;
        float s[16];
        float mx = -1e30f;
#pragma unroll
        for (int m = 0; m < 16; m++) {
            float dot = 0.f;
#pragma unroll
            for (int dd = 0; dd < 32; dd++) dot += Qs[h][q][dd] * Ks[h][m][dd];
            s[m] = dot * ATT_SCALE;
            mx = fmaxf(mx, s[m]);
        }
        float sum = 0.f;
#pragma unroll
        for (int m = 0; m < 16; m++) { s[m] = __expf(s[m] - mx); sum += s[m]; }
        float iv = 1.f / sum;
#pragma unroll
        for (int m = 0; m < 16; m++) {
            s[m] *= iv;
            atomicAdd(&csum[m], s[m]);
        }
        int nq = (gy * 4 + (q >> 2)) * W_ + gx * 4 + (q & 3);
        float* outp = d_cat + (size_t)(b * NTOK + nq) * 256 + 128 + h * 32;
#pragma unroll
        for (int dd = 0; dd < 32; dd++) {
            float o = 0.f;
#pragma unroll
            for (int m = 0; m < 16; m++) o += s[m] * Vs[h][m][dd];
            outp[dd] = o;
        }
    }
    __syncthreads();
    if (tid < 16) {
        int m = tid;
        int np = (gy * 4 + (m >> 2)) * W_ + gx * 4 + (m & 3);
        d_lm[b * NTOK + np] = csum[m] * (1.f / 64.f);
    }
}

// ---------------------------------------------------------------------------
__global__ void lepe_add_kernel(const float* __restrict__ proj,
                                const float* __restrict__ w9,
                                const float* __restrict__ cb)
{
    int r = blockIdx.x;
    int c = threadIdx.x;
    int b = r >> 12, n = r & 4095, y = n >> 6, x = n & 63;
    float wv[9];
#pragma unroll
    for (int t = 0; t < 9; t++) wv[t] = w9[c * 9 + t];
    float acc = cb[c];
#pragma unroll
    for (int dy = 0; dy < 3; dy++) {
        int yy = y + dy - 1;
        if (yy < 0 || yy >= H_) continue;
#pragma unroll
        for (int dx = 0; dx < 3; dx++) {
            int xx = x + dx - 1;
            if (xx < 0 || xx >= W_) continue;
            acc += wv[dy * 3 + dx] *
                   proj[(size_t)(b * NTOK + yy * W_ + xx) * 768 + 512 + c];
        }
    }
    float v = d_cat[(size_t)r * C_ + c] + acc;
    __nv_bfloat16 h = __float2bfloat16(v);
    d_cath[(size_t)r * C_ + c] = h;
    d_catl[(size_t)r * C_ + c] = __float2bfloat16(v - __bfloat162float(h));
}

// ---------------------------------------------------------------------------
__global__ void mask_kernel(float* __restrict__ out)
{
    int idx = blockIdx.x * 256 + threadIdx.x;
    int b = idx >> 12, pos = idx & 4095, y = pos >> 6, x = pos & 63;
    float gv = d_g[b * N1_ + (y >> 1) * 32 + (x >> 1)] * (1.f / (NH2 * NTOK));
    float val = d_lm[idx] + gv;
    out[OUT_M1 + idx] = val;
    out[OUT_M2 + b * NTOK + x * 64 + y] = val;
}

// ---------------------------------------------------------------------------
extern "C" void kernel_launch(void* const* d_in, const int* in_sizes, int n_in,
                              void* d_out, int out_size)
{
    const float* x      = (const float*)d_in[0];
    const float* q1_w   = (const float*)d_in[1];
    const float* q1_b   = (const float*)d_in[2];
    const float* kv1_w  = (const float*)d_in[3];
    const float* kv1_b  = (const float*)d_in[4];
    const float* q2_w   = (const float*)d_in[5];
    const float* q2_b   = (const float*)d_in[6];
    const float* kv2_w  = (const float*)d_in[7];
    const float* kv2_b  = (const float*)d_in[8];
    const float* lepe_w = (const float*)d_in[9];
    const float* lepe_b = (const float*)d_in[10];
    const float* lcw    = (const float*)d_in[11];
    const float* lcb    = (const float*)d_in[12];
    const float* sr_w   = (const float*)d_in[13];
    const float* sr_b   = (const float*)d_in[14];
    const float* nw     = (const float*)d_in[15];
    const float* nb     = (const float*)d_in[16];
    const float* pw     = (const float*)d_in[17];
    const float* pb     = (const float*)d_in[18];
    float* out = (float*)d_out;

    void* p;
    float *projp, *kv1p, *catp, *gp, *xsraw, *bcat;
    __nv_bfloat16 *xh, *xl, *wcath, *wcatl, *w2h, *w2l, *srwh, *srwl;
    __nv_bfloat16 *agh, *agl, *xsh, *xsl, *cath, *catl, *kv1h, *kv1l;
    cudaGetSymbolAddress(&p, d_proj);  projp = (float*)p;
    cudaGetSymbolAddress(&p, d_kv1);   kv1p  = (float*)p;
    cudaGetSymbolAddress(&p, d_cat);   catp  = (float*)p;
    cudaGetSymbolAddress(&p, d_g);     gp    = (float*)p;
    cudaGetSymbolAddress(&p, d_xsraw); xsraw = (float*)p;
    cudaGetSymbolAddress(&p, d_bcat);  bcat  = (float*)p;
    cudaGetSymbolAddress(&p, d_xh);    xh    = (__nv_bfloat16*)p;
    cudaGetSymbolAddress(&p, d_xl);    xl    = (__nv_bfloat16*)p;
    cudaGetSymbolAddress(&p, d_wcath); wcath = (__nv_bfloat16*)p;
    cudaGetSymbolAddress(&p, d_wcatl); wcatl = (__nv_bfloat16*)p;
    cudaGetSymbolAddress(&p, d_w2h);   w2h   = (__nv_bfloat16*)p;
    cudaGetSymbolAddress(&p, d_w2l);   w2l   = (__nv_bfloat16*)p;
    cudaGetSymbolAddress(&p, d_srwh);  srwh  = (__nv_bfloat16*)p;
    cudaGetSymbolAddress(&p, d_srwl);  srwl  = (__nv_bfloat16*)p;
    cudaGetSymbolAddress(&p, d_agh);   agh   = (__nv_bfloat16*)p;
    cudaGetSymbolAddress(&p, d_agl);   agl   = (__nv_bfloat16*)p;
    cudaGetSymbolAddress(&p, d_xsh);   xsh   = (__nv_bfloat16*)p;
    cudaGetSymbolAddress(&p, d_xsl);   xsl   = (__nv_bfloat16*)p;
    cudaGetSymbolAddress(&p, d_cath);  cath  = (__nv_bfloat16*)p;
    cudaGetSymbolAddress(&p, d_catl);  catl  = (__nv_bfloat16*)p;
    cudaGetSymbolAddress(&p, d_kv1h);  kv1h  = (__nv_bfloat16*)p;
    cudaGetSymbolAddress(&p, d_kv1l);  kv1l  = (__nv_bfloat16*)p;

    cudaFuncSetAttribute(attn1_mma,
                         cudaFuncAttributeMaxDynamicSharedMemorySize, ATTN_SMEM);
    cudaFuncSetAttribute(gemm2,
                         cudaFuncAttributeMaxDynamicSharedMemorySize, GEMM2_SMEM);

    const size_t XS_STRIDE = (size_t)B_ * N1_ * C_;

    // 1: all prep
    prep_all<<<10512, 256>>>(x, q1_w, q2_w, kv2_w, lepe_w,
                             q1_b, q2_b, kv2_b, lepe_b, kv1_w, pw, sr_w);

    // 2: sr conv GEMM, split-K x4
    gemm2<<<dim3(2, 32, 4), 256, GEMM2_SMEM>>>(agh, agl, 1024, srwh, srwl, 256,
                                               (const float*)0, xsraw, 256,
                                               XS_STRIDE, 256, 1.f);
    // 3: LN+GELU
    ln_gelu_kernel<<<B_ * N1_, 256>>>(nw, nb, sr_b);

    // 4: fused x-projections (profiled)
    gemm2<<<dim3(6, 128, 1), 256, GEMM2_SMEM>>>(xh, xl, 256, wcath, wcatl, 768,
                                                bcat, projp, 768, 0, 256, 1.f);

    // 5: kv1 GEMM
    gemm2<<<dim3(2, 32, 1), 256, GEMM2_SMEM>>>(xsh, xsl, 256, w2h, w2l, 256,
                                               kv1_b, kv1p, 256, 0, 256, 1.f);
    // 6: kv1 -> bf16 split
    kv1split<<<1024, 256>>>();

    // 7: tensor-core branch-1 attention (16 q/block, 2 CTAs/SM)
    attn1_mma<<<dim3(256, 16), 256, ATTN_SMEM>>>(projp, kv1h, kv1l, catp, gp);

    // 8-9: branch 2 + lepe/cat split
    attn2_kernel<<<B_ * 16 * 16, 128>>>(projp);
    lepe_add_kernel<<<B_ * NTOK, 256>>>(projp, lcw, lcb);

    // 10: final projection
    gemm2<<<dim3(2, 128, 1), 256, GEMM2_SMEM>>>(cath, catl, 256,
                                                w2h + 65536, w2l + 65536, 256,
                                                pb, out, 256, 0, 256, 2.f);
    // 11: masks
    mask_kernel<<<64, 256>>>(out);
}